// round 5
// baseline (speedup 1.0000x reference)
#include <cuda_runtime.h>
#include <cuda_fp16.h>
#include <math.h>
#include <stdint.h>

#define QROWS 4096
#define DIM   512
#define TWO_D 1024
#define NKEYS 32768
#define TOPK  64
#define EPSF  1e-8f
#define NBINS 2048
#define CAP   1024

// ---- int8 IMMA GEMM config ----
#define ITM 128
#define ITN 256
#define IKC 128                    // int8 per k-chunk = 128B per row
#define IPITCH 144                 // bytes per smem row (4-bank step -> conflict-free)
#define IA_BYTES (128 * IPITCH)    // 18432
#define IB_BYTES (256 * IPITCH)    // 36864
#define ISTAGE (IA_BYTES + IB_BYTES)
#define IGEMM_SMEM (2 * ISTAGE)    // 110592, double buffered
#define ICHUNKS (TWO_D / IKC)      // 8

// ---------------- scratch (no allocations allowed) ----------------
__device__ float  g_q[(size_t)QROWS * TWO_D];        // precise projected q [Q, D, 2]
__device__ int8_t g_q8[(size_t)QROWS * TWO_D];
__device__ int8_t g_k8[(size_t)NKEYS * TWO_D];
__device__ double g_qmagd[QROWS];
__device__ double g_kmagd[NKEYS];
__device__ float  g_fq[QROWS];                       // (amax/127)/|q|
__device__ float  g_fk[NKEYS];
__device__ __half g_scoresh[(size_t)QROWS * NKEYS];  // 256 MB screening scores
__device__ float  g_ret[(size_t)QROWS * TWO_D];
__device__ float  g_norm[(size_t)QROWS * TWO_D];

// ---------------- helpers ----------------
__device__ __forceinline__ uint32_t smem_u32(const void* p) {
    uint32_t a;
    asm("{ .reg .u64 t; cvta.to.shared.u64 t, %1; cvt.u32.u64 %0, t; }" : "=r"(a) : "l"(p));
    return a;
}
__device__ __forceinline__ void cpasync16(uint32_t dst, const void* src) {
    asm volatile("cp.async.cg.shared.global [%0], [%1], 16;" :: "r"(dst), "l"(src) : "memory");
}
__device__ __forceinline__ void ldmx4(uint32_t* r, uint32_t a) {
    asm volatile("ldmatrix.sync.aligned.m8n8.x4.shared.b16 {%0,%1,%2,%3}, [%4];"
                 : "=r"(r[0]), "=r"(r[1]), "=r"(r[2]), "=r"(r[3]) : "r"(a));
}
__device__ __forceinline__ void mma_s8(int* d, const uint32_t* a, uint32_t b0, uint32_t b1) {
    asm volatile(
        "mma.sync.aligned.m16n8k32.row.col.s32.s8.s8.s32 "
        "{%0,%1,%2,%3}, {%4,%5,%6,%7}, {%8,%9}, {%0,%1,%2,%3};"
        : "+r"(d[0]), "+r"(d[1]), "+r"(d[2]), "+r"(d[3])
        : "r"(a[0]), "r"(a[1]), "r"(a[2]), "r"(a[3]), "r"(b0), "r"(b1));
}

// ---------------- precise complex projection with fp64 accumulation ----------------
__global__ void __launch_bounds__(256)
cprojd_kernel(const float* __restrict__ X,
              const float* __restrict__ Wr, const float* __restrict__ Wi,
              const float* __restrict__ br, const float* __restrict__ bi,
              float* __restrict__ Y)
{
    __shared__ double2 Xs[16][64];
    __shared__ double2 Ws[16][64];
    const int tid = threadIdx.x;
    const int m0 = blockIdx.y * 64;
    const int n0 = blockIdx.x * 64;
    const int kk = tid & 15;
    const int rr = tid >> 4;
    const int ty4 = (tid >> 4) * 4;
    const int tx4 = (tid & 15) * 4;

    double cr[4][4], ci[4][4];
#pragma unroll
    for (int i = 0; i < 4; i++)
#pragma unroll
        for (int j = 0; j < 4; j++) { cr[i][j] = 0.0; ci[i][j] = 0.0; }

    for (int k0 = 0; k0 < DIM; k0 += 16) {
#pragma unroll
        for (int r = 0; r < 4; r++) {
            int row = rr + r * 16;
            float2 xv = *(const float2*)&X[((size_t)(m0 + row) * DIM + k0 + kk) * 2];
            Xs[kk][row] = make_double2((double)xv.x, (double)xv.y);
            float wr = Wr[(size_t)(n0 + row) * DIM + k0 + kk];
            float wi = Wi[(size_t)(n0 + row) * DIM + k0 + kk];
            Ws[kk][row] = make_double2((double)wr, (double)wi);
        }
        __syncthreads();
#pragma unroll
        for (int k = 0; k < 16; k++) {
            double2 a[4], w[4];
#pragma unroll
            for (int i = 0; i < 4; i++) a[i] = Xs[k][ty4 + i];
#pragma unroll
            for (int j = 0; j < 4; j++) w[j] = Ws[k][tx4 + j];
#pragma unroll
            for (int i = 0; i < 4; i++)
#pragma unroll
                for (int j = 0; j < 4; j++) {
                    cr[i][j] += a[i].x * w[j].x;
                    cr[i][j] -= a[i].y * w[j].y;
                    ci[i][j] += a[i].x * w[j].y;
                    ci[i][j] += a[i].y * w[j].x;
                }
        }
        __syncthreads();
    }
#pragma unroll
    for (int i = 0; i < 4; i++) {
        int m = m0 + ty4 + i;
#pragma unroll
        for (int j = 0; j < 4; j++) {
            int n = n0 + tx4 + j;
            Y[((size_t)m * DIM + n) * 2 + 0] = (float)cr[i][j] + br[n];
            Y[((size_t)m * DIM + n) * 2 + 1] = (float)ci[i][j] + bi[n];
        }
    }
}

// ---------------- plain fp32 complex projection (output path) ----------------
__global__ void __launch_bounds__(256)
cproj_kernel(const float* __restrict__ X,
             const float* __restrict__ Wr, const float* __restrict__ Wi,
             const float* __restrict__ br, const float* __restrict__ bi,
             float* __restrict__ Y)
{
    __shared__ float2 Xs[16][64];
    __shared__ float2 Ws[16][64];
    const int tid = threadIdx.x;
    const int m0 = blockIdx.y * 64;
    const int n0 = blockIdx.x * 64;
    const int kk = tid & 15;
    const int rr = tid >> 4;
    const int ty4 = (tid >> 4) * 4;
    const int tx4 = (tid & 15) * 4;

    float cr[4][4], ci[4][4];
#pragma unroll
    for (int i = 0; i < 4; i++)
#pragma unroll
        for (int j = 0; j < 4; j++) { cr[i][j] = 0.f; ci[i][j] = 0.f; }

    for (int k0 = 0; k0 < DIM; k0 += 16) {
#pragma unroll
        for (int r = 0; r < 4; r++) {
            int row = rr + r * 16;
            Xs[kk][row] = *(const float2*)&X[((size_t)(m0 + row) * DIM + k0 + kk) * 2];
            float wr = Wr[(size_t)(n0 + row) * DIM + k0 + kk];
            float wi = Wi[(size_t)(n0 + row) * DIM + k0 + kk];
            Ws[kk][row] = make_float2(wr, wi);
        }
        __syncthreads();
#pragma unroll
        for (int k = 0; k < 16; k++) {
            float2 a[4], w[4];
#pragma unroll
            for (int i = 0; i < 4; i++) a[i] = Xs[k][ty4 + i];
#pragma unroll
            for (int j = 0; j < 4; j++) w[j] = Ws[k][tx4 + j];
#pragma unroll
            for (int i = 0; i < 4; i++)
#pragma unroll
                for (int j = 0; j < 4; j++) {
                    cr[i][j] += a[i].x * w[j].x;
                    cr[i][j] -= a[i].y * w[j].y;
                    ci[i][j] += a[i].x * w[j].y;
                    ci[i][j] += a[i].y * w[j].x;
                }
        }
        __syncthreads();
    }
#pragma unroll
    for (int i = 0; i < 4; i++) {
        int m = m0 + ty4 + i;
#pragma unroll
        for (int j = 0; j < 4; j++) {
            int n = n0 + tx4 + j;
            Y[((size_t)m * DIM + n) * 2 + 0] = cr[i][j] + br[n];
            Y[((size_t)m * DIM + n) * 2 + 1] = ci[i][j] + bi[n];
        }
    }
}

// ---------------- prep: per-row mag(double) + amax + int8 quantize + score scale ----------
__global__ void __launch_bounds__(128)
prep_kernel(const float* __restrict__ X, int8_t* __restrict__ X8,
            double* __restrict__ magd, float* __restrict__ fscale)
{
    __shared__ double smd[128];
    __shared__ float  sma[128];
    __shared__ float  s_qsc;
    const int row = blockIdx.x;
    const int tid = threadIdx.x;
    const float* p = X + (size_t)row * TWO_D;

    double s = 0.0;
    float amax = 0.f;
    for (int i = tid; i < TWO_D; i += 128) {
        float v = p[i];
        s += (double)v * (double)v;
        amax = fmaxf(amax, fabsf(v));
    }
    smd[tid] = s; sma[tid] = amax;
    __syncthreads();
    for (int o = 64; o > 0; o >>= 1) {
        if (tid < o) {
            smd[tid] += smd[tid + o];
            sma[tid] = fmaxf(sma[tid], sma[tid + o]);
        }
        __syncthreads();
    }
    if (tid == 0) {
        double m = sqrt(smd[0] + 1e-8);
        magd[row] = m;
        float am = sma[0];
        fscale[row] = (am > 0.f) ? (float)(((double)am / 127.0) / m) : 0.f;
        s_qsc = (am > 0.f) ? 127.f / am : 0.f;
    }
    __syncthreads();
    const float qsc = s_qsc;

    // quantize 8 consecutive elems per thread -> 8-byte store
    const int base = tid * 8;
    float4 v0 = *(const float4*)(p + base);
    float4 v1 = *(const float4*)(p + base + 4);
    int b[8];
    b[0] = __float2int_rn(v0.x * qsc); b[1] = __float2int_rn(v0.y * qsc);
    b[2] = __float2int_rn(v0.z * qsc); b[3] = __float2int_rn(v0.w * qsc);
    b[4] = __float2int_rn(v1.x * qsc); b[5] = __float2int_rn(v1.y * qsc);
    b[6] = __float2int_rn(v1.z * qsc); b[7] = __float2int_rn(v1.w * qsc);
#pragma unroll
    for (int i = 0; i < 8; i++) b[i] = max(-127, min(127, b[i]));
    uint32_t lo = (b[0] & 0xff) | ((b[1] & 0xff) << 8) | ((b[2] & 0xff) << 16) | ((b[3] & 0xff) << 24);
    uint32_t hi = (b[4] & 0xff) | ((b[5] & 0xff) << 8) | ((b[6] & 0xff) << 16) | ((b[7] & 0xff) << 24);
    *(uint2*)(X8 + (size_t)row * TWO_D + base) = make_uint2(lo, hi);
}

// ---------------- int8 IMMA screening GEMM ----------------
// scoresh[q,n] = half( s32dot(q8[q,:], k8[n,:]) * fq[q] * fk[n] )
__device__ __forceinline__ void igemm_load_stage(
    const int8_t* A8, const int8_t* B8, uint32_t sb, int tid, int it, int s,
    int m0, int n0)
{
    const int seg = tid & 7;
    const int rowq = tid >> 3;                 // 0..63
    const size_t koff = (size_t)it * IKC + seg * 16;
    const uint32_t so = sb + (uint32_t)s * ISTAGE;
#pragma unroll
    for (int j = 0; j < 2; j++) {
        int row = rowq + 64 * j;
        cpasync16(so + row * IPITCH + seg * 16, A8 + (size_t)(m0 + row) * TWO_D + koff);
    }
#pragma unroll
    for (int j = 0; j < 4; j++) {
        int row = rowq + 64 * j;
        cpasync16(so + IA_BYTES + row * IPITCH + seg * 16, B8 + (size_t)(n0 + row) * TWO_D + koff);
    }
    asm volatile("cp.async.commit_group;" ::: "memory");
}

__global__ void __launch_bounds__(512, 1)
coh_gemm_imma(const int8_t* __restrict__ A8, const int8_t* __restrict__ B8,
              const float* __restrict__ fq, const float* __restrict__ fk,
              __half* __restrict__ C)
{
    extern __shared__ __align__(16) char smraw[];
    const uint32_t sb = smem_u32(smraw);
    const int tid = threadIdx.x;
    const int wid = tid >> 5, lane = tid & 31;
    const int m0 = blockIdx.x * ITM;           // x fastest -> B tile shared across wave
    const int n0 = blockIdx.y * ITN;
    const int wm = (wid & 3) * 32;
    const int wn = (wid >> 2) * 64;

    int acc[2][8][4];
#pragma unroll
    for (int a = 0; a < 2; a++)
#pragma unroll
        for (int b = 0; b < 8; b++)
#pragma unroll
            for (int c = 0; c < 4; c++) acc[a][b][c] = 0;

    igemm_load_stage(A8, B8, sb, tid, 0, 0, m0, n0);
    int buf = 0;
    const int lrow = lane & 15;
    const int lcol = (lane >> 4) * 16;         // byte offset within 32B k-slab

    for (int it = 0; it < ICHUNKS; it++) {
        if (it < ICHUNKS - 1) {
            igemm_load_stage(A8, B8, sb, tid, it + 1, buf ^ 1, m0, n0);
            asm volatile("cp.async.wait_group 1;" ::: "memory");
        } else {
            asm volatile("cp.async.wait_group 0;" ::: "memory");
        }
        __syncthreads();
        const uint32_t aB = sb + (uint32_t)buf * ISTAGE;
        const uint32_t bB = aB + IA_BYTES;
#pragma unroll
        for (int ks = 0; ks < 4; ks++) {       // 4 x k32 per 128B chunk
            uint32_t afr[2][4], bq[4][4];
#pragma unroll
            for (int fm = 0; fm < 2; fm++)
                ldmx4(afr[fm], aB + (wm + fm * 16 + lrow) * IPITCH + ks * 32 + lcol);
#pragma unroll
            for (int bg = 0; bg < 4; bg++)
                ldmx4(bq[bg], bB + (wn + bg * 16 + lrow) * IPITCH + ks * 32 + lcol);
#pragma unroll
            for (int fm = 0; fm < 2; fm++)
#pragma unroll
                for (int fn = 0; fn < 8; fn++) {
                    const int bg = fn >> 1, hf = fn & 1;
                    mma_s8(acc[fm][fn], afr[fm], bq[bg][hf], bq[bg][hf + 2]);
                }
        }
        __syncthreads();
        buf ^= 1;
    }

    // epilogue: scale + half store
#pragma unroll
    for (int fm = 0; fm < 2; fm++) {
        const int rlo = m0 + wm + fm * 16 + (lane >> 2);
        const int rhi = rlo + 8;
        const float qlo = fq[rlo], qhi = fq[rhi];
#pragma unroll
        for (int fn = 0; fn < 8; fn++) {
            const int n = n0 + wn + ((fn >> 1) * 16 + (fn & 1) * 8) + (lane & 3) * 2;
            const float k0v = fk[n], k1v = fk[n + 1];
            __half2 hlo, hhi;
            hlo.x = __float2half_rn((float)acc[fm][fn][0] * qlo * k0v);
            hlo.y = __float2half_rn((float)acc[fm][fn][1] * qlo * k1v);
            hhi.x = __float2half_rn((float)acc[fm][fn][2] * qhi * k0v);
            hhi.y = __float2half_rn((float)acc[fm][fn][3] * qhi * k1v);
            *(__half2*)&C[(size_t)rlo * NKEYS + n] = hlo;
            *(__half2*)&C[(size_t)rhi * NKEYS + n] = hhi;
        }
    }
}

// ---------------- top-64 (screen -> double rescore -> select) + softmax + gather ---------
__global__ void __launch_bounds__(256)
topk_kernel(const __half* __restrict__ scores,
            const float* __restrict__ qbuf,
            const float* __restrict__ keys,
            const double* __restrict__ qmagd,
            const double* __restrict__ kmagd,
            const float* __restrict__ values,
            float* __restrict__ ret)
{
    __shared__ int    hist[NBINS];
    __shared__ int    csum[256];
    __shared__ float  qs[TWO_D];
    __shared__ double cand_d[CAP];
    __shared__ int    cand_i[CAP];
    __shared__ int    s_cnt;
    __shared__ int    s_thresh;
    __shared__ double sel_d[TOPK];
    __shared__ int    sel_i[TOPK];
    __shared__ float  s_w[TOPK];
    __shared__ double redv[8];
    __shared__ int    redi[8];

    const int q = blockIdx.x;
    const int tid = threadIdx.x;
    const __half* row = scores + (size_t)q * NKEYS;

    for (int i = tid; i < NBINS; i += 256) hist[i] = 0;
    for (int i = tid; i < TWO_D; i += 256) qs[i] = qbuf[(size_t)q * TWO_D + i];
    if (tid == 0) s_cnt = 0;
    __syncthreads();

    for (int i = tid; i < NKEYS; i += 256) {
        float s = __half2float(row[i]);
        int b = (int)floorf((s + 1.0f) * 1024.0f);
        b = max(0, min(NBINS - 1, b));
        atomicAdd(&hist[b], 1);
    }
    __syncthreads();

    {
        int c = 0;
#pragma unroll
        for (int j = 0; j < 8; j++) c += hist[tid * 8 + j];
        csum[tid] = c;
    }
    __syncthreads();
    if (tid == 0) {
        int acc = 0, thr = 0;
        for (int ch = 255; ch >= 0; ch--) {
            if (acc + csum[ch] >= TOPK) {
                for (int b = ch * 8 + 7; b >= ch * 8; b--) {
                    acc += hist[b];
                    if (acc >= TOPK) { thr = b; break; }
                }
                break;
            }
            acc += csum[ch];
        }
        s_thresh = max(thr - 4, 0);   // 4-bin margin (3.9e-3) ~ 12 sigma of int8 screen error
    }
    __syncthreads();
    const int thresh = s_thresh;

    for (int i = tid; i < NKEYS; i += 256) {
        float s = __half2float(row[i]);
        int b = (int)floorf((s + 1.0f) * 1024.0f);
        b = max(0, min(NBINS - 1, b));
        if (b >= thresh) {
            int pos = atomicAdd(&s_cnt, 1);
            if (pos < CAP) cand_i[pos] = i;
        }
    }
    __syncthreads();
    const int cnt = min(s_cnt, CAP);

    // ---- double-precision rescore of candidates (one warp per candidate) ----
    {
        const int wid = tid >> 5, lane = tid & 31;
        const double qm = qmagd[q];
        for (int c = wid; c < cnt; c += 8) {
            const int ki = cand_i[c];
            const float* kr = keys + (size_t)ki * TWO_D;
            double acc = 0.0;
#pragma unroll
            for (int t = 0; t < 8; t++) {
                int e = t * 128 + lane * 4;
                float4 kv = *(const float4*)(kr + e);
                acc += (double)qs[e]     * (double)kv.x;
                acc += (double)qs[e + 1] * (double)kv.y;
                acc += (double)qs[e + 2] * (double)kv.z;
                acc += (double)qs[e + 3] * (double)kv.w;
            }
#pragma unroll
            for (int o = 16; o > 0; o >>= 1)
                acc += __shfl_down_sync(0xffffffffu, acc, o);
            if (lane == 0) cand_d[c] = acc / (qm * kmagd[ki] + (double)EPSF);
        }
    }
    __syncthreads();

    for (int t = 0; t < TOPK; t++) {
        double bv = -1e300; int bi = 0;
        for (int i = tid; i < cnt; i += 256) {
            double v = cand_d[i];
            if (v > bv) { bv = v; bi = i; }
        }
#pragma unroll
        for (int o = 16; o > 0; o >>= 1) {
            double ov = __shfl_down_sync(0xffffffffu, bv, o);
            int    oi = __shfl_down_sync(0xffffffffu, bi, o);
            if (ov > bv) { bv = ov; bi = oi; }
        }
        if ((tid & 31) == 0) { redv[tid >> 5] = bv; redi[tid >> 5] = bi; }
        __syncthreads();
        if (tid == 0) {
            double fv = redv[0]; int fi = redi[0];
#pragma unroll
            for (int w = 1; w < 8; w++)
                if (redv[w] > fv) { fv = redv[w]; fi = redi[w]; }
            sel_d[t] = fv; sel_i[t] = cand_i[fi];
            cand_d[fi] = -1e300;
        }
        __syncthreads();
    }

    if (tid == 0) {
        float m = (float)sel_d[0];
        float z = 0.f;
        for (int t = 0; t < TOPK; t++) { float w = expf((float)sel_d[t] - m); s_w[t] = w; z += w; }
        float inv = 1.0f / z;
        for (int t = 0; t < TOPK; t++) s_w[t] *= inv;
    }
    __syncthreads();

    const int col = tid * 4;
    float4 acc = make_float4(0.f, 0.f, 0.f, 0.f);
    for (int t = 0; t < TOPK; t++) {
        const float4 v = *(const float4*)&values[(size_t)sel_i[t] * TWO_D + col];
        float w = s_w[t];
        acc.x += w * v.x; acc.y += w * v.y; acc.z += w * v.z; acc.w += w * v.w;
    }
    *(float4*)&ret[(size_t)q * TWO_D + col] = acc;
}

// ---------------- phase norm: x * gamma[d] / rms(row) ----------------
__global__ void __launch_bounds__(256)
norm_kernel(const float* __restrict__ ret, const float* __restrict__ gamma,
            float* __restrict__ out)
{
    __shared__ float sm[256];
    __shared__ float s_inv;
    const int q = blockIdx.x;
    const int tid = threadIdx.x;
    const float* p = ret + (size_t)q * TWO_D;
    float s = 0.f;
    for (int i = tid; i < TWO_D; i += 256) { float v = p[i]; s += v * v; }
    sm[tid] = s;
    __syncthreads();
    for (int o = 128; o > 0; o >>= 1) {
        if (tid < o) sm[tid] += sm[tid + o];
        __syncthreads();
    }
    if (tid == 0) {
        float mean = sm[0] / (float)DIM;
        s_inv = 1.0f / sqrtf(mean + EPSF);
    }
    __syncthreads();
    const float inv = s_inv;
    for (int i = tid; i < TWO_D; i += 256) {
        int d = i >> 1;
        out[(size_t)q * TWO_D + i] = p[i] * gamma[d] * inv;
    }
}

// ---------------- launch ----------------
extern "C" void kernel_launch(void* const* d_in, const int* in_sizes, int n_in,
                              void* d_out, int out_size)
{
    const float* query = (const float*)d_in[0];
    const float* keys  = (const float*)d_in[1];
    const float* vals  = (const float*)d_in[2];
    const float* Wq_r  = (const float*)d_in[3];
    const float* Wq_i  = (const float*)d_in[4];
    const float* bq_r  = (const float*)d_in[5];
    const float* bq_i  = (const float*)d_in[6];
    const float* Wo_r  = (const float*)d_in[7];
    const float* Wo_i  = (const float*)d_in[8];
    const float* bo_r  = (const float*)d_in[9];
    const float* bo_i  = (const float*)d_in[10];
    const float* gamma = (const float*)d_in[11];
    float* out = (float*)d_out;

    void *p_q, *p_q8, *p_k8, *p_qmd, *p_kmd, *p_fq, *p_fk, *p_sc, *p_ret, *p_nrm;
    cudaGetSymbolAddress(&p_q,   g_q);
    cudaGetSymbolAddress(&p_q8,  g_q8);
    cudaGetSymbolAddress(&p_k8,  g_k8);
    cudaGetSymbolAddress(&p_qmd, g_qmagd);
    cudaGetSymbolAddress(&p_kmd, g_kmagd);
    cudaGetSymbolAddress(&p_fq,  g_fq);
    cudaGetSymbolAddress(&p_fk,  g_fk);
    cudaGetSymbolAddress(&p_sc,  g_scoresh);
    cudaGetSymbolAddress(&p_ret, g_ret);
    cudaGetSymbolAddress(&p_nrm, g_norm);
    float*  qbuf  = (float*)p_q;
    int8_t* q8    = (int8_t*)p_q8;
    int8_t* k8    = (int8_t*)p_k8;
    double* qmagd = (double*)p_qmd;
    double* kmagd = (double*)p_kmd;
    float*  fq    = (float*)p_fq;
    float*  fk    = (float*)p_fk;
    __half* sc    = (__half*)p_sc;
    float*  retb  = (float*)p_ret;
    float*  nrmb  = (float*)p_nrm;

    cudaFuncSetAttribute(coh_gemm_imma, cudaFuncAttributeMaxDynamicSharedMemorySize,
                         IGEMM_SMEM);

    dim3 gproj(DIM / 64, QROWS / 64);

    prep_kernel<<<NKEYS, 128>>>(keys, k8, kmagd, fk);          // 1
    cprojd_kernel<<<gproj, 256>>>(query, Wq_r, Wq_i, bq_r, bq_i, qbuf);  // 2
    prep_kernel<<<QROWS, 128>>>(qbuf, q8, qmagd, fq);          // 3

    dim3 ggemm(QROWS / ITM, NKEYS / ITN);
    coh_gemm_imma<<<ggemm, 512, IGEMM_SMEM>>>(q8, k8, fq, fk, sc);   // 4

    topk_kernel<<<QROWS, 256>>>(sc, qbuf, keys, qmagd, kmagd, vals, retb);  // 5
    norm_kernel<<<QROWS, 256>>>(retb, gamma, nrmb);            // 6
    cproj_kernel<<<gproj, 256>>>(nrmb, Wo_r, Wo_i, bo_r, bo_i, out);  // 7
}

// round 6
// speedup vs baseline: 1.9404x; 1.9404x over previous
#include <cuda_runtime.h>
#include <cuda_fp16.h>
#include <math.h>
#include <stdint.h>

#define QROWS 4096
#define DIM   512
#define TWO_D 1024
#define NKEYS 32768
#define TOPK  64
#define EPSF  1e-8f
#define NBINS 2048
#define CAP   1024

// ---- int8 IMMA GEMM config ----
#define ITM 128
#define ITN 256
#define IKC 128                    // int8 per k-chunk = 128B per row
#define IPITCH 144                 // bytes per smem row (4-bank step -> conflict-free)
#define IA_BYTES (128 * IPITCH)    // 18432
#define IB_BYTES (256 * IPITCH)    // 36864
#define ISTAGE (IA_BYTES + IB_BYTES)
#define IGEMM_SMEM (2 * ISTAGE)    // 110592, double buffered
#define ICHUNKS (TWO_D / IKC)      // 8

// ---------------- scratch (no allocations allowed) ----------------
__device__ float  g_q[(size_t)QROWS * TWO_D];        // precise projected q [Q, D, 2]
__device__ int8_t g_q8[(size_t)QROWS * TWO_D];
__device__ int8_t g_k8[(size_t)NKEYS * TWO_D];
__device__ double g_qmagd[QROWS];
__device__ double g_kmagd[NKEYS];
__device__ float  g_fq[QROWS];                       // (amax/127)/|q|
__device__ float  g_fk[NKEYS];
__device__ __half g_scoresh[(size_t)QROWS * NKEYS];  // 256 MB screening scores
__device__ float  g_ret[(size_t)QROWS * TWO_D];
__device__ float  g_norm[(size_t)QROWS * TWO_D];

// ---------------- helpers ----------------
__device__ __forceinline__ uint32_t smem_u32(const void* p) {
    uint32_t a;
    asm("{ .reg .u64 t; cvta.to.shared.u64 t, %1; cvt.u32.u64 %0, t; }" : "=r"(a) : "l"(p));
    return a;
}
__device__ __forceinline__ void cpasync16(uint32_t dst, const void* src) {
    asm volatile("cp.async.cg.shared.global [%0], [%1], 16;" :: "r"(dst), "l"(src) : "memory");
}
__device__ __forceinline__ void ldmx4(uint32_t* r, uint32_t a) {
    asm volatile("ldmatrix.sync.aligned.m8n8.x4.shared.b16 {%0,%1,%2,%3}, [%4];"
                 : "=r"(r[0]), "=r"(r[1]), "=r"(r[2]), "=r"(r[3]) : "r"(a));
}
__device__ __forceinline__ void mma_s8(int* d, const uint32_t* a, uint32_t b0, uint32_t b1) {
    asm volatile(
        "mma.sync.aligned.m16n8k32.row.col.s32.s8.s8.s32 "
        "{%0,%1,%2,%3}, {%4,%5,%6,%7}, {%8,%9}, {%0,%1,%2,%3};"
        : "+r"(d[0]), "+r"(d[1]), "+r"(d[2]), "+r"(d[3])
        : "r"(a[0]), "r"(a[1]), "r"(a[2]), "r"(a[3]), "r"(b0), "r"(b1));
}

// Kahan add, rounding-mode-pinned so fast-math/contraction cannot break it
__device__ __forceinline__ void kadd(float& s, float& c, float t) {
    float y = __fsub_rn(t, c);
    float u = __fadd_rn(s, y);
    c = __fsub_rn(__fsub_rn(u, s), y);
    s = u;
}

// ---------------- complex projection: Y = phase_linear(X, W, b) ----------------
// PRECISE=true -> Kahan compensated accumulation (q path feeding top-k selection).
template <bool PRECISE>
__global__ void __launch_bounds__(256)
cproj_kernel(const float* __restrict__ X,
             const float* __restrict__ Wr, const float* __restrict__ Wi,
             const float* __restrict__ br, const float* __restrict__ bi,
             float* __restrict__ Y)
{
    __shared__ float2 Xs[16][64];
    __shared__ float2 Ws[16][64];
    const int tid = threadIdx.x;
    const int m0 = blockIdx.y * 64;
    const int n0 = blockIdx.x * 64;
    const int kk = tid & 15;
    const int rr = tid >> 4;
    const int ty4 = (tid >> 4) * 4;
    const int tx4 = (tid & 15) * 4;

    float cr[4][4], ci[4][4], er[4][4], ei[4][4];
#pragma unroll
    for (int i = 0; i < 4; i++)
#pragma unroll
        for (int j = 0; j < 4; j++) { cr[i][j] = 0.f; ci[i][j] = 0.f; er[i][j] = 0.f; ei[i][j] = 0.f; }

    for (int k0 = 0; k0 < DIM; k0 += 16) {
#pragma unroll
        for (int r = 0; r < 4; r++) {
            int row = rr + r * 16;
            Xs[kk][row] = *(const float2*)&X[((size_t)(m0 + row) * DIM + k0 + kk) * 2];
            float wr = Wr[(size_t)(n0 + row) * DIM + k0 + kk];
            float wi = Wi[(size_t)(n0 + row) * DIM + k0 + kk];
            Ws[kk][row] = make_float2(wr, wi);
        }
        __syncthreads();
#pragma unroll
        for (int k = 0; k < 16; k++) {
            float2 a[4], w[4];
#pragma unroll
            for (int i = 0; i < 4; i++) a[i] = Xs[k][ty4 + i];
#pragma unroll
            for (int j = 0; j < 4; j++) w[j] = Ws[k][tx4 + j];
#pragma unroll
            for (int i = 0; i < 4; i++)
#pragma unroll
                for (int j = 0; j < 4; j++) {
                    if (PRECISE) {
                        kadd(cr[i][j], er[i][j],  __fmul_rn(a[i].x, w[j].x));
                        kadd(cr[i][j], er[i][j], -__fmul_rn(a[i].y, w[j].y));
                        kadd(ci[i][j], ei[i][j],  __fmul_rn(a[i].x, w[j].y));
                        kadd(ci[i][j], ei[i][j],  __fmul_rn(a[i].y, w[j].x));
                    } else {
                        cr[i][j] += a[i].x * w[j].x;
                        cr[i][j] -= a[i].y * w[j].y;
                        ci[i][j] += a[i].x * w[j].y;
                        ci[i][j] += a[i].y * w[j].x;
                    }
                }
        }
        __syncthreads();
    }
#pragma unroll
    for (int i = 0; i < 4; i++) {
        int m = m0 + ty4 + i;
#pragma unroll
        for (int j = 0; j < 4; j++) {
            int n = n0 + tx4 + j;
            float vr = PRECISE ? __fadd_rn(cr[i][j], er[i][j]) : cr[i][j];
            float vi = PRECISE ? __fadd_rn(ci[i][j], ei[i][j]) : ci[i][j];
            Y[((size_t)m * DIM + n) * 2 + 0] = vr + br[n];
            Y[((size_t)m * DIM + n) * 2 + 1] = vi + bi[n];
        }
    }
}

// ---------------- prep: per-row mag(double) + amax + int8 quantize + score scale ----------
__global__ void __launch_bounds__(128)
prep_kernel(const float* __restrict__ X, int8_t* __restrict__ X8,
            double* __restrict__ magd, float* __restrict__ fscale)
{
    __shared__ double smd[128];
    __shared__ float  sma[128];
    __shared__ float  s_qsc;
    const int row = blockIdx.x;
    const int tid = threadIdx.x;
    const float* p = X + (size_t)row * TWO_D;

    double s = 0.0;
    float amax = 0.f;
    for (int i = tid; i < TWO_D; i += 128) {
        float v = p[i];
        s += (double)v * (double)v;
        amax = fmaxf(amax, fabsf(v));
    }
    smd[tid] = s; sma[tid] = amax;
    __syncthreads();
    for (int o = 64; o > 0; o >>= 1) {
        if (tid < o) {
            smd[tid] += smd[tid + o];
            sma[tid] = fmaxf(sma[tid], sma[tid + o]);
        }
        __syncthreads();
    }
    if (tid == 0) {
        double m = sqrt(smd[0] + 1e-8);
        magd[row] = m;
        float am = sma[0];
        fscale[row] = (am > 0.f) ? (float)(((double)am / 127.0) / m) : 0.f;
        s_qsc = (am > 0.f) ? 127.f / am : 0.f;
    }
    __syncthreads();
    const float qsc = s_qsc;

    const int base = tid * 8;
    float4 v0 = *(const float4*)(p + base);
    float4 v1 = *(const float4*)(p + base + 4);
    int b[8];
    b[0] = __float2int_rn(v0.x * qsc); b[1] = __float2int_rn(v0.y * qsc);
    b[2] = __float2int_rn(v0.z * qsc); b[3] = __float2int_rn(v0.w * qsc);
    b[4] = __float2int_rn(v1.x * qsc); b[5] = __float2int_rn(v1.y * qsc);
    b[6] = __float2int_rn(v1.z * qsc); b[7] = __float2int_rn(v1.w * qsc);
#pragma unroll
    for (int i = 0; i < 8; i++) b[i] = max(-127, min(127, b[i]));
    uint32_t lo = (b[0] & 0xff) | ((b[1] & 0xff) << 8) | ((b[2] & 0xff) << 16) | ((b[3] & 0xff) << 24);
    uint32_t hi = (b[4] & 0xff) | ((b[5] & 0xff) << 8) | ((b[6] & 0xff) << 16) | ((b[7] & 0xff) << 24);
    *(uint2*)(X8 + (size_t)row * TWO_D + base) = make_uint2(lo, hi);
}

// ---------------- int8 IMMA screening GEMM ----------------
__device__ __forceinline__ void igemm_load_stage(
    const int8_t* A8, const int8_t* B8, uint32_t sb, int tid, int it, int s,
    int m0, int n0)
{
    const int seg = tid & 7;
    const int rowq = tid >> 3;                 // 0..63
    const size_t koff = (size_t)it * IKC + seg * 16;
    const uint32_t so = sb + (uint32_t)s * ISTAGE;
#pragma unroll
    for (int j = 0; j < 2; j++) {
        int row = rowq + 64 * j;
        cpasync16(so + row * IPITCH + seg * 16, A8 + (size_t)(m0 + row) * TWO_D + koff);
    }
#pragma unroll
    for (int j = 0; j < 4; j++) {
        int row = rowq + 64 * j;
        cpasync16(so + IA_BYTES + row * IPITCH + seg * 16, B8 + (size_t)(n0 + row) * TWO_D + koff);
    }
    asm volatile("cp.async.commit_group;" ::: "memory");
}

__global__ void __launch_bounds__(512, 1)
coh_gemm_imma(const int8_t* __restrict__ A8, const int8_t* __restrict__ B8,
              const float* __restrict__ fq, const float* __restrict__ fk,
              __half* __restrict__ C)
{
    extern __shared__ __align__(16) char smraw[];
    const uint32_t sb = smem_u32(smraw);
    const int tid = threadIdx.x;
    const int wid = tid >> 5, lane = tid & 31;
    const int m0 = blockIdx.x * ITM;           // x fastest -> B tile shared across wave
    const int n0 = blockIdx.y * ITN;
    const int wm = (wid & 3) * 32;
    const int wn = (wid >> 2) * 64;

    int acc[2][8][4];
#pragma unroll
    for (int a = 0; a < 2; a++)
#pragma unroll
        for (int b = 0; b < 8; b++)
#pragma unroll
            for (int c = 0; c < 4; c++) acc[a][b][c] = 0;

    igemm_load_stage(A8, B8, sb, tid, 0, 0, m0, n0);
    int buf = 0;
    const int lrow = lane & 15;
    const int lcol = (lane >> 4) * 16;

    for (int it = 0; it < ICHUNKS; it++) {
        if (it < ICHUNKS - 1) {
            igemm_load_stage(A8, B8, sb, tid, it + 1, buf ^ 1, m0, n0);
            asm volatile("cp.async.wait_group 1;" ::: "memory");
        } else {
            asm volatile("cp.async.wait_group 0;" ::: "memory");
        }
        __syncthreads();
        const uint32_t aB = sb + (uint32_t)buf * ISTAGE;
        const uint32_t bB = aB + IA_BYTES;
#pragma unroll
        for (int ks = 0; ks < 4; ks++) {
            uint32_t afr[2][4], bq[4][4];
#pragma unroll
            for (int fm = 0; fm < 2; fm++)
                ldmx4(afr[fm], aB + (wm + fm * 16 + lrow) * IPITCH + ks * 32 + lcol);
#pragma unroll
            for (int bg = 0; bg < 4; bg++)
                ldmx4(bq[bg], bB + (wn + bg * 16 + lrow) * IPITCH + ks * 32 + lcol);
#pragma unroll
            for (int fm = 0; fm < 2; fm++)
#pragma unroll
                for (int fn = 0; fn < 8; fn++) {
                    const int bg = fn >> 1, hf = fn & 1;
                    mma_s8(acc[fm][fn], afr[fm], bq[bg][hf], bq[bg][hf + 2]);
                }
        }
        __syncthreads();
        buf ^= 1;
    }

#pragma unroll
    for (int fm = 0; fm < 2; fm++) {
        const int rlo = m0 + wm + fm * 16 + (lane >> 2);
        const int rhi = rlo + 8;
        const float qlo = fq[rlo], qhi = fq[rhi];
#pragma unroll
        for (int fn = 0; fn < 8; fn++) {
            const int n = n0 + wn + ((fn >> 1) * 16 + (fn & 1) * 8) + (lane & 3) * 2;
            const float k0v = fk[n], k1v = fk[n + 1];
            __half2 hlo, hhi;
            hlo.x = __float2half_rn((float)acc[fm][fn][0] * qlo * k0v);
            hlo.y = __float2half_rn((float)acc[fm][fn][1] * qlo * k1v);
            hhi.x = __float2half_rn((float)acc[fm][fn][2] * qhi * k0v);
            hhi.y = __float2half_rn((float)acc[fm][fn][3] * qhi * k1v);
            *(__half2*)&C[(size_t)rlo * NKEYS + n] = hlo;
            *(__half2*)&C[(size_t)rhi * NKEYS + n] = hhi;
        }
    }
}

// ---------------- top-64 (screen -> double rescore -> select) + softmax + gather ---------
__global__ void __launch_bounds__(256)
topk_kernel(const __half* __restrict__ scores,
            const float* __restrict__ qbuf,
            const float* __restrict__ keys,
            const double* __restrict__ qmagd,
            const double* __restrict__ kmagd,
            const float* __restrict__ values,
            float* __restrict__ ret)
{
    __shared__ int    hist[NBINS];
    __shared__ int    csum[256];
    __shared__ float  qs[TWO_D];
    __shared__ double cand_d[CAP];
    __shared__ int    cand_i[CAP];
    __shared__ int    s_cnt;
    __shared__ int    s_thresh;
    __shared__ double sel_d[TOPK];
    __shared__ int    sel_i[TOPK];
    __shared__ float  s_w[TOPK];
    __shared__ double redv[8];
    __shared__ int    redi[8];

    const int q = blockIdx.x;
    const int tid = threadIdx.x;
    const __half* row = scores + (size_t)q * NKEYS;

    for (int i = tid; i < NBINS; i += 256) hist[i] = 0;
    for (int i = tid; i < TWO_D; i += 256) qs[i] = qbuf[(size_t)q * TWO_D + i];
    if (tid == 0) s_cnt = 0;
    __syncthreads();

    for (int i = tid; i < NKEYS; i += 256) {
        float s = __half2float(row[i]);
        int b = (int)floorf((s + 1.0f) * 1024.0f);
        b = max(0, min(NBINS - 1, b));
        atomicAdd(&hist[b], 1);
    }
    __syncthreads();

    {
        int c = 0;
#pragma unroll
        for (int j = 0; j < 8; j++) c += hist[tid * 8 + j];
        csum[tid] = c;
    }
    __syncthreads();
    if (tid == 0) {
        int acc = 0, thr = 0;
        for (int ch = 255; ch >= 0; ch--) {
            if (acc + csum[ch] >= TOPK) {
                for (int b = ch * 8 + 7; b >= ch * 8; b--) {
                    acc += hist[b];
                    if (acc >= TOPK) { thr = b; break; }
                }
                break;
            }
            acc += csum[ch];
        }
        s_thresh = max(thr - 4, 0);   // 4-bin margin (3.9e-3) ~ 12 sigma of int8 screen error
    }
    __syncthreads();
    const int thresh = s_thresh;

    for (int i = tid; i < NKEYS; i += 256) {
        float s = __half2float(row[i]);
        int b = (int)floorf((s + 1.0f) * 1024.0f);
        b = max(0, min(NBINS - 1, b));
        if (b >= thresh) {
            int pos = atomicAdd(&s_cnt, 1);
            if (pos < CAP) cand_i[pos] = i;
        }
    }
    __syncthreads();
    const int cnt = min(s_cnt, CAP);

    // ---- double-precision rescore of candidates (one warp per candidate) ----
    {
        const int wid = tid >> 5, lane = tid & 31;
        const double qm = qmagd[q];
        for (int c = wid; c < cnt; c += 8) {
            const int ki = cand_i[c];
            const float* kr = keys + (size_t)ki * TWO_D;
            double acc = 0.0;
#pragma unroll
            for (int t = 0; t < 8; t++) {
                int e = t * 128 + lane * 4;
                float4 kv = *(const float4*)(kr + e);
                acc += (double)qs[e]     * (double)kv.x;
                acc += (double)qs[e + 1] * (double)kv.y;
                acc += (double)qs[e + 2] * (double)kv.z;
                acc += (double)qs[e + 3] * (double)kv.w;
            }
#pragma unroll
            for (int o = 16; o > 0; o >>= 1)
                acc += __shfl_down_sync(0xffffffffu, acc, o);
            if (lane == 0) cand_d[c] = acc / (qm * kmagd[ki] + (double)EPSF);
        }
    }
    __syncthreads();

    for (int t = 0; t < TOPK; t++) {
        double bv = -1e300; int bi = 0;
        for (int i = tid; i < cnt; i += 256) {
            double v = cand_d[i];
            if (v > bv) { bv = v; bi = i; }
        }
#pragma unroll
        for (int o = 16; o > 0; o >>= 1) {
            double ov = __shfl_down_sync(0xffffffffu, bv, o);
            int    oi = __shfl_down_sync(0xffffffffu, bi, o);
            if (ov > bv) { bv = ov; bi = oi; }
        }
        if ((tid & 31) == 0) { redv[tid >> 5] = bv; redi[tid >> 5] = bi; }
        __syncthreads();
        if (tid == 0) {
            double fv = redv[0]; int fi = redi[0];
#pragma unroll
            for (int w = 1; w < 8; w++)
                if (redv[w] > fv) { fv = redv[w]; fi = redi[w]; }
            sel_d[t] = fv; sel_i[t] = cand_i[fi];
            cand_d[fi] = -1e300;
        }
        __syncthreads();
    }

    if (tid == 0) {
        float m = (float)sel_d[0];
        float z = 0.f;
        for (int t = 0; t < TOPK; t++) { float w = expf((float)sel_d[t] - m); s_w[t] = w; z += w; }
        float inv = 1.0f / z;
        for (int t = 0; t < TOPK; t++) s_w[t] *= inv;
    }
    __syncthreads();

    const int col = tid * 4;
    float4 acc = make_float4(0.f, 0.f, 0.f, 0.f);
    for (int t = 0; t < TOPK; t++) {
        const float4 v = *(const float4*)&values[(size_t)sel_i[t] * TWO_D + col];
        float w = s_w[t];
        acc.x += w * v.x; acc.y += w * v.y; acc.z += w * v.z; acc.w += w * v.w;
    }
    *(float4*)&ret[(size_t)q * TWO_D + col] = acc;
}

// ---------------- phase norm: x * gamma[d] / rms(row) ----------------
__global__ void __launch_bounds__(256)
norm_kernel(const float* __restrict__ ret, const float* __restrict__ gamma,
            float* __restrict__ out)
{
    __shared__ float sm[256];
    __shared__ float s_inv;
    const int q = blockIdx.x;
    const int tid = threadIdx.x;
    const float* p = ret + (size_t)q * TWO_D;
    float s = 0.f;
    for (int i = tid; i < TWO_D; i += 256) { float v = p[i]; s += v * v; }
    sm[tid] = s;
    __syncthreads();
    for (int o = 128; o > 0; o >>= 1) {
        if (tid < o) sm[tid] += sm[tid + o];
        __syncthreads();
    }
    if (tid == 0) {
        float mean = sm[0] / (float)DIM;
        s_inv = 1.0f / sqrtf(mean + EPSF);
    }
    __syncthreads();
    const float inv = s_inv;
    for (int i = tid; i < TWO_D; i += 256) {
        int d = i >> 1;
        out[(size_t)q * TWO_D + i] = p[i] * gamma[d] * inv;
    }
}

// ---------------- launch ----------------
extern "C" void kernel_launch(void* const* d_in, const int* in_sizes, int n_in,
                              void* d_out, int out_size)
{
    const float* query = (const float*)d_in[0];
    const float* keys  = (const float*)d_in[1];
    const float* vals  = (const float*)d_in[2];
    const float* Wq_r  = (const float*)d_in[3];
    const float* Wq_i  = (const float*)d_in[4];
    const float* bq_r  = (const float*)d_in[5];
    const float* bq_i  = (const float*)d_in[6];
    const float* Wo_r  = (const float*)d_in[7];
    const float* Wo_i  = (const float*)d_in[8];
    const float* bo_r  = (const float*)d_in[9];
    const float* bo_i  = (const float*)d_in[10];
    const float* gamma = (const float*)d_in[11];
    float* out = (float*)d_out;

    void *p_q, *p_q8, *p_k8, *p_qmd, *p_kmd, *p_fq, *p_fk, *p_sc, *p_ret, *p_nrm;
    cudaGetSymbolAddress(&p_q,   g_q);
    cudaGetSymbolAddress(&p_q8,  g_q8);
    cudaGetSymbolAddress(&p_k8,  g_k8);
    cudaGetSymbolAddress(&p_qmd, g_qmagd);
    cudaGetSymbolAddress(&p_kmd, g_kmagd);
    cudaGetSymbolAddress(&p_fq,  g_fq);
    cudaGetSymbolAddress(&p_fk,  g_fk);
    cudaGetSymbolAddress(&p_sc,  g_scoresh);
    cudaGetSymbolAddress(&p_ret, g_ret);
    cudaGetSymbolAddress(&p_nrm, g_norm);
    float*  qbuf  = (float*)p_q;
    int8_t* q8    = (int8_t*)p_q8;
    int8_t* k8    = (int8_t*)p_k8;
    double* qmagd = (double*)p_qmd;
    double* kmagd = (double*)p_kmd;
    float*  fq    = (float*)p_fq;
    float*  fk    = (float*)p_fk;
    __half* sc    = (__half*)p_sc;
    float*  retb  = (float*)p_ret;
    float*  nrmb  = (float*)p_nrm;

    cudaFuncSetAttribute(coh_gemm_imma, cudaFuncAttributeMaxDynamicSharedMemorySize,
                         IGEMM_SMEM);

    dim3 gproj(DIM / 64, QROWS / 64);

    prep_kernel<<<NKEYS, 128>>>(keys, k8, kmagd, fk);
    cproj_kernel<true><<<gproj, 256>>>(query, Wq_r, Wq_i, bq_r, bq_i, qbuf);
    prep_kernel<<<QROWS, 128>>>(qbuf, q8, qmagd, fq);

    dim3 ggemm(QROWS / ITM, NKEYS / ITN);
    coh_gemm_imma<<<ggemm, 512, IGEMM_SMEM>>>(q8, k8, fq, fk, sc);

    topk_kernel<<<QROWS, 256>>>(sc, qbuf, keys, qmagd, kmagd, vals, retb);
    norm_kernel<<<QROWS, 256>>>(retb, gamma, nrmb);
    cproj_kernel<false><<<gproj, 256>>>(nrmb, Wo_r, Wo_i, bo_r, bo_i, out);
}

// round 7
// speedup vs baseline: 2.6686x; 1.3753x over previous
#include <cuda_runtime.h>
#include <cuda_fp16.h>
#include <cuda_bf16.h>
#include <math.h>
#include <stdint.h>

#define QROWS 4096
#define DIM   512
#define TWO_D 1024
#define NKEYS 32768
#define TOPK  64
#define EPSF  1e-8f
#define NBINS 2048
#define CAP   1024

// ---- bf16 mma.sync GEMM config (round-4 proven) ----
#define GTM 128
#define GTN 128
#define GKC 64                    // bf16 per k-chunk = 128B per row
#define TILE_BYTES (128 * 144)    // 18432 per operand tile (144B pitch, conflict-free)
#define STAGE_BYTES (2 * TILE_BYTES)
#define GEMM_SMEM (2 * STAGE_BYTES)   // 73728, double buffered
#define KCHUNKS (TWO_D / GKC)     // 16

// ---------------- scratch (no allocations allowed) ----------------
__device__ float  g_q[(size_t)QROWS * TWO_D];        // precise projected q [Q, D, 2]
__device__ __nv_bfloat16 g_qh[(size_t)QROWS * TWO_D];
__device__ __nv_bfloat16 g_kh[(size_t)NKEYS * TWO_D];
__device__ double g_qmagd[QROWS];
__device__ float  g_qmagf[QROWS];
__device__ double g_kmagd[NKEYS];
__device__ float  g_kmagf[NKEYS];
__device__ __half g_scoresh[(size_t)QROWS * NKEYS];  // 256 MB screening scores
__device__ float  g_ret[(size_t)QROWS * TWO_D];
__device__ float  g_norm[(size_t)QROWS * TWO_D];

// ---------------- helpers ----------------
__device__ __forceinline__ uint32_t smem_u32(const void* p) {
    uint32_t a;
    asm("{ .reg .u64 t; cvta.to.shared.u64 t, %1; cvt.u32.u64 %0, t; }" : "=r"(a) : "l"(p));
    return a;
}
__device__ __forceinline__ void cpasync16(uint32_t dst, const void* src) {
    asm volatile("cp.async.cg.shared.global [%0], [%1], 16;" :: "r"(dst), "l"(src) : "memory");
}
__device__ __forceinline__ void ldmx4(uint32_t* r, uint32_t a) {
    asm volatile("ldmatrix.sync.aligned.m8n8.x4.shared.b16 {%0,%1,%2,%3}, [%4];"
                 : "=r"(r[0]), "=r"(r[1]), "=r"(r[2]), "=r"(r[3]) : "r"(a));
}
__device__ __forceinline__ void ldmx2(uint32_t* r, uint32_t a) {
    asm volatile("ldmatrix.sync.aligned.m8n8.x2.shared.b16 {%0,%1}, [%2];"
                 : "=r"(r[0]), "=r"(r[1]) : "r"(a));
}
__device__ __forceinline__ void mma_bf16(float* d, const uint32_t* a, const uint32_t* b) {
    asm volatile(
        "mma.sync.aligned.m16n8k16.row.col.f32.bf16.bf16.f32 "
        "{%0,%1,%2,%3}, {%4,%5,%6,%7}, {%8,%9}, {%0,%1,%2,%3};"
        : "+f"(d[0]), "+f"(d[1]), "+f"(d[2]), "+f"(d[3])
        : "r"(a[0]), "r"(a[1]), "r"(a[2]), "r"(a[3]), "r"(b[0]), "r"(b[1]));
}

// Kahan add, rounding-mode-pinned so fast-math/contraction cannot break it
__device__ __forceinline__ void kadd(float& s, float& c, float t) {
    float y = __fsub_rn(t, c);
    float u = __fadd_rn(s, y);
    c = __fsub_rn(__fsub_rn(u, s), y);
    s = u;
}

// ---------------- complex projection: Y = phase_linear(X, W, b) ----------------
template <bool PRECISE>
__global__ void __launch_bounds__(256)
cproj_kernel(const float* __restrict__ X,
             const float* __restrict__ Wr, const float* __restrict__ Wi,
             const float* __restrict__ br, const float* __restrict__ bi,
             float* __restrict__ Y)
{
    __shared__ float2 Xs[16][64];
    __shared__ float2 Ws[16][64];
    const int tid = threadIdx.x;
    const int m0 = blockIdx.y * 64;
    const int n0 = blockIdx.x * 64;
    const int kk = tid & 15;
    const int rr = tid >> 4;
    const int ty4 = (tid >> 4) * 4;
    const int tx4 = (tid & 15) * 4;

    float cr[4][4], ci[4][4], er[4][4], ei[4][4];
#pragma unroll
    for (int i = 0; i < 4; i++)
#pragma unroll
        for (int j = 0; j < 4; j++) { cr[i][j] = 0.f; ci[i][j] = 0.f; er[i][j] = 0.f; ei[i][j] = 0.f; }

    for (int k0 = 0; k0 < DIM; k0 += 16) {
#pragma unroll
        for (int r = 0; r < 4; r++) {
            int row = rr + r * 16;
            Xs[kk][row] = *(const float2*)&X[((size_t)(m0 + row) * DIM + k0 + kk) * 2];
            float wr = Wr[(size_t)(n0 + row) * DIM + k0 + kk];
            float wi = Wi[(size_t)(n0 + row) * DIM + k0 + kk];
            Ws[kk][row] = make_float2(wr, wi);
        }
        __syncthreads();
#pragma unroll
        for (int k = 0; k < 16; k++) {
            float2 a[4], w[4];
#pragma unroll
            for (int i = 0; i < 4; i++) a[i] = Xs[k][ty4 + i];
#pragma unroll
            for (int j = 0; j < 4; j++) w[j] = Ws[k][tx4 + j];
#pragma unroll
            for (int i = 0; i < 4; i++)
#pragma unroll
                for (int j = 0; j < 4; j++) {
                    if (PRECISE) {
                        kadd(cr[i][j], er[i][j],  __fmul_rn(a[i].x, w[j].x));
                        kadd(cr[i][j], er[i][j], -__fmul_rn(a[i].y, w[j].y));
                        kadd(ci[i][j], ei[i][j],  __fmul_rn(a[i].x, w[j].y));
                        kadd(ci[i][j], ei[i][j],  __fmul_rn(a[i].y, w[j].x));
                    } else {
                        cr[i][j] += a[i].x * w[j].x;
                        cr[i][j] -= a[i].y * w[j].y;
                        ci[i][j] += a[i].x * w[j].y;
                        ci[i][j] += a[i].y * w[j].x;
                    }
                }
        }
        __syncthreads();
    }
#pragma unroll
    for (int i = 0; i < 4; i++) {
        int m = m0 + ty4 + i;
#pragma unroll
        for (int j = 0; j < 4; j++) {
            int n = n0 + tx4 + j;
            float vr = PRECISE ? __fadd_rn(cr[i][j], er[i][j]) : cr[i][j];
            float vi = PRECISE ? __fadd_rn(ci[i][j], ei[i][j]) : ci[i][j];
            Y[((size_t)m * DIM + n) * 2 + 0] = vr + br[n];
            Y[((size_t)m * DIM + n) * 2 + 1] = vi + bi[n];
        }
    }
}

// ---------------- fused prep: double mag + fp32 mag + bf16 conversion ----------------
__global__ void __launch_bounds__(128)
prep_bf16_kernel(const float* __restrict__ X, __nv_bfloat16* __restrict__ Xh,
                 double* __restrict__ out_d, float* __restrict__ out_f)
{
    __shared__ double sm[128];
    const int row = blockIdx.x;
    const int tid = threadIdx.x;
    const float* p = X + (size_t)row * TWO_D;
    const int base = tid * 8;

    float4 v0 = *(const float4*)(p + base);
    float4 v1 = *(const float4*)(p + base + 4);

    double s = (double)v0.x * v0.x + (double)v0.y * v0.y
             + (double)v0.z * v0.z + (double)v0.w * v0.w
             + (double)v1.x * v1.x + (double)v1.y * v1.y
             + (double)v1.z * v1.z + (double)v1.w * v1.w;

    __nv_bfloat162 b0 = __float22bfloat162_rn(make_float2(v0.x, v0.y));
    __nv_bfloat162 b1 = __float22bfloat162_rn(make_float2(v0.z, v0.w));
    __nv_bfloat162 b2 = __float22bfloat162_rn(make_float2(v1.x, v1.y));
    __nv_bfloat162 b3 = __float22bfloat162_rn(make_float2(v1.z, v1.w));
    uint4 packed;
    packed.x = *(uint32_t*)&b0; packed.y = *(uint32_t*)&b1;
    packed.z = *(uint32_t*)&b2; packed.w = *(uint32_t*)&b3;
    *(uint4*)(Xh + (size_t)row * TWO_D + base) = packed;

    sm[tid] = s;
    __syncthreads();
    for (int o = 64; o > 0; o >>= 1) {
        if (tid < o) sm[tid] += sm[tid + o];
        __syncthreads();
    }
    if (tid == 0) {
        double m = sqrt(sm[0] + 1e-8);
        out_d[row] = m;
        out_f[row] = (float)m;
    }
}

// ---------------- bf16 mma.sync screening GEMM (round-4 mainloop, half output) ---------
__device__ __forceinline__ void gemm_load_stage(
    const char* Abase, const char* Bbase, uint32_t sb, int tid, int it, int s)
{
    const int seg = tid & 7;
    const size_t koff = (size_t)it * 128 + (size_t)seg * 16;
    const uint32_t so = sb + (uint32_t)s * STAGE_BYTES;
#pragma unroll
    for (int j = 0; j < 4; j++) {
        int row = (tid >> 3) + 32 * j;
        cpasync16(so + row * 144 + seg * 16, Abase + (size_t)row * 2048 + koff);
    }
#pragma unroll
    for (int j = 0; j < 4; j++) {
        int row = (tid >> 3) + 32 * j;
        cpasync16(so + TILE_BYTES + row * 144 + seg * 16, Bbase + (size_t)row * 2048 + koff);
    }
    asm volatile("cp.async.commit_group;" ::: "memory");
}

__global__ void __launch_bounds__(256, 2)
coh_gemm_mma(const __nv_bfloat16* __restrict__ A, const __nv_bfloat16* __restrict__ B,
             const float* __restrict__ qmag, const float* __restrict__ kmag,
             __half* __restrict__ C)
{
    extern __shared__ __align__(16) char smraw[];
    const uint32_t sb = smem_u32(smraw);
    const int tid = threadIdx.x;
    const int wid = tid >> 5, lane = tid & 31;
    const int m0 = blockIdx.x * GTM;     // m fastest -> B tile shared in-wave
    const int n0 = blockIdx.y * GTN;
    const int wm0 = (wid & 1) * 64, wn0 = (wid >> 1) * 32;

    float acc[4][4][4];
#pragma unroll
    for (int a = 0; a < 4; a++)
#pragma unroll
        for (int b = 0; b < 4; b++)
#pragma unroll
            for (int c = 0; c < 4; c++) acc[a][b][c] = 0.f;

    const char* Abase = (const char*)A + (size_t)m0 * 2048;
    const char* Bbase = (const char*)B + (size_t)n0 * 2048;

    gemm_load_stage(Abase, Bbase, sb, tid, 0, 0);
    int buf = 0;
    const int arow = lane & 15, acol = (lane >> 4) * 8;
    const int brow = lane & 7,  bcol = ((lane >> 3) & 1) * 8;

    for (int it = 0; it < KCHUNKS; it++) {
        if (it < KCHUNKS - 1) {
            gemm_load_stage(Abase, Bbase, sb, tid, it + 1, buf ^ 1);
            asm volatile("cp.async.wait_group 1;" ::: "memory");
        } else {
            asm volatile("cp.async.wait_group 0;" ::: "memory");
        }
        __syncthreads();
        const uint32_t aB = sb + (uint32_t)buf * STAGE_BYTES;
        const uint32_t bB = aB + TILE_BYTES;
#pragma unroll
        for (int ks = 0; ks < 4; ks++) {
            uint32_t afr[4][4], bfr[4][2];
#pragma unroll
            for (int fm = 0; fm < 4; fm++)
                ldmx4(afr[fm], aB + (wm0 + fm * 16 + arow) * 144 + (ks * 16 + acol) * 2);
#pragma unroll
            for (int fn = 0; fn < 4; fn++)
                ldmx2(bfr[fn], bB + (wn0 + fn * 8 + brow) * 144 + (ks * 16 + bcol) * 2);
#pragma unroll
            for (int fm = 0; fm < 4; fm++)
#pragma unroll
                for (int fn = 0; fn < 4; fn++)
                    mma_bf16(acc[fm][fn], afr[fm], bfr[fn]);
        }
        __syncthreads();
        buf ^= 1;
    }

    // epilogue: normalize + half store
#pragma unroll
    for (int fm = 0; fm < 4; fm++) {
        int mlo = m0 + wm0 + fm * 16 + (lane >> 2);
        int mhi = mlo + 8;
        float qlo = qmag[mlo], qhi = qmag[mhi];
#pragma unroll
        for (int fn = 0; fn < 4; fn++) {
            int n = n0 + wn0 + fn * 8 + (lane & 3) * 2;
            float k0v = kmag[n], k1v = kmag[n + 1];
            __half2 hlo, hhi;
            hlo.x = __float2half_rn(acc[fm][fn][0] / (qlo * k0v + EPSF));
            hlo.y = __float2half_rn(acc[fm][fn][1] / (qlo * k1v + EPSF));
            hhi.x = __float2half_rn(acc[fm][fn][2] / (qhi * k0v + EPSF));
            hhi.y = __float2half_rn(acc[fm][fn][3] / (qhi * k1v + EPSF));
            *(__half2*)&C[(size_t)mlo * NKEYS + n] = hlo;
            *(__half2*)&C[(size_t)mhi * NKEYS + n] = hhi;
        }
    }
}

// ---------------- top-64 (screen -> double rescore -> select) + softmax + gather ---------
__global__ void __launch_bounds__(256)
topk_kernel(const __half* __restrict__ scores,
            const float* __restrict__ qbuf,
            const float* __restrict__ keys,
            const double* __restrict__ qmagd,
            const double* __restrict__ kmagd,
            const float* __restrict__ values,
            float* __restrict__ ret)
{
    __shared__ int    hist[NBINS];
    __shared__ int    csum[256];
    __shared__ float  qs[TWO_D];
    __shared__ double cand_d[CAP];
    __shared__ int    cand_i[CAP];
    __shared__ int    s_cnt;
    __shared__ int    s_thresh;
    __shared__ double sel_d[TOPK];
    __shared__ int    sel_i[TOPK];
    __shared__ float  s_w[TOPK];
    __shared__ double redv[8];
    __shared__ int    redi[8];

    const int q = blockIdx.x;
    const int tid = threadIdx.x;
    const __half* row = scores + (size_t)q * NKEYS;

    for (int i = tid; i < NBINS; i += 256) hist[i] = 0;
    for (int i = tid; i < TWO_D; i += 256) qs[i] = qbuf[(size_t)q * TWO_D + i];
    if (tid == 0) s_cnt = 0;
    __syncthreads();

    for (int i = tid; i < NKEYS; i += 256) {
        float s = __half2float(row[i]);
        int b = (int)floorf((s + 1.0f) * 1024.0f);
        b = max(0, min(NBINS - 1, b));
        atomicAdd(&hist[b], 1);
    }
    __syncthreads();

    {
        int c = 0;
#pragma unroll
        for (int j = 0; j < 8; j++) c += hist[tid * 8 + j];
        csum[tid] = c;
    }
    __syncthreads();
    if (tid == 0) {
        int acc = 0, thr = 0;
        for (int ch = 255; ch >= 0; ch--) {
            if (acc + csum[ch] >= TOPK) {
                for (int b = ch * 8 + 7; b >= ch * 8; b--) {
                    acc += hist[b];
                    if (acc >= TOPK) { thr = b; break; }
                }
                break;
            }
            acc += csum[ch];
        }
        s_thresh = max(thr - 2, 0);   // 2-bin margin (1.95e-3) >> bf16 screen + half store error
    }
    __syncthreads();
    const int thresh = s_thresh;

    for (int i = tid; i < NKEYS; i += 256) {
        float s = __half2float(row[i]);
        int b = (int)floorf((s + 1.0f) * 1024.0f);
        b = max(0, min(NBINS - 1, b));
        if (b >= thresh) {
            int pos = atomicAdd(&s_cnt, 1);
            if (pos < CAP) cand_i[pos] = i;
        }
    }
    __syncthreads();
    const int cnt = min(s_cnt, CAP);

    // ---- double-precision rescore of candidates (one warp per candidate) ----
    {
        const int wid = tid >> 5, lane = tid & 31;
        const double qm = qmagd[q];
        for (int c = wid; c < cnt; c += 8) {
            const int ki = cand_i[c];
            const float* kr = keys + (size_t)ki * TWO_D;
            double acc = 0.0;
#pragma unroll
            for (int t = 0; t < 8; t++) {
                int e = t * 128 + lane * 4;
                float4 kv = *(const float4*)(kr + e);
                acc += (double)qs[e]     * (double)kv.x;
                acc += (double)qs[e + 1] * (double)kv.y;
                acc += (double)qs[e + 2] * (double)kv.z;
                acc += (double)qs[e + 3] * (double)kv.w;
            }
#pragma unroll
            for (int o = 16; o > 0; o >>= 1)
                acc += __shfl_down_sync(0xffffffffu, acc, o);
            if (lane == 0) cand_d[c] = acc / (qm * kmagd[ki] + (double)EPSF);
        }
    }
    __syncthreads();

    for (int t = 0; t < TOPK; t++) {
        double bv = -1e300; int bi = 0;
        for (int i = tid; i < cnt; i += 256) {
            double v = cand_d[i];
            if (v > bv) { bv = v; bi = i; }
        }
#pragma unroll
        for (int o = 16; o > 0; o >>= 1) {
            double ov = __shfl_down_sync(0xffffffffu, bv, o);
            int    oi = __shfl_down_sync(0xffffffffu, bi, o);
            if (ov > bv) { bv = ov; bi = oi; }
        }
        if ((tid & 31) == 0) { redv[tid >> 5] = bv; redi[tid >> 5] = bi; }
        __syncthreads();
        if (tid == 0) {
            double fv = redv[0]; int fi = redi[0];
#pragma unroll
            for (int w = 1; w < 8; w++)
                if (redv[w] > fv) { fv = redv[w]; fi = redi[w]; }
            sel_d[t] = fv; sel_i[t] = cand_i[fi];
            cand_d[fi] = -1e300;
        }
        __syncthreads();
    }

    if (tid == 0) {
        float m = (float)sel_d[0];
        float z = 0.f;
        for (int t = 0; t < TOPK; t++) { float w = expf((float)sel_d[t] - m); s_w[t] = w; z += w; }
        float inv = 1.0f / z;
        for (int t = 0; t < TOPK; t++) s_w[t] *= inv;
    }
    __syncthreads();

    const int col = tid * 4;
    float4 acc = make_float4(0.f, 0.f, 0.f, 0.f);
    for (int t = 0; t < TOPK; t++) {
        const float4 v = *(const float4*)&values[(size_t)sel_i[t] * TWO_D + col];
        float w = s_w[t];
        acc.x += w * v.x; acc.y += w * v.y; acc.z += w * v.z; acc.w += w * v.w;
    }
    *(float4*)&ret[(size_t)q * TWO_D + col] = acc;
}

// ---------------- phase norm: x * gamma[d] / rms(row) ----------------
__global__ void __launch_bounds__(256)
norm_kernel(const float* __restrict__ ret, const float* __restrict__ gamma,
            float* __restrict__ out)
{
    __shared__ float sm[256];
    __shared__ float s_inv;
    const int q = blockIdx.x;
    const int tid = threadIdx.x;
    const float* p = ret + (size_t)q * TWO_D;
    float s = 0.f;
    for (int i = tid; i < TWO_D; i += 256) { float v = p[i]; s += v * v; }
    sm[tid] = s;
    __syncthreads();
    for (int o = 128; o > 0; o >>= 1) {
        if (tid < o) sm[tid] += sm[tid + o];
        __syncthreads();
    }
    if (tid == 0) {
        float mean = sm[0] / (float)DIM;
        s_inv = 1.0f / sqrtf(mean + EPSF);
    }
    __syncthreads();
    const float inv = s_inv;
    for (int i = tid; i < TWO_D; i += 256) {
        int d = i >> 1;
        out[(size_t)q * TWO_D + i] = p[i] * gamma[d] * inv;
    }
}

// ---------------- launch ----------------
extern "C" void kernel_launch(void* const* d_in, const int* in_sizes, int n_in,
                              void* d_out, int out_size)
{
    const float* query = (const float*)d_in[0];
    const float* keys  = (const float*)d_in[1];
    const float* vals  = (const float*)d_in[2];
    const float* Wq_r  = (const float*)d_in[3];
    const float* Wq_i  = (const float*)d_in[4];
    const float* bq_r  = (const float*)d_in[5];
    const float* bq_i  = (const float*)d_in[6];
    const float* Wo_r  = (const float*)d_in[7];
    const float* Wo_i  = (const float*)d_in[8];
    const float* bo_r  = (const float*)d_in[9];
    const float* bo_i  = (const float*)d_in[10];
    const float* gamma = (const float*)d_in[11];
    float* out = (float*)d_out;

    void *p_q, *p_qh, *p_kh, *p_qmd, *p_qmf, *p_kmd, *p_kmf, *p_sc, *p_ret, *p_nrm;
    cudaGetSymbolAddress(&p_q,   g_q);
    cudaGetSymbolAddress(&p_qh,  g_qh);
    cudaGetSymbolAddress(&p_kh,  g_kh);
    cudaGetSymbolAddress(&p_qmd, g_qmagd);
    cudaGetSymbolAddress(&p_qmf, g_qmagf);
    cudaGetSymbolAddress(&p_kmd, g_kmagd);
    cudaGetSymbolAddress(&p_kmf, g_kmagf);
    cudaGetSymbolAddress(&p_sc,  g_scoresh);
    cudaGetSymbolAddress(&p_ret, g_ret);
    cudaGetSymbolAddress(&p_nrm, g_norm);
    float*  qbuf  = (float*)p_q;
    __nv_bfloat16* qh = (__nv_bfloat16*)p_qh;
    __nv_bfloat16* kh = (__nv_bfloat16*)p_kh;
    double* qmagd = (double*)p_qmd;
    float*  qmagf = (float*)p_qmf;
    double* kmagd = (double*)p_kmd;
    float*  kmagf = (float*)p_kmf;
    __half* sc    = (__half*)p_sc;
    float*  retb  = (float*)p_ret;
    float*  nrmb  = (float*)p_nrm;

    cudaFuncSetAttribute(coh_gemm_mma, cudaFuncAttributeMaxDynamicSharedMemorySize, GEMM_SMEM);

    dim3 gproj(DIM / 64, QROWS / 64);

    prep_bf16_kernel<<<NKEYS, 128>>>(keys, kh, kmagd, kmagf);              // 1
    cproj_kernel<true><<<gproj, 256>>>(query, Wq_r, Wq_i, bq_r, bq_i, qbuf); // 2
    prep_bf16_kernel<<<QROWS, 128>>>(qbuf, qh, qmagd, qmagf);              // 3

    dim3 ggemm(QROWS / GTM, NKEYS / GTN);
    coh_gemm_mma<<<ggemm, 256, GEMM_SMEM>>>(qh, kh, qmagf, kmagf, sc);     // 4 (ncu slot)

    topk_kernel<<<QROWS, 256>>>(sc, qbuf, keys, qmagd, kmagd, vals, retb); // 5
    norm_kernel<<<QROWS, 256>>>(retb, gamma, nrmb);                        // 6
    cproj_kernel<false><<<gproj, 256>>>(nrmb, Wo_r, Wo_i, bo_r, bo_i, out); // 7
}

// round 8
// speedup vs baseline: 3.9694x; 1.4874x over previous
#include <cuda_runtime.h>
#include <cuda_fp16.h>
#include <cuda_bf16.h>
#include <math.h>
#include <stdint.h>

#define QROWS 4096
#define DIM   512
#define TWO_D 1024
#define NKEYS 32768
#define TOPK  64
#define EPSF  1e-8f
#define NBINS 2048
#define CAP   1024

// ---- bf16 mma.sync GEMM config ----
#define GTM 128
#define GTN 128
#define TILE_BYTES (128 * 144)
#define STAGE_BYTES (2 * TILE_BYTES)
#define GEMM_SMEM (2 * STAGE_BYTES)
#define KCHUNKS 16

// ---------------- scratch (no allocations allowed) ----------------
__device__ float  g_q[(size_t)QROWS * TWO_D];
__device__ __nv_bfloat16 g_qh[(size_t)QROWS * TWO_D];
__device__ __nv_bfloat16 g_kh[(size_t)NKEYS * TWO_D];
__device__ double g_qmagd[QROWS];
__device__ float  g_qmagf[QROWS];
__device__ double g_kmagd[NKEYS];
__device__ float  g_kmagf[NKEYS];
__device__ __half g_scoresh[(size_t)QROWS * NKEYS];
__device__ float  g_ret[(size_t)QROWS * TWO_D];
__device__ float  g_norm[(size_t)QROWS * TWO_D];

// ---------------- helpers ----------------
__device__ __forceinline__ uint32_t smem_u32(const void* p) {
    uint32_t a;
    asm("{ .reg .u64 t; cvta.to.shared.u64 t, %1; cvt.u32.u64 %0, t; }" : "=r"(a) : "l"(p));
    return a;
}
__device__ __forceinline__ void cpasync16(uint32_t dst, const void* src) {
    asm volatile("cp.async.cg.shared.global [%0], [%1], 16;" :: "r"(dst), "l"(src) : "memory");
}
__device__ __forceinline__ void ldmx4(uint32_t* r, uint32_t a) {
    asm volatile("ldmatrix.sync.aligned.m8n8.x4.shared.b16 {%0,%1,%2,%3}, [%4];"
                 : "=r"(r[0]), "=r"(r[1]), "=r"(r[2]), "=r"(r[3]) : "r"(a));
}
__device__ __forceinline__ void ldmx2(uint32_t* r, uint32_t a) {
    asm volatile("ldmatrix.sync.aligned.m8n8.x2.shared.b16 {%0,%1}, [%2];"
                 : "=r"(r[0]), "=r"(r[1]) : "r"(a));
}
__device__ __forceinline__ void mma_bf16(float* d, const uint32_t* a, const uint32_t* b) {
    asm volatile(
        "mma.sync.aligned.m16n8k16.row.col.f32.bf16.bf16.f32 "
        "{%0,%1,%2,%3}, {%4,%5,%6,%7}, {%8,%9}, {%0,%1,%2,%3};"
        : "+f"(d[0]), "+f"(d[1]), "+f"(d[2]), "+f"(d[3])
        : "r"(a[0]), "r"(a[1]), "r"(a[2]), "r"(a[3]), "r"(b[0]), "r"(b[1]));
}

// Kahan add, rounding-mode-pinned so fast-math/contraction cannot break it
__device__ __forceinline__ void kadd(float& s, float& c, float t) {
    float y = __fsub_rn(t, c);
    float u = __fadd_rn(s, y);
    c = __fsub_rn(__fsub_rn(u, s), y);
    s = u;
}
// compensated product-accumulate: s+c+es accumulates exact sum of a*b products
__device__ __forceinline__ void cdot(float& s, float& c, float& es, float a, float b) {
    float p = __fmul_rn(a, b);
    float e = __fmaf_rn(a, b, -p);   // exact residual of the product
    kadd(s, c, p);
    es = __fadd_rn(es, e);
}

// ---------------- complex projection: Y = phase_linear(X, W, b) ----------------
template <bool PRECISE>
__global__ void __launch_bounds__(256)
cproj_kernel(const float* __restrict__ X,
             const float* __restrict__ Wr, const float* __restrict__ Wi,
             const float* __restrict__ br, const float* __restrict__ bi,
             float* __restrict__ Y)
{
    __shared__ float2 Xs[16][64];
    __shared__ float2 Ws[16][64];
    const int tid = threadIdx.x;
    const int m0 = blockIdx.y * 64;
    const int n0 = blockIdx.x * 64;
    const int kk = tid & 15;
    const int rr = tid >> 4;
    const int ty4 = (tid >> 4) * 4;
    const int tx4 = (tid & 15) * 4;

    float cr[4][4], ci[4][4], er[4][4], ei[4][4];
#pragma unroll
    for (int i = 0; i < 4; i++)
#pragma unroll
        for (int j = 0; j < 4; j++) { cr[i][j] = 0.f; ci[i][j] = 0.f; er[i][j] = 0.f; ei[i][j] = 0.f; }

    for (int k0 = 0; k0 < DIM; k0 += 16) {
#pragma unroll
        for (int r = 0; r < 4; r++) {
            int row = rr + r * 16;
            Xs[kk][row] = *(const float2*)&X[((size_t)(m0 + row) * DIM + k0 + kk) * 2];
            float wr = Wr[(size_t)(n0 + row) * DIM + k0 + kk];
            float wi = Wi[(size_t)(n0 + row) * DIM + k0 + kk];
            Ws[kk][row] = make_float2(wr, wi);
        }
        __syncthreads();
#pragma unroll
        for (int k = 0; k < 16; k++) {
            float2 a[4], w[4];
#pragma unroll
            for (int i = 0; i < 4; i++) a[i] = Xs[k][ty4 + i];
#pragma unroll
            for (int j = 0; j < 4; j++) w[j] = Ws[k][tx4 + j];
#pragma unroll
            for (int i = 0; i < 4; i++)
#pragma unroll
                for (int j = 0; j < 4; j++) {
                    if (PRECISE) {
                        kadd(cr[i][j], er[i][j],  __fmul_rn(a[i].x, w[j].x));
                        kadd(cr[i][j], er[i][j], -__fmul_rn(a[i].y, w[j].y));
                        kadd(ci[i][j], ei[i][j],  __fmul_rn(a[i].x, w[j].y));
                        kadd(ci[i][j], ei[i][j],  __fmul_rn(a[i].y, w[j].x));
                    } else {
                        cr[i][j] += a[i].x * w[j].x;
                        cr[i][j] -= a[i].y * w[j].y;
                        ci[i][j] += a[i].x * w[j].y;
                        ci[i][j] += a[i].y * w[j].x;
                    }
                }
        }
        __syncthreads();
    }
#pragma unroll
    for (int i = 0; i < 4; i++) {
        int m = m0 + ty4 + i;
#pragma unroll
        for (int j = 0; j < 4; j++) {
            int n = n0 + tx4 + j;
            float vr = PRECISE ? __fadd_rn(cr[i][j], er[i][j]) : cr[i][j];
            float vi = PRECISE ? __fadd_rn(ci[i][j], ei[i][j]) : ci[i][j];
            Y[((size_t)m * DIM + n) * 2 + 0] = vr + br[n];
            Y[((size_t)m * DIM + n) * 2 + 1] = vi + bi[n];
        }
    }
}

// ---------------- fused prep: double mag + fp32 mag + bf16 conversion ----------------
__global__ void __launch_bounds__(128)
prep_bf16_kernel(const float* __restrict__ X, __nv_bfloat16* __restrict__ Xh,
                 double* __restrict__ out_d, float* __restrict__ out_f)
{
    __shared__ double sm[128];
    const int row = blockIdx.x;
    const int tid = threadIdx.x;
    const float* p = X + (size_t)row * TWO_D;
    const int base = tid * 8;

    float4 v0 = *(const float4*)(p + base);
    float4 v1 = *(const float4*)(p + base + 4);

    double s = (double)v0.x * v0.x + (double)v0.y * v0.y
             + (double)v0.z * v0.z + (double)v0.w * v0.w
             + (double)v1.x * v1.x + (double)v1.y * v1.y
             + (double)v1.z * v1.z + (double)v1.w * v1.w;

    __nv_bfloat162 b0 = __float22bfloat162_rn(make_float2(v0.x, v0.y));
    __nv_bfloat162 b1 = __float22bfloat162_rn(make_float2(v0.z, v0.w));
    __nv_bfloat162 b2 = __float22bfloat162_rn(make_float2(v1.x, v1.y));
    __nv_bfloat162 b3 = __float22bfloat162_rn(make_float2(v1.z, v1.w));
    uint4 packed;
    packed.x = *(uint32_t*)&b0; packed.y = *(uint32_t*)&b1;
    packed.z = *(uint32_t*)&b2; packed.w = *(uint32_t*)&b3;
    *(uint4*)(Xh + (size_t)row * TWO_D + base) = packed;

    sm[tid] = s;
    __syncthreads();
    for (int o = 64; o > 0; o >>= 1) {
        if (tid < o) sm[tid] += sm[tid + o];
        __syncthreads();
    }
    if (tid == 0) {
        double m = sqrt(sm[0] + 1e-8);
        out_d[row] = m;
        out_f[row] = (float)m;
    }
}

// ---------------- bf16 mma.sync screening GEMM (half output) ----------------
__device__ __forceinline__ void gemm_load_stage(
    const char* Abase, const char* Bbase, uint32_t sb, int tid, int it, int s)
{
    const int seg = tid & 7;
    const size_t koff = (size_t)it * 128 + (size_t)seg * 16;
    const uint32_t so = sb + (uint32_t)s * STAGE_BYTES;
#pragma unroll
    for (int j = 0; j < 4; j++) {
        int row = (tid >> 3) + 32 * j;
        cpasync16(so + row * 144 + seg * 16, Abase + (size_t)row * 2048 + koff);
    }
#pragma unroll
    for (int j = 0; j < 4; j++) {
        int row = (tid >> 3) + 32 * j;
        cpasync16(so + TILE_BYTES + row * 144 + seg * 16, Bbase + (size_t)row * 2048 + koff);
    }
    asm volatile("cp.async.commit_group;" ::: "memory");
}

__global__ void __launch_bounds__(256, 2)
coh_gemm_mma(const __nv_bfloat16* __restrict__ A, const __nv_bfloat16* __restrict__ B,
             const float* __restrict__ qmag, const float* __restrict__ kmag,
             __half* __restrict__ C)
{
    extern __shared__ __align__(16) char smraw[];
    const uint32_t sb = smem_u32(smraw);
    const int tid = threadIdx.x;
    const int wid = tid >> 5, lane = tid & 31;
    const int m0 = blockIdx.x * GTM;
    const int n0 = blockIdx.y * GTN;
    const int wm0 = (wid & 1) * 64, wn0 = (wid >> 1) * 32;

    float acc[4][4][4];
#pragma unroll
    for (int a = 0; a < 4; a++)
#pragma unroll
        for (int b = 0; b < 4; b++)
#pragma unroll
            for (int c = 0; c < 4; c++) acc[a][b][c] = 0.f;

    const char* Abase = (const char*)A + (size_t)m0 * 2048;
    const char* Bbase = (const char*)B + (size_t)n0 * 2048;

    gemm_load_stage(Abase, Bbase, sb, tid, 0, 0);
    int buf = 0;
    const int arow = lane & 15, acol = (lane >> 4) * 8;
    const int brow = lane & 7,  bcol = ((lane >> 3) & 1) * 8;

    for (int it = 0; it < KCHUNKS; it++) {
        if (it < KCHUNKS - 1) {
            gemm_load_stage(Abase, Bbase, sb, tid, it + 1, buf ^ 1);
            asm volatile("cp.async.wait_group 1;" ::: "memory");
        } else {
            asm volatile("cp.async.wait_group 0;" ::: "memory");
        }
        __syncthreads();
        const uint32_t aB = sb + (uint32_t)buf * STAGE_BYTES;
        const uint32_t bB = aB + TILE_BYTES;
#pragma unroll
        for (int ks = 0; ks < 4; ks++) {
            uint32_t afr[4][4], bfr[4][2];
#pragma unroll
            for (int fm = 0; fm < 4; fm++)
                ldmx4(afr[fm], aB + (wm0 + fm * 16 + arow) * 144 + (ks * 16 + acol) * 2);
#pragma unroll
            for (int fn = 0; fn < 4; fn++)
                ldmx2(bfr[fn], bB + (wn0 + fn * 8 + brow) * 144 + (ks * 16 + bcol) * 2);
#pragma unroll
            for (int fm = 0; fm < 4; fm++)
#pragma unroll
                for (int fn = 0; fn < 4; fn++)
                    mma_bf16(acc[fm][fn], afr[fm], bfr[fn]);
        }
        __syncthreads();
        buf ^= 1;
    }

#pragma unroll
    for (int fm = 0; fm < 4; fm++) {
        int mlo = m0 + wm0 + fm * 16 + (lane >> 2);
        int mhi = mlo + 8;
        float qlo = qmag[mlo], qhi = qmag[mhi];
#pragma unroll
        for (int fn = 0; fn < 4; fn++) {
            int n = n0 + wn0 + fn * 8 + (lane & 3) * 2;
            float k0v = kmag[n], k1v = kmag[n + 1];
            __half2 hlo, hhi;
            hlo.x = __float2half_rn(acc[fm][fn][0] / (qlo * k0v + EPSF));
            hlo.y = __float2half_rn(acc[fm][fn][1] / (qlo * k1v + EPSF));
            hhi.x = __float2half_rn(acc[fm][fn][2] / (qhi * k0v + EPSF));
            hhi.y = __float2half_rn(acc[fm][fn][3] / (qhi * k1v + EPSF));
            *(__half2*)&C[(size_t)mlo * NKEYS + n] = hlo;
            *(__half2*)&C[(size_t)mhi * NKEYS + n] = hhi;
        }
    }
}

// ---------------- top-64 (screen -> float-float rescore -> select) + softmax + gather ----
__global__ void __launch_bounds__(256)
topk_kernel(const __half* __restrict__ scores,
            const float* __restrict__ qbuf,
            const float* __restrict__ keys,
            const double* __restrict__ qmagd,
            const double* __restrict__ kmagd,
            const float* __restrict__ values,
            float* __restrict__ ret)
{
    __shared__ int    hist[NBINS];
    __shared__ int    csum[256];
    __shared__ float  qs[TWO_D];
    __shared__ double cand_d[CAP];
    __shared__ int    cand_i[CAP];
    __shared__ int    s_cnt;
    __shared__ int    s_thresh;
    __shared__ double sel_d[TOPK];
    __shared__ int    sel_i[TOPK];
    __shared__ float  s_w[TOPK];
    __shared__ double redv[8];
    __shared__ int    redi[8];

    const int q = blockIdx.x;
    const int tid = threadIdx.x;
    const __half* row = scores + (size_t)q * NKEYS;

    for (int i = tid; i < NBINS; i += 256) hist[i] = 0;
    for (int i = tid; i < TWO_D; i += 256) qs[i] = qbuf[(size_t)q * TWO_D + i];
    if (tid == 0) s_cnt = 0;
    __syncthreads();

    for (int i = tid; i < NKEYS; i += 256) {
        float s = __half2float(row[i]);
        int b = (int)floorf((s + 1.0f) * 1024.0f);
        b = max(0, min(NBINS - 1, b));
        atomicAdd(&hist[b], 1);
    }
    __syncthreads();

    {
        int c = 0;
#pragma unroll
        for (int j = 0; j < 8; j++) c += hist[tid * 8 + j];
        csum[tid] = c;
    }
    __syncthreads();
    if (tid == 0) {
        int acc = 0, thr = 0;
        for (int ch = 255; ch >= 0; ch--) {
            if (acc + csum[ch] >= TOPK) {
                for (int b = ch * 8 + 7; b >= ch * 8; b--) {
                    acc += hist[b];
                    if (acc >= TOPK) { thr = b; break; }
                }
                break;
            }
            acc += csum[ch];
        }
        s_thresh = max(thr - 2, 0);   // 2-bin margin (1.95e-3) >> bf16 screen + half store error
    }
    __syncthreads();
    const int thresh = s_thresh;

    for (int i = tid; i < NKEYS; i += 256) {
        float s = __half2float(row[i]);
        int b = (int)floorf((s + 1.0f) * 1024.0f);
        b = max(0, min(NBINS - 1, b));
        if (b >= thresh) {
            int pos = atomicAdd(&s_cnt, 1);
            if (pos < CAP) cand_i[pos] = i;
        }
    }
    __syncthreads();
    const int cnt = min(s_cnt, CAP);

    // ---- float-float compensated rescore (one warp per candidate, fma pipe) ----
    {
        const int wid = tid >> 5, lane = tid & 31;
        const double qm = qmagd[q];
        for (int c = wid; c < cnt; c += 8) {
            const int ki = cand_i[c];
            const float* kr = keys + (size_t)ki * TWO_D;
            float s = 0.f, comp = 0.f, es = 0.f;
#pragma unroll
            for (int t = 0; t < 8; t++) {
                int e = t * 128 + lane * 4;
                float4 kv = *(const float4*)(kr + e);
                cdot(s, comp, es, qs[e],     kv.x);
                cdot(s, comp, es, qs[e + 1], kv.y);
                cdot(s, comp, es, qs[e + 2], kv.z);
                cdot(s, comp, es, qs[e + 3], kv.w);
            }
            double acc = (double)s + (double)comp + (double)es;
#pragma unroll
            for (int o = 16; o > 0; o >>= 1)
                acc += __shfl_down_sync(0xffffffffu, acc, o);
            if (lane == 0) cand_d[c] = acc / (qm * kmagd[ki] + (double)EPSF);
        }
    }
    __syncthreads();

    for (int t = 0; t < TOPK; t++) {
        double bv = -1e300; int bi = 0;
        for (int i = tid; i < cnt; i += 256) {
            double v = cand_d[i];
            if (v > bv) { bv = v; bi = i; }
        }
#pragma unroll
        for (int o = 16; o > 0; o >>= 1) {
            double ov = __shfl_down_sync(0xffffffffu, bv, o);
            int    oi = __shfl_down_sync(0xffffffffu, bi, o);
            if (ov > bv) { bv = ov; bi = oi; }
        }
        if ((tid & 31) == 0) { redv[tid >> 5] = bv; redi[tid >> 5] = bi; }
        __syncthreads();
        if (tid == 0) {
            double fv = redv[0]; int fi = redi[0];
#pragma unroll
            for (int w = 1; w < 8; w++)
                if (redv[w] > fv) { fv = redv[w]; fi = redi[w]; }
            sel_d[t] = fv; sel_i[t] = cand_i[fi];
            cand_d[fi] = -1e300;
        }
        __syncthreads();
    }

    if (tid == 0) {
        float m = (float)sel_d[0];
        float z = 0.f;
        for (int t = 0; t < TOPK; t++) { float w = expf((float)sel_d[t] - m); s_w[t] = w; z += w; }
        float inv = 1.0f / z;
        for (int t = 0; t < TOPK; t++) s_w[t] *= inv;
    }
    __syncthreads();

    const int col = tid * 4;
    float4 acc = make_float4(0.f, 0.f, 0.f, 0.f);
    for (int t = 0; t < TOPK; t++) {
        const float4 v = *(const float4*)&values[(size_t)sel_i[t] * TWO_D + col];
        float w = s_w[t];
        acc.x += w * v.x; acc.y += w * v.y; acc.z += w * v.z; acc.w += w * v.w;
    }
    *(float4*)&ret[(size_t)q * TWO_D + col] = acc;
}

// ---------------- phase norm: x * gamma[d] / rms(row) ----------------
__global__ void __launch_bounds__(256)
norm_kernel(const float* __restrict__ ret, const float* __restrict__ gamma,
            float* __restrict__ out)
{
    __shared__ float sm[256];
    __shared__ float s_inv;
    const int q = blockIdx.x;
    const int tid = threadIdx.x;
    const float* p = ret + (size_t)q * TWO_D;
    float s = 0.f;
    for (int i = tid; i < TWO_D; i += 256) { float v = p[i]; s += v * v; }
    sm[tid] = s;
    __syncthreads();
    for (int o = 128; o > 0; o >>= 1) {
        if (tid < o) sm[tid] += sm[tid + o];
        __syncthreads();
    }
    if (tid == 0) {
        float mean = sm[0] / (float)DIM;
        s_inv = 1.0f / sqrtf(mean + EPSF);
    }
    __syncthreads();
    const float inv = s_inv;
    for (int i = tid; i < TWO_D; i += 256) {
        int d = i >> 1;
        out[(size_t)q * TWO_D + i] = p[i] * gamma[d] * inv;
    }
}

// ---------------- launch ----------------
extern "C" void kernel_launch(void* const* d_in, const int* in_sizes, int n_in,
                              void* d_out, int out_size)
{
    const float* query = (const float*)d_in[0];
    const float* keys  = (const float*)d_in[1];
    const float* vals  = (const float*)d_in[2];
    const float* Wq_r  = (const float*)d_in[3];
    const float* Wq_i  = (const float*)d_in[4];
    const float* bq_r  = (const float*)d_in[5];
    const float* bq_i  = (const float*)d_in[6];
    const float* Wo_r  = (const float*)d_in[7];
    const float* Wo_i  = (const float*)d_in[8];
    const float* bo_r  = (const float*)d_in[9];
    const float* bo_i  = (const float*)d_in[10];
    const float* gamma = (const float*)d_in[11];
    float* out = (float*)d_out;

    void *p_q, *p_qh, *p_kh, *p_qmd, *p_qmf, *p_kmd, *p_kmf, *p_sc, *p_ret, *p_nrm;
    cudaGetSymbolAddress(&p_q,   g_q);
    cudaGetSymbolAddress(&p_qh,  g_qh);
    cudaGetSymbolAddress(&p_kh,  g_kh);
    cudaGetSymbolAddress(&p_qmd, g_qmagd);
    cudaGetSymbolAddress(&p_qmf, g_qmagf);
    cudaGetSymbolAddress(&p_kmd, g_kmagd);
    cudaGetSymbolAddress(&p_kmf, g_kmagf);
    cudaGetSymbolAddress(&p_sc,  g_scoresh);
    cudaGetSymbolAddress(&p_ret, g_ret);
    cudaGetSymbolAddress(&p_nrm, g_norm);
    float*  qbuf  = (float*)p_q;
    __nv_bfloat16* qh = (__nv_bfloat16*)p_qh;
    __nv_bfloat16* kh = (__nv_bfloat16*)p_kh;
    double* qmagd = (double*)p_qmd;
    float*  qmagf = (float*)p_qmf;
    double* kmagd = (double*)p_kmd;
    float*  kmagf = (float*)p_kmf;
    __half* sc    = (__half*)p_sc;
    float*  retb  = (float*)p_ret;
    float*  nrmb  = (float*)p_nrm;

    cudaFuncSetAttribute(coh_gemm_mma, cudaFuncAttributeMaxDynamicSharedMemorySize, GEMM_SMEM);

    dim3 gproj(DIM / 64, QROWS / 64);

    prep_bf16_kernel<<<NKEYS, 128>>>(keys, kh, kmagd, kmagf);
    cproj_kernel<true><<<gproj, 256>>>(query, Wq_r, Wq_i, bq_r, bq_i, qbuf);
    prep_bf16_kernel<<<QROWS, 128>>>(qbuf, qh, qmagd, qmagf);

    dim3 ggemm(QROWS / GTM, NKEYS / GTN);
    coh_gemm_mma<<<ggemm, 256, GEMM_SMEM>>>(qh, kh, qmagf, kmagf, sc);

    topk_kernel<<<QROWS, 256>>>(sc, qbuf, keys, qmagd, kmagd, vals, retb);
    norm_kernel<<<QROWS, 256>>>(retb, gamma, nrmb);
    cproj_kernel<false><<<gproj, 256>>>(nrmb, Wo_r, Wo_i, bo_r, bo_i, out);
}

// round 9
// speedup vs baseline: 4.1584x; 1.0476x over previous
#include <cuda_runtime.h>
#include <cuda_fp16.h>
#include <cuda_bf16.h>
#include <math.h>
#include <stdint.h>

#define QROWS 4096
#define DIM   512
#define TWO_D 1024
#define NKEYS 32768
#define TOPK  64
#define EPSF  1e-8f
#define NBINS 2048
#define CAP   1024

// ---- bf16 mma.sync GEMM config: CTA 128x256, 8 warps of 64x64 ----
#define GTM 128
#define GTN 256
#define IA_BYTES (128 * 144)            // 18432
#define IB_BYTES (256 * 144)            // 36864
#define STAGE_BYTES (IA_BYTES + IB_BYTES)
#define GEMM_SMEM (2 * STAGE_BYTES)     // 110592
#define KCHUNKS 16

// ---------------- scratch (no allocations allowed) ----------------
__device__ float  g_q[(size_t)QROWS * TWO_D];
__device__ __nv_bfloat16 g_qh[(size_t)QROWS * TWO_D];
__device__ __nv_bfloat16 g_kh[(size_t)NKEYS * TWO_D];
__device__ double g_qmagd[QROWS];
__device__ float  g_qmagf[QROWS];
__device__ double g_kmagd[NKEYS];
__device__ float  g_kmagf[NKEYS];
__device__ __half g_scoresh[(size_t)QROWS * NKEYS];
__device__ float  g_ret[(size_t)QROWS * TWO_D];
__device__ float  g_norm[(size_t)QROWS * TWO_D];

// ---------------- helpers ----------------
__device__ __forceinline__ uint32_t smem_u32(const void* p) {
    uint32_t a;
    asm("{ .reg .u64 t; cvta.to.shared.u64 t, %1; cvt.u32.u64 %0, t; }" : "=r"(a) : "l"(p));
    return a;
}
__device__ __forceinline__ void cpasync16(uint32_t dst, const void* src) {
    asm volatile("cp.async.cg.shared.global [%0], [%1], 16;" :: "r"(dst), "l"(src) : "memory");
}
__device__ __forceinline__ void ldmx4(uint32_t* r, uint32_t a) {
    asm volatile("ldmatrix.sync.aligned.m8n8.x4.shared.b16 {%0,%1,%2,%3}, [%4];"
                 : "=r"(r[0]), "=r"(r[1]), "=r"(r[2]), "=r"(r[3]) : "r"(a));
}
__device__ __forceinline__ void mma_bf16_b2(float* d, const uint32_t* a, uint32_t b0, uint32_t b1) {
    asm volatile(
        "mma.sync.aligned.m16n8k16.row.col.f32.bf16.bf16.f32 "
        "{%0,%1,%2,%3}, {%4,%5,%6,%7}, {%8,%9}, {%0,%1,%2,%3};"
        : "+f"(d[0]), "+f"(d[1]), "+f"(d[2]), "+f"(d[3])
        : "r"(a[0]), "r"(a[1]), "r"(a[2]), "r"(a[3]), "r"(b0), "r"(b1));
}

// Kahan add, rounding-mode-pinned so fast-math/contraction cannot break it
__device__ __forceinline__ void kadd(float& s, float& c, float t) {
    float y = __fsub_rn(t, c);
    float u = __fadd_rn(s, y);
    c = __fsub_rn(__fsub_rn(u, s), y);
    s = u;
}
// compensated product-accumulate: s+c+es accumulates exact sum of a*b products
__device__ __forceinline__ void cdot(float& s, float& c, float& es, float a, float b) {
    float p = __fmul_rn(a, b);
    float e = __fmaf_rn(a, b, -p);
    kadd(s, c, p);
    es = __fadd_rn(es, e);
}

// ---------------- complex projection: Y = phase_linear(X, W, b) ----------------
// PRECISE: mul+fma pair per accumulator (1 rounding/product, Kahan-compensated adds)
template <bool PRECISE>
__global__ void __launch_bounds__(256)
cproj_kernel(const float* __restrict__ X,
             const float* __restrict__ Wr, const float* __restrict__ Wi,
             const float* __restrict__ br, const float* __restrict__ bi,
             float* __restrict__ Y)
{
    __shared__ float2 Xs[16][64];
    __shared__ float2 Ws[16][64];
    const int tid = threadIdx.x;
    const int m0 = blockIdx.y * 64;
    const int n0 = blockIdx.x * 64;
    const int kk = tid & 15;
    const int rr = tid >> 4;
    const int ty4 = (tid >> 4) * 4;
    const int tx4 = (tid & 15) * 4;

    float cr[4][4], ci[4][4], er[4][4], ei[4][4];
#pragma unroll
    for (int i = 0; i < 4; i++)
#pragma unroll
        for (int j = 0; j < 4; j++) { cr[i][j] = 0.f; ci[i][j] = 0.f; er[i][j] = 0.f; ei[i][j] = 0.f; }

    for (int k0 = 0; k0 < DIM; k0 += 16) {
#pragma unroll
        for (int r = 0; r < 4; r++) {
            int row = rr + r * 16;
            Xs[kk][row] = *(const float2*)&X[((size_t)(m0 + row) * DIM + k0 + kk) * 2];
            float wr = Wr[(size_t)(n0 + row) * DIM + k0 + kk];
            float wi = Wi[(size_t)(n0 + row) * DIM + k0 + kk];
            Ws[kk][row] = make_float2(wr, wi);
        }
        __syncthreads();
#pragma unroll
        for (int k = 0; k < 16; k++) {
            float2 a[4], w[4];
#pragma unroll
            for (int i = 0; i < 4; i++) a[i] = Xs[k][ty4 + i];
#pragma unroll
            for (int j = 0; j < 4; j++) w[j] = Ws[k][tx4 + j];
#pragma unroll
            for (int i = 0; i < 4; i++)
#pragma unroll
                for (int j = 0; j < 4; j++) {
                    if (PRECISE) {
                        float tr = __fmul_rn(a[i].x, w[j].x);
                        tr = __fmaf_rn(-a[i].y, w[j].y, tr);
                        kadd(cr[i][j], er[i][j], tr);
                        float tim = __fmul_rn(a[i].x, w[j].y);
                        tim = __fmaf_rn(a[i].y, w[j].x, tim);
                        kadd(ci[i][j], ei[i][j], tim);
                    } else {
                        cr[i][j] += a[i].x * w[j].x;
                        cr[i][j] -= a[i].y * w[j].y;
                        ci[i][j] += a[i].x * w[j].y;
                        ci[i][j] += a[i].y * w[j].x;
                    }
                }
        }
        __syncthreads();
    }
#pragma unroll
    for (int i = 0; i < 4; i++) {
        int m = m0 + ty4 + i;
#pragma unroll
        for (int j = 0; j < 4; j++) {
            int n = n0 + tx4 + j;
            float vr = PRECISE ? __fadd_rn(cr[i][j], er[i][j]) : cr[i][j];
            float vi = PRECISE ? __fadd_rn(ci[i][j], ei[i][j]) : ci[i][j];
            Y[((size_t)m * DIM + n) * 2 + 0] = vr + br[n];
            Y[((size_t)m * DIM + n) * 2 + 1] = vi + bi[n];
        }
    }
}

// ---------------- fused prep: double mag + fp32 mag + bf16 conversion ----------------
__global__ void __launch_bounds__(128)
prep_bf16_kernel(const float* __restrict__ X, __nv_bfloat16* __restrict__ Xh,
                 double* __restrict__ out_d, float* __restrict__ out_f)
{
    __shared__ double sm[128];
    const int row = blockIdx.x;
    const int tid = threadIdx.x;
    const float* p = X + (size_t)row * TWO_D;
    const int base = tid * 8;

    float4 v0 = *(const float4*)(p + base);
    float4 v1 = *(const float4*)(p + base + 4);

    double s = (double)v0.x * v0.x + (double)v0.y * v0.y
             + (double)v0.z * v0.z + (double)v0.w * v0.w
             + (double)v1.x * v1.x + (double)v1.y * v1.y
             + (double)v1.z * v1.z + (double)v1.w * v1.w;

    __nv_bfloat162 b0 = __float22bfloat162_rn(make_float2(v0.x, v0.y));
    __nv_bfloat162 b1 = __float22bfloat162_rn(make_float2(v0.z, v0.w));
    __nv_bfloat162 b2 = __float22bfloat162_rn(make_float2(v1.x, v1.y));
    __nv_bfloat162 b3 = __float22bfloat162_rn(make_float2(v1.z, v1.w));
    uint4 packed;
    packed.x = *(uint32_t*)&b0; packed.y = *(uint32_t*)&b1;
    packed.z = *(uint32_t*)&b2; packed.w = *(uint32_t*)&b3;
    *(uint4*)(Xh + (size_t)row * TWO_D + base) = packed;

    sm[tid] = s;
    __syncthreads();
    for (int o = 64; o > 0; o >>= 1) {
        if (tid < o) sm[tid] += sm[tid + o];
        __syncthreads();
    }
    if (tid == 0) {
        double m = sqrt(sm[0] + 1e-8);
        out_d[row] = m;
        out_f[row] = (float)m;
    }
}

// ---------------- bf16 mma.sync screening GEMM: 128x256 CTA, 64x64 warps ----------------
__device__ __forceinline__ void gemm_load_stage(
    const char* Abase, const char* Bbase, uint32_t sb, int tid, int it, int s)
{
    const int seg = tid & 7;
    const int rowq = tid >> 3;                 // 0..31
    const size_t koff = (size_t)it * 128 + (size_t)seg * 16;
    const uint32_t so = sb + (uint32_t)s * STAGE_BYTES;
#pragma unroll
    for (int j = 0; j < 4; j++) {              // A: 128 rows
        int row = rowq + 32 * j;
        cpasync16(so + row * 144 + seg * 16, Abase + (size_t)row * 2048 + koff);
    }
#pragma unroll
    for (int j = 0; j < 8; j++) {              // B: 256 rows
        int row = rowq + 32 * j;
        cpasync16(so + IA_BYTES + row * 144 + seg * 16, Bbase + (size_t)row * 2048 + koff);
    }
    asm volatile("cp.async.commit_group;" ::: "memory");
}

__global__ void __launch_bounds__(256, 1)
coh_gemm_mma(const __nv_bfloat16* __restrict__ A, const __nv_bfloat16* __restrict__ B,
             const float* __restrict__ qmag, const float* __restrict__ kmag,
             __half* __restrict__ C)
{
    extern __shared__ __align__(16) char smraw[];
    const uint32_t sb = smem_u32(smraw);
    const int tid = threadIdx.x;
    const int wid = tid >> 5, lane = tid & 31;
    const int m0 = blockIdx.x * GTM;           // x fastest -> B tile shared in-wave
    const int n0 = blockIdx.y * GTN;
    const int wm0 = (wid & 1) * 64;
    const int wn0 = (wid >> 1) * 64;

    float acc[4][8][4];
#pragma unroll
    for (int a = 0; a < 4; a++)
#pragma unroll
        for (int b = 0; b < 8; b++)
#pragma unroll
            for (int c = 0; c < 4; c++) acc[a][b][c] = 0.f;

    const char* Abase = (const char*)A + (size_t)m0 * 2048;
    const char* Bbase = (const char*)B + (size_t)n0 * 2048;

    gemm_load_stage(Abase, Bbase, sb, tid, 0, 0);
    int buf = 0;
    const int frow = lane & 15;                // shared by A and B frag loads
    const int fcol = (lane >> 4) * 8;

    for (int it = 0; it < KCHUNKS; it++) {
        if (it < KCHUNKS - 1) {
            gemm_load_stage(Abase, Bbase, sb, tid, it + 1, buf ^ 1);
            asm volatile("cp.async.wait_group 1;" ::: "memory");
        } else {
            asm volatile("cp.async.wait_group 0;" ::: "memory");
        }
        __syncthreads();
        const uint32_t aB = sb + (uint32_t)buf * STAGE_BYTES;
        const uint32_t bB = aB + IA_BYTES;
#pragma unroll
        for (int ks = 0; ks < 4; ks++) {
            uint32_t afr[4][4], bfr[4][4];
#pragma unroll
            for (int fm = 0; fm < 4; fm++)
                ldmx4(afr[fm], aB + (wm0 + fm * 16 + frow) * 144 + (ks * 16 + fcol) * 2);
#pragma unroll
            for (int fb = 0; fb < 4; fb++)
                ldmx4(bfr[fb], bB + (wn0 + fb * 16 + frow) * 144 + (ks * 16 + fcol) * 2);
#pragma unroll
            for (int fm = 0; fm < 4; fm++)
#pragma unroll
                for (int fb = 0; fb < 4; fb++) {
                    mma_bf16_b2(acc[fm][fb * 2],     afr[fm], bfr[fb][0], bfr[fb][2]);
                    mma_bf16_b2(acc[fm][fb * 2 + 1], afr[fm], bfr[fb][1], bfr[fb][3]);
                }
        }
        __syncthreads();
        buf ^= 1;
    }

    // epilogue: normalize + half store
#pragma unroll
    for (int fm = 0; fm < 4; fm++) {
        int mlo = m0 + wm0 + fm * 16 + (lane >> 2);
        int mhi = mlo + 8;
        float qlo = qmag[mlo], qhi = qmag[mhi];
#pragma unroll
        for (int fn = 0; fn < 8; fn++) {
            int n = n0 + wn0 + (fn >> 1) * 16 + (fn & 1) * 8 + (lane & 3) * 2;
            float k0v = kmag[n], k1v = kmag[n + 1];
            __half2 hlo, hhi;
            hlo.x = __float2half_rn(acc[fm][fn][0] / (qlo * k0v + EPSF));
            hlo.y = __float2half_rn(acc[fm][fn][1] / (qlo * k1v + EPSF));
            hhi.x = __float2half_rn(acc[fm][fn][2] / (qhi * k0v + EPSF));
            hhi.y = __float2half_rn(acc[fm][fn][3] / (qhi * k1v + EPSF));
            *(__half2*)&C[(size_t)mlo * NKEYS + n] = hlo;
            *(__half2*)&C[(size_t)mhi * NKEYS + n] = hhi;
        }
    }
}

// ---------------- top-64 (screen -> float-float rescore -> select) + softmax + gather ----
__global__ void __launch_bounds__(256)
topk_kernel(const __half* __restrict__ scores,
            const float* __restrict__ qbuf,
            const float* __restrict__ keys,
            const double* __restrict__ qmagd,
            const double* __restrict__ kmagd,
            const float* __restrict__ values,
            float* __restrict__ ret)
{
    __shared__ int    hist[NBINS];
    __shared__ int    csum[256];
    __shared__ float  qs[TWO_D];
    __shared__ double cand_d[CAP];
    __shared__ int    cand_i[CAP];
    __shared__ int    s_cnt;
    __shared__ int    s_thresh;
    __shared__ double sel_d[TOPK];
    __shared__ int    sel_i[TOPK];
    __shared__ float  s_w[TOPK];
    __shared__ double redv[8];
    __shared__ int    redi[8];

    const int q = blockIdx.x;
    const int tid = threadIdx.x;
    const __half* row = scores + (size_t)q * NKEYS;

    for (int i = tid; i < NBINS; i += 256) hist[i] = 0;
    for (int i = tid; i < TWO_D; i += 256) qs[i] = qbuf[(size_t)q * TWO_D + i];
    if (tid == 0) s_cnt = 0;
    __syncthreads();

    for (int i = tid; i < NKEYS; i += 256) {
        float s = __half2float(row[i]);
        int b = (int)floorf((s + 1.0f) * 1024.0f);
        b = max(0, min(NBINS - 1, b));
        atomicAdd(&hist[b], 1);
    }
    __syncthreads();

    {
        int c = 0;
#pragma unroll
        for (int j = 0; j < 8; j++) c += hist[tid * 8 + j];
        csum[tid] = c;
    }
    __syncthreads();
    if (tid == 0) {
        int acc = 0, thr = 0;
        for (int ch = 255; ch >= 0; ch--) {
            if (acc + csum[ch] >= TOPK) {
                for (int b = ch * 8 + 7; b >= ch * 8; b--) {
                    acc += hist[b];
                    if (acc >= TOPK) { thr = b; break; }
                }
                break;
            }
            acc += csum[ch];
        }
        s_thresh = max(thr - 2, 0);   // 2-bin margin (1.95e-3) >> bf16 screen + half store error
    }
    __syncthreads();
    const int thresh = s_thresh;

    for (int i = tid; i < NKEYS; i += 256) {
        float s = __half2float(row[i]);
        int b = (int)floorf((s + 1.0f) * 1024.0f);
        b = max(0, min(NBINS - 1, b));
        if (b >= thresh) {
            int pos = atomicAdd(&s_cnt, 1);
            if (pos < CAP) cand_i[pos] = i;
        }
    }
    __syncthreads();
    const int cnt = min(s_cnt, CAP);

    // ---- float-float compensated rescore (one warp per candidate, fma pipe) ----
    {
        const int wid = tid >> 5, lane = tid & 31;
        const double qm = qmagd[q];
        for (int c = wid; c < cnt; c += 8) {
            const int ki = cand_i[c];
            const float* kr = keys + (size_t)ki * TWO_D;
            float s = 0.f, comp = 0.f, es = 0.f;
#pragma unroll
            for (int t = 0; t < 8; t++) {
                int e = t * 128 + lane * 4;
                float4 kv = *(const float4*)(kr + e);
                cdot(s, comp, es, qs[e],     kv.x);
                cdot(s, comp, es, qs[e + 1], kv.y);
                cdot(s, comp, es, qs[e + 2], kv.z);
                cdot(s, comp, es, qs[e + 3], kv.w);
            }
            double acc = (double)s + (double)comp + (double)es;
#pragma unroll
            for (int o = 16; o > 0; o >>= 1)
                acc += __shfl_down_sync(0xffffffffu, acc, o);
            if (lane == 0) cand_d[c] = acc / (qm * kmagd[ki] + (double)EPSF);
        }
    }
    __syncthreads();

    for (int t = 0; t < TOPK; t++) {
        double bv = -1e300; int bi = 0;
        for (int i = tid; i < cnt; i += 256) {
            double v = cand_d[i];
            if (v > bv) { bv = v; bi = i; }
        }
#pragma unroll
        for (int o = 16; o > 0; o >>= 1) {
            double ov = __shfl_down_sync(0xffffffffu, bv, o);
            int    oi = __shfl_down_sync(0xffffffffu, bi, o);
            if (ov > bv) { bv = ov; bi = oi; }
        }
        if ((tid & 31) == 0) { redv[tid >> 5] = bv; redi[tid >> 5] = bi; }
        __syncthreads();
        if (tid == 0) {
            double fv = redv[0]; int fi = redi[0];
#pragma unroll
            for (int w = 1; w < 8; w++)
                if (redv[w] > fv) { fv = redv[w]; fi = redi[w]; }
            sel_d[t] = fv; sel_i[t] = cand_i[fi];
            cand_d[fi] = -1e300;
        }
        __syncthreads();
    }

    if (tid == 0) {
        float m = (float)sel_d[0];
        float z = 0.f;
        for (int t = 0; t < TOPK; t++) { float w = expf((float)sel_d[t] - m); s_w[t] = w; z += w; }
        float inv = 1.0f / z;
        for (int t = 0; t < TOPK; t++) s_w[t] *= inv;
    }
    __syncthreads();

    const int col = tid * 4;
    float4 acc = make_float4(0.f, 0.f, 0.f, 0.f);
    for (int t = 0; t < TOPK; t++) {
        const float4 v = *(const float4*)&values[(size_t)sel_i[t] * TWO_D + col];
        float w = s_w[t];
        acc.x += w * v.x; acc.y += w * v.y; acc.z += w * v.z; acc.w += w * v.w;
    }
    *(float4*)&ret[(size_t)q * TWO_D + col] = acc;
}

// ---------------- phase norm: x * gamma[d] / rms(row) ----------------
__global__ void __launch_bounds__(256)
norm_kernel(const float* __restrict__ ret, const float* __restrict__ gamma,
            float* __restrict__ out)
{
    __shared__ float sm[256];
    __shared__ float s_inv;
    const int q = blockIdx.x;
    const int tid = threadIdx.x;
    const float* p = ret + (size_t)q * TWO_D;
    float s = 0.f;
    for (int i = tid; i < TWO_D; i += 256) { float v = p[i]; s += v * v; }
    sm[tid] = s;
    __syncthreads();
    for (int o = 128; o > 0; o >>= 1) {
        if (tid < o) sm[tid] += sm[tid + o];
        __syncthreads();
    }
    if (tid == 0) {
        float mean = sm[0] / (float)DIM;
        s_inv = 1.0f / sqrtf(mean + EPSF);
    }
    __syncthreads();
    const float inv = s_inv;
    for (int i = tid; i < TWO_D; i += 256) {
        int d = i >> 1;
        out[(size_t)q * TWO_D + i] = p[i] * gamma[d] * inv;
    }
}

// ---------------- launch ----------------
extern "C" void kernel_launch(void* const* d_in, const int* in_sizes, int n_in,
                              void* d_out, int out_size)
{
    const float* query = (const float*)d_in[0];
    const float* keys  = (const float*)d_in[1];
    const float* vals  = (const float*)d_in[2];
    const float* Wq_r  = (const float*)d_in[3];
    const float* Wq_i  = (const float*)d_in[4];
    const float* bq_r  = (const float*)d_in[5];
    const float* bq_i  = (const float*)d_in[6];
    const float* Wo_r  = (const float*)d_in[7];
    const float* Wo_i  = (const float*)d_in[8];
    const float* bo_r  = (const float*)d_in[9];
    const float* bo_i  = (const float*)d_in[10];
    const float* gamma = (const float*)d_in[11];
    float* out = (float*)d_out;

    void *p_q, *p_qh, *p_kh, *p_qmd, *p_qmf, *p_kmd, *p_kmf, *p_sc, *p_ret, *p_nrm;
    cudaGetSymbolAddress(&p_q,   g_q);
    cudaGetSymbolAddress(&p_qh,  g_qh);
    cudaGetSymbolAddress(&p_kh,  g_kh);
    cudaGetSymbolAddress(&p_qmd, g_qmagd);
    cudaGetSymbolAddress(&p_qmf, g_qmagf);
    cudaGetSymbolAddress(&p_kmd, g_kmagd);
    cudaGetSymbolAddress(&p_kmf, g_kmagf);
    cudaGetSymbolAddress(&p_sc,  g_scoresh);
    cudaGetSymbolAddress(&p_ret, g_ret);
    cudaGetSymbolAddress(&p_nrm, g_norm);
    float*  qbuf  = (float*)p_q;
    __nv_bfloat16* qh = (__nv_bfloat16*)p_qh;
    __nv_bfloat16* kh = (__nv_bfloat16*)p_kh;
    double* qmagd = (double*)p_qmd;
    float*  qmagf = (float*)p_qmf;
    double* kmagd = (double*)p_kmd;
    float*  kmagf = (float*)p_kmf;
    __half* sc    = (__half*)p_sc;
    float*  retb  = (float*)p_ret;
    float*  nrmb  = (float*)p_nrm;

    cudaFuncSetAttribute(coh_gemm_mma, cudaFuncAttributeMaxDynamicSharedMemorySize, GEMM_SMEM);

    dim3 gproj(DIM / 64, QROWS / 64);

    prep_bf16_kernel<<<NKEYS, 128>>>(keys, kh, kmagd, kmagf);
    cproj_kernel<true><<<gproj, 256>>>(query, Wq_r, Wq_i, bq_r, bq_i, qbuf);
    prep_bf16_kernel<<<QROWS, 128>>>(qbuf, qh, qmagd, qmagf);

    dim3 ggemm(QROWS / GTM, NKEYS / GTN);
    coh_gemm_mma<<<ggemm, 256, GEMM_SMEM>>>(qh, kh, qmagf, kmagf, sc);

    topk_kernel<<<QROWS, 256>>>(sc, qbuf, keys, qmagd, kmagd, vals, retb);
    norm_kernel<<<QROWS, 256>>>(retb, gamma, nrmb);
    cproj_kernel<false><<<gproj, 256>>>(nrmb, Wo_r, Wo_i, bo_r, bo_i, out);
}

// round 10
// speedup vs baseline: 4.1587x; 1.0001x over previous
#include <cuda_runtime.h>
#include <cuda_fp16.h>
#include <cuda_bf16.h>
#include <math.h>
#include <stdint.h>

#define QROWS 4096
#define DIM   512
#define TWO_D 1024
#define NKEYS 32768
#define TOPK  64
#define EPSF  1e-8f
#define NBINS 2048
#define CAP   1024

// ---- bf16 mma.sync GEMM config: CTA 128x256, 8 warps of 64x64 ----
#define GTM 128
#define GTN 256
#define IA_BYTES (128 * 144)            // 18432
#define IB_BYTES (256 * 144)            // 36864
#define STAGE_BYTES (IA_BYTES + IB_BYTES)
#define GEMM_SMEM (2 * STAGE_BYTES)     // 110592
#define KCHUNKS 16

// ---------------- scratch (no allocations allowed) ----------------
__device__ float  g_q[(size_t)QROWS * TWO_D];
__device__ __nv_bfloat16 g_qh[(size_t)QROWS * TWO_D];
__device__ __nv_bfloat16 g_kh[(size_t)NKEYS * TWO_D];
__device__ double g_qmagd[QROWS];
__device__ float  g_qmagf[QROWS];
__device__ double g_kmagd[NKEYS];
__device__ float  g_kmagf[NKEYS];
__device__ __half g_scoresh[(size_t)QROWS * NKEYS];
__device__ float  g_ret[(size_t)QROWS * TWO_D];
__device__ float  g_norm[(size_t)QROWS * TWO_D];

// ---------------- helpers ----------------
__device__ __forceinline__ uint32_t smem_u32(const void* p) {
    uint32_t a;
    asm("{ .reg .u64 t; cvta.to.shared.u64 t, %1; cvt.u32.u64 %0, t; }" : "=r"(a) : "l"(p));
    return a;
}
__device__ __forceinline__ void cpasync16(uint32_t dst, const void* src) {
    asm volatile("cp.async.cg.shared.global [%0], [%1], 16;" :: "r"(dst), "l"(src) : "memory");
}
__device__ __forceinline__ void ldmx4(uint32_t* r, uint32_t a) {
    asm volatile("ldmatrix.sync.aligned.m8n8.x4.shared.b16 {%0,%1,%2,%3}, [%4];"
                 : "=r"(r[0]), "=r"(r[1]), "=r"(r[2]), "=r"(r[3]) : "r"(a));
}
__device__ __forceinline__ void mma_bf16_b2(float* d, const uint32_t* a, uint32_t b0, uint32_t b1) {
    asm volatile(
        "mma.sync.aligned.m16n8k16.row.col.f32.bf16.bf16.f32 "
        "{%0,%1,%2,%3}, {%4,%5,%6,%7}, {%8,%9}, {%0,%1,%2,%3};"
        : "+f"(d[0]), "+f"(d[1]), "+f"(d[2]), "+f"(d[3])
        : "r"(a[0]), "r"(a[1]), "r"(a[2]), "r"(a[3]), "r"(b0), "r"(b1));
}

// Kahan add, rounding-mode-pinned so fast-math/contraction cannot break it
__device__ __forceinline__ void kadd(float& s, float& c, float t) {
    float y = __fsub_rn(t, c);
    float u = __fadd_rn(s, y);
    c = __fsub_rn(__fsub_rn(u, s), y);
    s = u;
}
// compensated product-accumulate: s+c+es accumulates exact sum of a*b products
__device__ __forceinline__ void cdot(float& s, float& c, float& es, float a, float b) {
    float p = __fmul_rn(a, b);
    float e = __fmaf_rn(a, b, -p);
    kadd(s, c, p);
    es = __fadd_rn(es, e);
}

// ---------------- complex projection: Y = phase_linear(X, W, b) ----------------
// PRECISE: mul+fma pair per accumulator (1 rounding/product, Kahan-compensated adds)
template <bool PRECISE>
__global__ void __launch_bounds__(256)
cproj_kernel(const float* __restrict__ X,
             const float* __restrict__ Wr, const float* __restrict__ Wi,
             const float* __restrict__ br, const float* __restrict__ bi,
             float* __restrict__ Y)
{
    __shared__ float2 Xs[16][64];
    __shared__ float2 Ws[16][64];
    const int tid = threadIdx.x;
    const int m0 = blockIdx.y * 64;
    const int n0 = blockIdx.x * 64;
    const int kk = tid & 15;
    const int rr = tid >> 4;
    const int ty4 = (tid >> 4) * 4;
    const int tx4 = (tid & 15) * 4;

    float cr[4][4], ci[4][4], er[4][4], ei[4][4];
#pragma unroll
    for (int i = 0; i < 4; i++)
#pragma unroll
        for (int j = 0; j < 4; j++) { cr[i][j] = 0.f; ci[i][j] = 0.f; er[i][j] = 0.f; ei[i][j] = 0.f; }

    for (int k0 = 0; k0 < DIM; k0 += 16) {
#pragma unroll
        for (int r = 0; r < 4; r++) {
            int row = rr + r * 16;
            Xs[kk][row] = *(const float2*)&X[((size_t)(m0 + row) * DIM + k0 + kk) * 2];
            float wr = Wr[(size_t)(n0 + row) * DIM + k0 + kk];
            float wi = Wi[(size_t)(n0 + row) * DIM + k0 + kk];
            Ws[kk][row] = make_float2(wr, wi);
        }
        __syncthreads();
#pragma unroll
        for (int k = 0; k < 16; k++) {
            float2 a[4], w[4];
#pragma unroll
            for (int i = 0; i < 4; i++) a[i] = Xs[k][ty4 + i];
#pragma unroll
            for (int j = 0; j < 4; j++) w[j] = Ws[k][tx4 + j];
#pragma unroll
            for (int i = 0; i < 4; i++)
#pragma unroll
                for (int j = 0; j < 4; j++) {
                    if (PRECISE) {
                        float tr = __fmul_rn(a[i].x, w[j].x);
                        tr = __fmaf_rn(-a[i].y, w[j].y, tr);
                        kadd(cr[i][j], er[i][j], tr);
                        float tim = __fmul_rn(a[i].x, w[j].y);
                        tim = __fmaf_rn(a[i].y, w[j].x, tim);
                        kadd(ci[i][j], ei[i][j], tim);
                    } else {
                        cr[i][j] += a[i].x * w[j].x;
                        cr[i][j] -= a[i].y * w[j].y;
                        ci[i][j] += a[i].x * w[j].y;
                        ci[i][j] += a[i].y * w[j].x;
                    }
                }
        }
        __syncthreads();
    }
#pragma unroll
    for (int i = 0; i < 4; i++) {
        int m = m0 + ty4 + i;
#pragma unroll
        for (int j = 0; j < 4; j++) {
            int n = n0 + tx4 + j;
            float vr = PRECISE ? __fadd_rn(cr[i][j], er[i][j]) : cr[i][j];
            float vi = PRECISE ? __fadd_rn(ci[i][j], ei[i][j]) : ci[i][j];
            Y[((size_t)m * DIM + n) * 2 + 0] = vr + br[n];
            Y[((size_t)m * DIM + n) * 2 + 1] = vi + bi[n];
        }
    }
}

// ---------------- fused prep: double mag + fp32 mag + bf16 conversion ----------------
__global__ void __launch_bounds__(128)
prep_bf16_kernel(const float* __restrict__ X, __nv_bfloat16* __restrict__ Xh,
                 double* __restrict__ out_d, float* __restrict__ out_f)
{
    __shared__ double sm[128];
    const int row = blockIdx.x;
    const int tid = threadIdx.x;
    const float* p = X + (size_t)row * TWO_D;
    const int base = tid * 8;

    float4 v0 = *(const float4*)(p + base);
    float4 v1 = *(const float4*)(p + base + 4);

    double s = (double)v0.x * v0.x + (double)v0.y * v0.y
             + (double)v0.z * v0.z + (double)v0.w * v0.w
             + (double)v1.x * v1.x + (double)v1.y * v1.y
             + (double)v1.z * v1.z + (double)v1.w * v1.w;

    __nv_bfloat162 b0 = __float22bfloat162_rn(make_float2(v0.x, v0.y));
    __nv_bfloat162 b1 = __float22bfloat162_rn(make_float2(v0.z, v0.w));
    __nv_bfloat162 b2 = __float22bfloat162_rn(make_float2(v1.x, v1.y));
    __nv_bfloat162 b3 = __float22bfloat162_rn(make_float2(v1.z, v1.w));
    uint4 packed;
    packed.x = *(uint32_t*)&b0; packed.y = *(uint32_t*)&b1;
    packed.z = *(uint32_t*)&b2; packed.w = *(uint32_t*)&b3;
    *(uint4*)(Xh + (size_t)row * TWO_D + base) = packed;

    sm[tid] = s;
    __syncthreads();
    for (int o = 64; o > 0; o >>= 1) {
        if (tid < o) sm[tid] += sm[tid + o];
        __syncthreads();
    }
    if (tid == 0) {
        double m = sqrt(sm[0] + 1e-8);
        out_d[row] = m;
        out_f[row] = (float)m;
    }
}

// ---------------- bf16 mma.sync screening GEMM: 128x256 CTA, 64x64 warps ----------------
__device__ __forceinline__ void gemm_load_stage(
    const char* Abase, const char* Bbase, uint32_t sb, int tid, int it, int s)
{
    const int seg = tid & 7;
    const int rowq = tid >> 3;                 // 0..31
    const size_t koff = (size_t)it * 128 + (size_t)seg * 16;
    const uint32_t so = sb + (uint32_t)s * STAGE_BYTES;
#pragma unroll
    for (int j = 0; j < 4; j++) {              // A: 128 rows
        int row = rowq + 32 * j;
        cpasync16(so + row * 144 + seg * 16, Abase + (size_t)row * 2048 + koff);
    }
#pragma unroll
    for (int j = 0; j < 8; j++) {              // B: 256 rows
        int row = rowq + 32 * j;
        cpasync16(so + IA_BYTES + row * 144 + seg * 16, Bbase + (size_t)row * 2048 + koff);
    }
    asm volatile("cp.async.commit_group;" ::: "memory");
}

__global__ void __launch_bounds__(256, 1)
coh_gemm_mma(const __nv_bfloat16* __restrict__ A, const __nv_bfloat16* __restrict__ B,
             const float* __restrict__ qmag, const float* __restrict__ kmag,
             __half* __restrict__ C)
{
    extern __shared__ __align__(16) char smraw[];
    const uint32_t sb = smem_u32(smraw);
    const int tid = threadIdx.x;
    const int wid = tid >> 5, lane = tid & 31;
    const int m0 = blockIdx.x * GTM;           // x fastest -> B tile shared in-wave
    const int n0 = blockIdx.y * GTN;
    const int wm0 = (wid & 1) * 64;
    const int wn0 = (wid >> 1) * 64;

    float acc[4][8][4];
#pragma unroll
    for (int a = 0; a < 4; a++)
#pragma unroll
        for (int b = 0; b < 8; b++)
#pragma unroll
            for (int c = 0; c < 4; c++) acc[a][b][c] = 0.f;

    const char* Abase = (const char*)A + (size_t)m0 * 2048;
    const char* Bbase = (const char*)B + (size_t)n0 * 2048;

    gemm_load_stage(Abase, Bbase, sb, tid, 0, 0);
    int buf = 0;
    const int frow = lane & 15;                // shared by A and B frag loads
    const int fcol = (lane >> 4) * 8;

    for (int it = 0; it < KCHUNKS; it++) {
        if (it < KCHUNKS - 1) {
            gemm_load_stage(Abase, Bbase, sb, tid, it + 1, buf ^ 1);
            asm volatile("cp.async.wait_group 1;" ::: "memory");
        } else {
            asm volatile("cp.async.wait_group 0;" ::: "memory");
        }
        __syncthreads();
        const uint32_t aB = sb + (uint32_t)buf * STAGE_BYTES;
        const uint32_t bB = aB + IA_BYTES;
#pragma unroll
        for (int ks = 0; ks < 4; ks++) {
            uint32_t afr[4][4], bfr[4][4];
#pragma unroll
            for (int fm = 0; fm < 4; fm++)
                ldmx4(afr[fm], aB + (wm0 + fm * 16 + frow) * 144 + (ks * 16 + fcol) * 2);
#pragma unroll
            for (int fb = 0; fb < 4; fb++)
                ldmx4(bfr[fb], bB + (wn0 + fb * 16 + frow) * 144 + (ks * 16 + fcol) * 2);
#pragma unroll
            for (int fm = 0; fm < 4; fm++)
#pragma unroll
                for (int fb = 0; fb < 4; fb++) {
                    mma_bf16_b2(acc[fm][fb * 2],     afr[fm], bfr[fb][0], bfr[fb][2]);
                    mma_bf16_b2(acc[fm][fb * 2 + 1], afr[fm], bfr[fb][1], bfr[fb][3]);
                }
        }
        __syncthreads();
        buf ^= 1;
    }

    // epilogue: normalize + half store
#pragma unroll
    for (int fm = 0; fm < 4; fm++) {
        int mlo = m0 + wm0 + fm * 16 + (lane >> 2);
        int mhi = mlo + 8;
        float qlo = qmag[mlo], qhi = qmag[mhi];
#pragma unroll
        for (int fn = 0; fn < 8; fn++) {
            int n = n0 + wn0 + (fn >> 1) * 16 + (fn & 1) * 8 + (lane & 3) * 2;
            float k0v = kmag[n], k1v = kmag[n + 1];
            __half2 hlo, hhi;
            hlo.x = __float2half_rn(acc[fm][fn][0] / (qlo * k0v + EPSF));
            hlo.y = __float2half_rn(acc[fm][fn][1] / (qlo * k1v + EPSF));
            hhi.x = __float2half_rn(acc[fm][fn][2] / (qhi * k0v + EPSF));
            hhi.y = __float2half_rn(acc[fm][fn][3] / (qhi * k1v + EPSF));
            *(__half2*)&C[(size_t)mlo * NKEYS + n] = hlo;
            *(__half2*)&C[(size_t)mhi * NKEYS + n] = hhi;
        }
    }
}

// ---------------- top-64 (screen -> float-float rescore -> select) + softmax + gather ----
__global__ void __launch_bounds__(256)
topk_kernel(const __half* __restrict__ scores,
            const float* __restrict__ qbuf,
            const float* __restrict__ keys,
            const double* __restrict__ qmagd,
            const double* __restrict__ kmagd,
            const float* __restrict__ values,
            float* __restrict__ ret)
{
    __shared__ int    hist[NBINS];
    __shared__ int    csum[256];
    __shared__ float  qs[TWO_D];
    __shared__ double cand_d[CAP];
    __shared__ int    cand_i[CAP];
    __shared__ int    s_cnt;
    __shared__ int    s_thresh;
    __shared__ double sel_d[TOPK];
    __shared__ int    sel_i[TOPK];
    __shared__ float  s_w[TOPK];
    __shared__ double redv[8];
    __shared__ int    redi[8];

    const int q = blockIdx.x;
    const int tid = threadIdx.x;
    const __half* row = scores + (size_t)q * NKEYS;

    for (int i = tid; i < NBINS; i += 256) hist[i] = 0;
    for (int i = tid; i < TWO_D; i += 256) qs[i] = qbuf[(size_t)q * TWO_D + i];
    if (tid == 0) s_cnt = 0;
    __syncthreads();

    for (int i = tid; i < NKEYS; i += 256) {
        float s = __half2float(row[i]);
        int b = (int)floorf((s + 1.0f) * 1024.0f);
        b = max(0, min(NBINS - 1, b));
        atomicAdd(&hist[b], 1);
    }
    __syncthreads();

    {
        int c = 0;
#pragma unroll
        for (int j = 0; j < 8; j++) c += hist[tid * 8 + j];
        csum[tid] = c;
    }
    __syncthreads();
    if (tid == 0) {
        int acc = 0, thr = 0;
        for (int ch = 255; ch >= 0; ch--) {
            if (acc + csum[ch] >= TOPK) {
                for (int b = ch * 8 + 7; b >= ch * 8; b--) {
                    acc += hist[b];
                    if (acc >= TOPK) { thr = b; break; }
                }
                break;
            }
            acc += csum[ch];
        }
        s_thresh = max(thr - 2, 0);   // 2-bin margin (1.95e-3) >> bf16 screen + half store error
    }
    __syncthreads();
    const int thresh = s_thresh;

    for (int i = tid; i < NKEYS; i += 256) {
        float s = __half2float(row[i]);
        int b = (int)floorf((s + 1.0f) * 1024.0f);
        b = max(0, min(NBINS - 1, b));
        if (b >= thresh) {
            int pos = atomicAdd(&s_cnt, 1);
            if (pos < CAP) cand_i[pos] = i;
        }
    }
    __syncthreads();
    const int cnt = min(s_cnt, CAP);

    // ---- float-float compensated rescore (one warp per candidate, fma pipe) ----
    {
        const int wid = tid >> 5, lane = tid & 31;
        const double qm = qmagd[q];
        for (int c = wid; c < cnt; c += 8) {
            const int ki = cand_i[c];
            const float* kr = keys + (size_t)ki * TWO_D;
            float s = 0.f, comp = 0.f, es = 0.f;
#pragma unroll
            for (int t = 0; t < 8; t++) {
                int e = t * 128 + lane * 4;
                float4 kv = *(const float4*)(kr + e);
                cdot(s, comp, es, qs[e],     kv.x);
                cdot(s, comp, es, qs[e + 1], kv.y);
                cdot(s, comp, es, qs[e + 2], kv.z);
                cdot(s, comp, es, qs[e + 3], kv.w);
            }
            double acc = (double)s + (double)comp + (double)es;
#pragma unroll
            for (int o = 16; o > 0; o >>= 1)
                acc += __shfl_down_sync(0xffffffffu, acc, o);
            if (lane == 0) cand_d[c] = acc / (qm * kmagd[ki] + (double)EPSF);
        }
    }
    __syncthreads();

    for (int t = 0; t < TOPK; t++) {
        double bv = -1e300; int bi = 0;
        for (int i = tid; i < cnt; i += 256) {
            double v = cand_d[i];
            if (v > bv) { bv = v; bi = i; }
        }
#pragma unroll
        for (int o = 16; o > 0; o >>= 1) {
            double ov = __shfl_down_sync(0xffffffffu, bv, o);
            int    oi = __shfl_down_sync(0xffffffffu, bi, o);
            if (ov > bv) { bv = ov; bi = oi; }
        }
        if ((tid & 31) == 0) { redv[tid >> 5] = bv; redi[tid >> 5] = bi; }
        __syncthreads();
        if (tid == 0) {
            double fv = redv[0]; int fi = redi[0];
#pragma unroll
            for (int w = 1; w < 8; w++)
                if (redv[w] > fv) { fv = redv[w]; fi = redi[w]; }
            sel_d[t] = fv; sel_i[t] = cand_i[fi];
            cand_d[fi] = -1e300;
        }
        __syncthreads();
    }

    if (tid == 0) {
        float m = (float)sel_d[0];
        float z = 0.f;
        for (int t = 0; t < TOPK; t++) { float w = expf((float)sel_d[t] - m); s_w[t] = w; z += w; }
        float inv = 1.0f / z;
        for (int t = 0; t < TOPK; t++) s_w[t] *= inv;
    }
    __syncthreads();

    const int col = tid * 4;
    float4 acc = make_float4(0.f, 0.f, 0.f, 0.f);
    for (int t = 0; t < TOPK; t++) {
        const float4 v = *(const float4*)&values[(size_t)sel_i[t] * TWO_D + col];
        float w = s_w[t];
        acc.x += w * v.x; acc.y += w * v.y; acc.z += w * v.z; acc.w += w * v.w;
    }
    *(float4*)&ret[(size_t)q * TWO_D + col] = acc;
}

// ---------------- phase norm: x * gamma[d] / rms(row) ----------------
__global__ void __launch_bounds__(256)
norm_kernel(const float* __restrict__ ret, const float* __restrict__ gamma,
            float* __restrict__ out)
{
    __shared__ float sm[256];
    __shared__ float s_inv;
    const int q = blockIdx.x;
    const int tid = threadIdx.x;
    const float* p = ret + (size_t)q * TWO_D;
    float s = 0.f;
    for (int i = tid; i < TWO_D; i += 256) { float v = p[i]; s += v * v; }
    sm[tid] = s;
    __syncthreads();
    for (int o = 128; o > 0; o >>= 1) {
        if (tid < o) sm[tid] += sm[tid + o];
        __syncthreads();
    }
    if (tid == 0) {
        float mean = sm[0] / (float)DIM;
        s_inv = 1.0f / sqrtf(mean + EPSF);
    }
    __syncthreads();
    const float inv = s_inv;
    for (int i = tid; i < TWO_D; i += 256) {
        int d = i >> 1;
        out[(size_t)q * TWO_D + i] = p[i] * gamma[d] * inv;
    }
}

// ---------------- launch ----------------
extern "C" void kernel_launch(void* const* d_in, const int* in_sizes, int n_in,
                              void* d_out, int out_size)
{
    const float* query = (const float*)d_in[0];
    const float* keys  = (const float*)d_in[1];
    const float* vals  = (const float*)d_in[2];
    const float* Wq_r  = (const float*)d_in[3];
    const float* Wq_i  = (const float*)d_in[4];
    const float* bq_r  = (const float*)d_in[5];
    const float* bq_i  = (const float*)d_in[6];
    const float* Wo_r  = (const float*)d_in[7];
    const float* Wo_i  = (const float*)d_in[8];
    const float* bo_r  = (const float*)d_in[9];
    const float* bo_i  = (const float*)d_in[10];
    const float* gamma = (const float*)d_in[11];
    float* out = (float*)d_out;

    void *p_q, *p_qh, *p_kh, *p_qmd, *p_qmf, *p_kmd, *p_kmf, *p_sc, *p_ret, *p_nrm;
    cudaGetSymbolAddress(&p_q,   g_q);
    cudaGetSymbolAddress(&p_qh,  g_qh);
    cudaGetSymbolAddress(&p_kh,  g_kh);
    cudaGetSymbolAddress(&p_qmd, g_qmagd);
    cudaGetSymbolAddress(&p_qmf, g_qmagf);
    cudaGetSymbolAddress(&p_kmd, g_kmagd);
    cudaGetSymbolAddress(&p_kmf, g_kmagf);
    cudaGetSymbolAddress(&p_sc,  g_scoresh);
    cudaGetSymbolAddress(&p_ret, g_ret);
    cudaGetSymbolAddress(&p_nrm, g_norm);
    float*  qbuf  = (float*)p_q;
    __nv_bfloat16* qh = (__nv_bfloat16*)p_qh;
    __nv_bfloat16* kh = (__nv_bfloat16*)p_kh;
    double* qmagd = (double*)p_qmd;
    float*  qmagf = (float*)p_qmf;
    double* kmagd = (double*)p_kmd;
    float*  kmagf = (float*)p_kmf;
    __half* sc    = (__half*)p_sc;
    float*  retb  = (float*)p_ret;
    float*  nrmb  = (float*)p_nrm;

    cudaFuncSetAttribute(coh_gemm_mma, cudaFuncAttributeMaxDynamicSharedMemorySize, GEMM_SMEM);

    dim3 gproj(DIM / 64, QROWS / 64);

    prep_bf16_kernel<<<NKEYS, 128>>>(keys, kh, kmagd, kmagf);
    cproj_kernel<true><<<gproj, 256>>>(query, Wq_r, Wq_i, bq_r, bq_i, qbuf);
    prep_bf16_kernel<<<QROWS, 128>>>(qbuf, qh, qmagd, qmagf);

    dim3 ggemm(QROWS / GTM, NKEYS / GTN);
    coh_gemm_mma<<<ggemm, 256, GEMM_SMEM>>>(qh, kh, qmagf, kmagf, sc);

    topk_kernel<<<QROWS, 256>>>(sc, qbuf, keys, qmagd, kmagd, vals, retb);
    norm_kernel<<<QROWS, 256>>>(retb, gamma, nrmb);
    cproj_kernel<false><<<gproj, 256>>>(nrmb, Wo_r, Wo_i, bo_r, bo_i, out);
}

// round 11
// speedup vs baseline: 4.3426x; 1.0442x over previous
#include <cuda_runtime.h>
#include <cuda_fp16.h>
#include <cuda_bf16.h>
#include <math.h>
#include <stdint.h>

#define QROWS 4096
#define DIM   512
#define TWO_D 1024
#define NKEYS 32768
#define TOPK  64
#define EPSF  1e-8f
#define NBINS 2048
#define CAP   1024

// ---- bf16 mma.sync GEMM config (round-8 proven: 128x128, 2 CTA/SM) ----
#define GTM 128
#define GTN 128
#define TILE_BYTES (128 * 144)
#define STAGE_BYTES (2 * TILE_BYTES)
#define GEMM_SMEM (2 * STAGE_BYTES)
#define KCHUNKS 16

// ---------------- scratch (no allocations allowed) ----------------
__device__ float  g_q[(size_t)QROWS * TWO_D];
__device__ __nv_bfloat16 g_qh[(size_t)QROWS * TWO_D];
__device__ __nv_bfloat16 g_kh[(size_t)NKEYS * TWO_D];
__device__ double g_qmagd[QROWS];
__device__ float  g_qmagf[QROWS];
__device__ double g_kmagd[NKEYS];
__device__ float  g_kmagf[NKEYS];
__device__ __half g_scoresh[(size_t)QROWS * NKEYS];
__device__ float  g_norm[(size_t)QROWS * TWO_D];

// ---------------- helpers ----------------
__device__ __forceinline__ uint32_t smem_u32(const void* p) {
    uint32_t a;
    asm("{ .reg .u64 t; cvta.to.shared.u64 t, %1; cvt.u32.u64 %0, t; }" : "=r"(a) : "l"(p));
    return a;
}
__device__ __forceinline__ void cpasync16(uint32_t dst, const void* src) {
    asm volatile("cp.async.cg.shared.global [%0], [%1], 16;" :: "r"(dst), "l"(src) : "memory");
}
__device__ __forceinline__ void ldmx4(uint32_t* r, uint32_t a) {
    asm volatile("ldmatrix.sync.aligned.m8n8.x4.shared.b16 {%0,%1,%2,%3}, [%4];"
                 : "=r"(r[0]), "=r"(r[1]), "=r"(r[2]), "=r"(r[3]) : "r"(a));
}
__device__ __forceinline__ void ldmx2(uint32_t* r, uint32_t a) {
    asm volatile("ldmatrix.sync.aligned.m8n8.x2.shared.b16 {%0,%1}, [%2];"
                 : "=r"(r[0]), "=r"(r[1]) : "r"(a));
}
__device__ __forceinline__ void mma_bf16(float* d, const uint32_t* a, const uint32_t* b) {
    asm volatile(
        "mma.sync.aligned.m16n8k16.row.col.f32.bf16.bf16.f32 "
        "{%0,%1,%2,%3}, {%4,%5,%6,%7}, {%8,%9}, {%0,%1,%2,%3};"
        : "+f"(d[0]), "+f"(d[1]), "+f"(d[2]), "+f"(d[3])
        : "r"(a[0]), "r"(a[1]), "r"(a[2]), "r"(a[3]), "r"(b[0]), "r"(b[1]));
}

// Kahan add, rounding-mode-pinned so fast-math/contraction cannot break it
__device__ __forceinline__ void kadd(float& s, float& c, float t) {
    float y = __fsub_rn(t, c);
    float u = __fadd_rn(s, y);
    c = __fsub_rn(__fsub_rn(u, s), y);
    s = u;
}
// compensated product-accumulate
__device__ __forceinline__ void cdot(float& s, float& c, float& es, float a, float b) {
    float p = __fmul_rn(a, b);
    float e = __fmaf_rn(a, b, -p);
    kadd(s, c, p);
    es = __fadd_rn(es, e);
}

// ---------------- complex projection: Y = phase_linear(X, W, b) ----------------
template <bool PRECISE>
__global__ void __launch_bounds__(256)
cproj_kernel(const float* __restrict__ X,
             const float* __restrict__ Wr, const float* __restrict__ Wi,
             const float* __restrict__ br, const float* __restrict__ bi,
             float* __restrict__ Y)
{
    __shared__ float2 Xs[16][64];
    __shared__ float2 Ws[16][64];
    const int tid = threadIdx.x;
    const int m0 = blockIdx.y * 64;
    const int n0 = blockIdx.x * 64;
    const int kk = tid & 15;
    const int rr = tid >> 4;
    const int ty4 = (tid >> 4) * 4;
    const int tx4 = (tid & 15) * 4;

    float cr[4][4], ci[4][4], er[4][4], ei[4][4];
#pragma unroll
    for (int i = 0; i < 4; i++)
#pragma unroll
        for (int j = 0; j < 4; j++) { cr[i][j] = 0.f; ci[i][j] = 0.f; er[i][j] = 0.f; ei[i][j] = 0.f; }

    for (int k0 = 0; k0 < DIM; k0 += 16) {
#pragma unroll
        for (int r = 0; r < 4; r++) {
            int row = rr + r * 16;
            Xs[kk][row] = *(const float2*)&X[((size_t)(m0 + row) * DIM + k0 + kk) * 2];
            float wr = Wr[(size_t)(n0 + row) * DIM + k0 + kk];
            float wi = Wi[(size_t)(n0 + row) * DIM + k0 + kk];
            Ws[kk][row] = make_float2(wr, wi);
        }
        __syncthreads();
#pragma unroll
        for (int k = 0; k < 16; k++) {
            float2 a[4], w[4];
#pragma unroll
            for (int i = 0; i < 4; i++) a[i] = Xs[k][ty4 + i];
#pragma unroll
            for (int j = 0; j < 4; j++) w[j] = Ws[k][tx4 + j];
#pragma unroll
            for (int i = 0; i < 4; i++)
#pragma unroll
                for (int j = 0; j < 4; j++) {
                    if (PRECISE) {
                        float tr = __fmul_rn(a[i].x, w[j].x);
                        tr = __fmaf_rn(-a[i].y, w[j].y, tr);
                        kadd(cr[i][j], er[i][j], tr);
                        float tim = __fmul_rn(a[i].x, w[j].y);
                        tim = __fmaf_rn(a[i].y, w[j].x, tim);
                        kadd(ci[i][j], ei[i][j], tim);
                    } else {
                        cr[i][j] += a[i].x * w[j].x;
                        cr[i][j] -= a[i].y * w[j].y;
                        ci[i][j] += a[i].x * w[j].y;
                        ci[i][j] += a[i].y * w[j].x;
                    }
                }
        }
        __syncthreads();
    }
#pragma unroll
    for (int i = 0; i < 4; i++) {
        int m = m0 + ty4 + i;
#pragma unroll
        for (int j = 0; j < 4; j++) {
            int n = n0 + tx4 + j;
            float vr = PRECISE ? __fadd_rn(cr[i][j], er[i][j]) : cr[i][j];
            float vi = PRECISE ? __fadd_rn(ci[i][j], ei[i][j]) : ci[i][j];
            Y[((size_t)m * DIM + n) * 2 + 0] = vr + br[n];
            Y[((size_t)m * DIM + n) * 2 + 1] = vi + bi[n];
        }
    }
}

// ---------------- fused prep: double mag + fp32 mag + bf16 conversion ----------------
__global__ void __launch_bounds__(128)
prep_bf16_kernel(const float* __restrict__ X, __nv_bfloat16* __restrict__ Xh,
                 double* __restrict__ out_d, float* __restrict__ out_f)
{
    __shared__ double sm[128];
    const int row = blockIdx.x;
    const int tid = threadIdx.x;
    const float* p = X + (size_t)row * TWO_D;
    const int base = tid * 8;

    float4 v0 = *(const float4*)(p + base);
    float4 v1 = *(const float4*)(p + base + 4);

    double s = (double)v0.x * v0.x + (double)v0.y * v0.y
             + (double)v0.z * v0.z + (double)v0.w * v0.w
             + (double)v1.x * v1.x + (double)v1.y * v1.y
             + (double)v1.z * v1.z + (double)v1.w * v1.w;

    __nv_bfloat162 b0 = __float22bfloat162_rn(make_float2(v0.x, v0.y));
    __nv_bfloat162 b1 = __float22bfloat162_rn(make_float2(v0.z, v0.w));
    __nv_bfloat162 b2 = __float22bfloat162_rn(make_float2(v1.x, v1.y));
    __nv_bfloat162 b3 = __float22bfloat162_rn(make_float2(v1.z, v1.w));
    uint4 packed;
    packed.x = *(uint32_t*)&b0; packed.y = *(uint32_t*)&b1;
    packed.z = *(uint32_t*)&b2; packed.w = *(uint32_t*)&b3;
    *(uint4*)(Xh + (size_t)row * TWO_D + base) = packed;

    sm[tid] = s;
    __syncthreads();
    for (int o = 64; o > 0; o >>= 1) {
        if (tid < o) sm[tid] += sm[tid + o];
        __syncthreads();
    }
    if (tid == 0) {
        double m = sqrt(sm[0] + 1e-8);
        out_d[row] = m;
        out_f[row] = (float)m;
    }
}

// ---------------- bf16 mma.sync screening GEMM (round-8 proven) ----------------
__device__ __forceinline__ void gemm_load_stage(
    const char* Abase, const char* Bbase, uint32_t sb, int tid, int it, int s)
{
    const int seg = tid & 7;
    const size_t koff = (size_t)it * 128 + (size_t)seg * 16;
    const uint32_t so = sb + (uint32_t)s * STAGE_BYTES;
#pragma unroll
    for (int j = 0; j < 4; j++) {
        int row = (tid >> 3) + 32 * j;
        cpasync16(so + row * 144 + seg * 16, Abase + (size_t)row * 2048 + koff);
    }
#pragma unroll
    for (int j = 0; j < 4; j++) {
        int row = (tid >> 3) + 32 * j;
        cpasync16(so + TILE_BYTES + row * 144 + seg * 16, Bbase + (size_t)row * 2048 + koff);
    }
    asm volatile("cp.async.commit_group;" ::: "memory");
}

__global__ void __launch_bounds__(256, 2)
coh_gemm_mma(const __nv_bfloat16* __restrict__ A, const __nv_bfloat16* __restrict__ B,
             const float* __restrict__ qmag, const float* __restrict__ kmag,
             __half* __restrict__ C)
{
    extern __shared__ __align__(16) char smraw[];
    const uint32_t sb = smem_u32(smraw);
    const int tid = threadIdx.x;
    const int wid = tid >> 5, lane = tid & 31;
    const int m0 = blockIdx.x * GTM;
    const int n0 = blockIdx.y * GTN;
    const int wm0 = (wid & 1) * 64, wn0 = (wid >> 1) * 32;

    float acc[4][4][4];
#pragma unroll
    for (int a = 0; a < 4; a++)
#pragma unroll
        for (int b = 0; b < 4; b++)
#pragma unroll
            for (int c = 0; c < 4; c++) acc[a][b][c] = 0.f;

    const char* Abase = (const char*)A + (size_t)m0 * 2048;
    const char* Bbase = (const char*)B + (size_t)n0 * 2048;

    gemm_load_stage(Abase, Bbase, sb, tid, 0, 0);
    int buf = 0;
    const int arow = lane & 15, acol = (lane >> 4) * 8;
    const int brow = lane & 7,  bcol = ((lane >> 3) & 1) * 8;

    for (int it = 0; it < KCHUNKS; it++) {
        if (it < KCHUNKS - 1) {
            gemm_load_stage(Abase, Bbase, sb, tid, it + 1, buf ^ 1);
            asm volatile("cp.async.wait_group 1;" ::: "memory");
        } else {
            asm volatile("cp.async.wait_group 0;" ::: "memory");
        }
        __syncthreads();
        const uint32_t aB = sb + (uint32_t)buf * STAGE_BYTES;
        const uint32_t bB = aB + TILE_BYTES;
#pragma unroll
        for (int ks = 0; ks < 4; ks++) {
            uint32_t afr[4][4], bfr[4][2];
#pragma unroll
            for (int fm = 0; fm < 4; fm++)
                ldmx4(afr[fm], aB + (wm0 + fm * 16 + arow) * 144 + (ks * 16 + acol) * 2);
#pragma unroll
            for (int fn = 0; fn < 4; fn++)
                ldmx2(bfr[fn], bB + (wn0 + fn * 8 + brow) * 144 + (ks * 16 + bcol) * 2);
#pragma unroll
            for (int fm = 0; fm < 4; fm++)
#pragma unroll
                for (int fn = 0; fn < 4; fn++)
                    mma_bf16(acc[fm][fn], afr[fm], bfr[fn]);
        }
        __syncthreads();
        buf ^= 1;
    }

#pragma unroll
    for (int fm = 0; fm < 4; fm++) {
        int mlo = m0 + wm0 + fm * 16 + (lane >> 2);
        int mhi = mlo + 8;
        float qlo = qmag[mlo], qhi = qmag[mhi];
#pragma unroll
        for (int fn = 0; fn < 4; fn++) {
            int n = n0 + wn0 + fn * 8 + (lane & 3) * 2;
            float k0v = kmag[n], k1v = kmag[n + 1];
            __half2 hlo, hhi;
            hlo.x = __float2half_rn(acc[fm][fn][0] / (qlo * k0v + EPSF));
            hlo.y = __float2half_rn(acc[fm][fn][1] / (qlo * k1v + EPSF));
            hhi.x = __float2half_rn(acc[fm][fn][2] / (qhi * k0v + EPSF));
            hhi.y = __float2half_rn(acc[fm][fn][3] / (qhi * k1v + EPSF));
            *(__half2*)&C[(size_t)mlo * NKEYS + n] = hlo;
            *(__half2*)&C[(size_t)mhi * NKEYS + n] = hhi;
        }
    }
}

// ------- top-64 (half2 screen -> float-float rescore -> select) + softmax + gather + norm -----
__global__ void __launch_bounds__(256)
topk_kernel(const __half* __restrict__ scores,
            const float* __restrict__ qbuf,
            const float* __restrict__ keys,
            const double* __restrict__ qmagd,
            const double* __restrict__ kmagd,
            const float* __restrict__ values,
            const float* __restrict__ gamma,
            float* __restrict__ outn)
{
    __shared__ int    hist[NBINS];
    __shared__ int    csum[256];
    __shared__ float  qs[TWO_D];
    __shared__ double cand_d[CAP];
    __shared__ int    cand_i[CAP];
    __shared__ int    s_cnt;
    __shared__ int    s_thresh;
    __shared__ double sel_d[TOPK];
    __shared__ int    sel_i[TOPK];
    __shared__ float  s_w[TOPK];
    __shared__ double redv[8];
    __shared__ int    redi[8];
    __shared__ float  snorm[256];
    __shared__ float  s_inv;

    const int q = blockIdx.x;
    const int tid = threadIdx.x;
    const __half2* row2 = (const __half2*)(scores + (size_t)q * NKEYS);

    for (int i = tid; i < NBINS; i += 256) hist[i] = 0;
    for (int i = tid; i < TWO_D; i += 256) qs[i] = qbuf[(size_t)q * TWO_D + i];
    if (tid == 0) s_cnt = 0;
    __syncthreads();

    // pass 1: histogram (half2 vectorized: 64 iterations)
    for (int i = tid; i < NKEYS / 2; i += 256) {
        float2 s2 = __half22float2(row2[i]);
        int b0 = (int)floorf(__fmaf_rn(s2.x, 1024.f, 1024.f));
        int b1 = (int)floorf(__fmaf_rn(s2.y, 1024.f, 1024.f));
        b0 = max(0, min(NBINS - 1, b0));
        b1 = max(0, min(NBINS - 1, b1));
        atomicAdd(&hist[b0], 1);
        atomicAdd(&hist[b1], 1);
    }
    __syncthreads();

    {
        int c = 0;
#pragma unroll
        for (int j = 0; j < 8; j++) c += hist[tid * 8 + j];
        csum[tid] = c;
    }
    __syncthreads();
    if (tid == 0) {
        int acc = 0, thr = 0;
        for (int ch = 255; ch >= 0; ch--) {
            if (acc + csum[ch] >= TOPK) {
                for (int b = ch * 8 + 7; b >= ch * 8; b--) {
                    acc += hist[b];
                    if (acc >= TOPK) { thr = b; break; }
                }
                break;
            }
            acc += csum[ch];
        }
        s_thresh = max(thr - 2, 0);   // 2-bin margin (1.95e-3) >> bf16 screen + half store error
    }
    __syncthreads();
    const int thresh = s_thresh;

    // pass 2: candidate collection (half2 vectorized)
    for (int i = tid; i < NKEYS / 2; i += 256) {
        float2 s2 = __half22float2(row2[i]);
        int b0 = (int)floorf(__fmaf_rn(s2.x, 1024.f, 1024.f));
        int b1 = (int)floorf(__fmaf_rn(s2.y, 1024.f, 1024.f));
        b0 = max(0, min(NBINS - 1, b0));
        b1 = max(0, min(NBINS - 1, b1));
        if (b0 >= thresh) {
            int pos = atomicAdd(&s_cnt, 1);
            if (pos < CAP) cand_i[pos] = 2 * i;
        }
        if (b1 >= thresh) {
            int pos = atomicAdd(&s_cnt, 1);
            if (pos < CAP) cand_i[pos] = 2 * i + 1;
        }
    }
    __syncthreads();
    const int cnt = min(s_cnt, CAP);

    // ---- float-float compensated rescore (one warp per candidate) ----
    {
        const int wid = tid >> 5, lane = tid & 31;
        const double qm = qmagd[q];
        for (int c = wid; c < cnt; c += 8) {
            const int ki = cand_i[c];
            const float* kr = keys + (size_t)ki * TWO_D;
            float s = 0.f, comp = 0.f, es = 0.f;
#pragma unroll
            for (int t = 0; t < 8; t++) {
                int e = t * 128 + lane * 4;
                float4 kv = *(const float4*)(kr + e);
                cdot(s, comp, es, qs[e],     kv.x);
                cdot(s, comp, es, qs[e + 1], kv.y);
                cdot(s, comp, es, qs[e + 2], kv.z);
                cdot(s, comp, es, qs[e + 3], kv.w);
            }
            double acc = (double)s + (double)comp + (double)es;
#pragma unroll
            for (int o = 16; o > 0; o >>= 1)
                acc += __shfl_down_sync(0xffffffffu, acc, o);
            if (lane == 0) cand_d[c] = acc / (qm * kmagd[ki] + (double)EPSF);
        }
    }
    __syncthreads();

    for (int t = 0; t < TOPK; t++) {
        double bv = -1e300; int bi = 0;
        for (int i = tid; i < cnt; i += 256) {
            double v = cand_d[i];
            if (v > bv) { bv = v; bi = i; }
        }
#pragma unroll
        for (int o = 16; o > 0; o >>= 1) {
            double ov = __shfl_down_sync(0xffffffffu, bv, o);
            int    oi = __shfl_down_sync(0xffffffffu, bi, o);
            if (ov > bv) { bv = ov; bi = oi; }
        }
        if ((tid & 31) == 0) { redv[tid >> 5] = bv; redi[tid >> 5] = bi; }
        __syncthreads();
        if (tid == 0) {
            double fv = redv[0]; int fi = redi[0];
#pragma unroll
            for (int w = 1; w < 8; w++)
                if (redv[w] > fv) { fv = redv[w]; fi = redi[w]; }
            sel_d[t] = fv; sel_i[t] = cand_i[fi];
            cand_d[fi] = -1e300;
        }
        __syncthreads();
    }

    if (tid == 0) {
        float m = (float)sel_d[0];
        float z = 0.f;
        for (int t = 0; t < TOPK; t++) { float w = expf((float)sel_d[t] - m); s_w[t] = w; z += w; }
        float inv = 1.0f / z;
        for (int t = 0; t < TOPK; t++) s_w[t] *= inv;
    }
    __syncthreads();

    // weighted gather (each thread: 4 contiguous floats of the 1024-wide row)
    const int col = tid * 4;
    float4 acc = make_float4(0.f, 0.f, 0.f, 0.f);
    for (int t = 0; t < TOPK; t++) {
        const float4 v = *(const float4*)&values[(size_t)sel_i[t] * TWO_D + col];
        float w = s_w[t];
        acc.x += w * v.x; acc.y += w * v.y; acc.z += w * v.z; acc.w += w * v.w;
    }

    // fused phase norm: rms over the row, scale by gamma
    snorm[tid] = acc.x * acc.x + acc.y * acc.y + acc.z * acc.z + acc.w * acc.w;
    __syncthreads();
    for (int o = 128; o > 0; o >>= 1) {
        if (tid < o) snorm[tid] += snorm[tid + o];
        __syncthreads();
    }
    if (tid == 0) {
        float mean = snorm[0] / (float)DIM;
        s_inv = 1.0f / sqrtf(mean + EPSF);
    }
    __syncthreads();
    const float inv = s_inv;
    float2 g2 = *(const float2*)&gamma[col >> 1];
    float4 o4;
    o4.x = acc.x * g2.x * inv;
    o4.y = acc.y * g2.x * inv;
    o4.z = acc.z * g2.y * inv;
    o4.w = acc.w * g2.y * inv;
    *(float4*)&outn[(size_t)q * TWO_D + col] = o4;
}

// ---------------- launch ----------------
extern "C" void kernel_launch(void* const* d_in, const int* in_sizes, int n_in,
                              void* d_out, int out_size)
{
    const float* query = (const float*)d_in[0];
    const float* keys  = (const float*)d_in[1];
    const float* vals  = (const float*)d_in[2];
    const float* Wq_r  = (const float*)d_in[3];
    const float* Wq_i  = (const float*)d_in[4];
    const float* bq_r  = (const float*)d_in[5];
    const float* bq_i  = (const float*)d_in[6];
    const float* Wo_r  = (const float*)d_in[7];
    const float* Wo_i  = (const float*)d_in[8];
    const float* bo_r  = (const float*)d_in[9];
    const float* bo_i  = (const float*)d_in[10];
    const float* gamma = (const float*)d_in[11];
    float* out = (float*)d_out;

    void *p_q, *p_qh, *p_kh, *p_qmd, *p_qmf, *p_kmd, *p_kmf, *p_sc, *p_nrm;
    cudaGetSymbolAddress(&p_q,   g_q);
    cudaGetSymbolAddress(&p_qh,  g_qh);
    cudaGetSymbolAddress(&p_kh,  g_kh);
    cudaGetSymbolAddress(&p_qmd, g_qmagd);
    cudaGetSymbolAddress(&p_qmf, g_qmagf);
    cudaGetSymbolAddress(&p_kmd, g_kmagd);
    cudaGetSymbolAddress(&p_kmf, g_kmagf);
    cudaGetSymbolAddress(&p_sc,  g_scoresh);
    cudaGetSymbolAddress(&p_nrm, g_norm);
    float*  qbuf  = (float*)p_q;
    __nv_bfloat16* qh = (__nv_bfloat16*)p_qh;
    __nv_bfloat16* kh = (__nv_bfloat16*)p_kh;
    double* qmagd = (double*)p_qmd;
    float*  qmagf = (float*)p_qmf;
    double* kmagd = (double*)p_kmd;
    float*  kmagf = (float*)p_kmf;
    __half* sc    = (__half*)p_sc;
    float*  nrmb  = (float*)p_nrm;

    cudaFuncSetAttribute(coh_gemm_mma, cudaFuncAttributeMaxDynamicSharedMemorySize, GEMM_SMEM);

    dim3 gproj(DIM / 64, QROWS / 64);

    prep_bf16_kernel<<<NKEYS, 128>>>(keys, kh, kmagd, kmagf);
    cproj_kernel<true><<<gproj, 256>>>(query, Wq_r, Wq_i, bq_r, bq_i, qbuf);
    prep_bf16_kernel<<<QROWS, 128>>>(qbuf, qh, qmagd, qmagf);

    dim3 ggemm(QROWS / GTM, NKEYS / GTN);
    coh_gemm_mma<<<ggemm, 256, GEMM_SMEM>>>(qh, kh, qmagf, kmagf, sc);

    topk_kernel<<<QROWS, 256>>>(sc, qbuf, keys, qmagd, kmagd, vals, gamma, nrmb);
    cproj_kernel<false><<<gproj, 256>>>(nrmb, Wo_r, Wo_i, bo_r, bo_i, out);
}

// round 12
// speedup vs baseline: 4.7903x; 1.1031x over previous
#include <cuda_runtime.h>
#include <cuda_fp16.h>
#include <cuda_bf16.h>
#include <math.h>
#include <stdint.h>

#define QROWS 4096
#define DIM   512
#define TWO_D 1024
#define NKEYS 32768
#define TOPK  64
#define EPSF  1e-8f
#define NBINS 2048
#define CAP   1024

// ---- coherence GEMM: 128x128 tile, 3-stage cp.async ----
#define GTM 128
#define GTN 128
#define TILE_BYTES (128 * 144)
#define STAGE_BYTES (2 * TILE_BYTES)        // 36864 (A tile + B tile per stage)
#define NSTG 3
#define GEMM_SMEM (NSTG * STAGE_BYTES)      // 110592
#define KCHUNKS 16

// ---- out-projection split-bf16 GEMM: K = 3072 ----
#define PK 3072
#define PKCHUNKS (PK / 64)                  // 48
#define PGEMM_SMEM (2 * STAGE_BYTES)        // 73728, 2-stage

// ---------------- scratch (no allocations allowed) ----------------
__device__ float  g_q[(size_t)QROWS * TWO_D];
__device__ __nv_bfloat16 g_qh[(size_t)QROWS * TWO_D];
__device__ __nv_bfloat16 g_kh[(size_t)NKEYS * TWO_D];
__device__ double g_qmagd[QROWS];
__device__ float  g_qmagf[QROWS];
__device__ double g_kmagd[NKEYS];
__device__ float  g_kmagf[NKEYS];
__device__ __half g_scoresh[(size_t)QROWS * NKEYS];
__device__ float  g_norm[(size_t)QROWS * TWO_D];
__device__ __nv_bfloat16 g_A2[(size_t)QROWS * PK];      // [xh | xh | xl]
__device__ __nv_bfloat16 g_B2[(size_t)TWO_D * PK];      // [Bh | Bl | Bh]

// ---------------- helpers ----------------
__device__ __forceinline__ uint32_t smem_u32(const void* p) {
    uint32_t a;
    asm("{ .reg .u64 t; cvta.to.shared.u64 t, %1; cvt.u32.u64 %0, t; }" : "=r"(a) : "l"(p));
    return a;
}
__device__ __forceinline__ void cpasync16(uint32_t dst, const void* src) {
    asm volatile("cp.async.cg.shared.global [%0], [%1], 16;" :: "r"(dst), "l"(src) : "memory");
}
__device__ __forceinline__ void ldmx4(uint32_t* r, uint32_t a) {
    asm volatile("ldmatrix.sync.aligned.m8n8.x4.shared.b16 {%0,%1,%2,%3}, [%4];"
                 : "=r"(r[0]), "=r"(r[1]), "=r"(r[2]), "=r"(r[3]) : "r"(a));
}
__device__ __forceinline__ void ldmx2(uint32_t* r, uint32_t a) {
    asm volatile("ldmatrix.sync.aligned.m8n8.x2.shared.b16 {%0,%1}, [%2];"
                 : "=r"(r[0]), "=r"(r[1]) : "r"(a));
}
__device__ __forceinline__ void mma_bf16(float* d, const uint32_t* a, const uint32_t* b) {
    asm volatile(
        "mma.sync.aligned.m16n8k16.row.col.f32.bf16.bf16.f32 "
        "{%0,%1,%2,%3}, {%4,%5,%6,%7}, {%8,%9}, {%0,%1,%2,%3};"
        : "+f"(d[0]), "+f"(d[1]), "+f"(d[2]), "+f"(d[3])
        : "r"(a[0]), "r"(a[1]), "r"(a[2]), "r"(a[3]), "r"(b[0]), "r"(b[1]));
}

// Kahan add, rounding-mode-pinned
__device__ __forceinline__ void kadd(float& s, float& c, float t) {
    float y = __fsub_rn(t, c);
    float u = __fadd_rn(s, y);
    c = __fsub_rn(__fsub_rn(u, s), y);
    s = u;
}
// compensated product-accumulate
__device__ __forceinline__ void cdot(float& s, float& c, float& es, float a, float b) {
    float p = __fmul_rn(a, b);
    float e = __fmaf_rn(a, b, -p);
    kadd(s, c, p);
    es = __fadd_rn(es, e);
}

// ---------------- precise complex projection (q path) ----------------
__global__ void __launch_bounds__(256)
cproj_kernel(const float* __restrict__ X,
             const float* __restrict__ Wr, const float* __restrict__ Wi,
             const float* __restrict__ br, const float* __restrict__ bi,
             float* __restrict__ Y)
{
    __shared__ float2 Xs[16][64];
    __shared__ float2 Ws[16][64];
    const int tid = threadIdx.x;
    const int m0 = blockIdx.y * 64;
    const int n0 = blockIdx.x * 64;
    const int kk = tid & 15;
    const int rr = tid >> 4;
    const int ty4 = (tid >> 4) * 4;
    const int tx4 = (tid & 15) * 4;

    float cr[4][4], ci[4][4], er[4][4], ei[4][4];
#pragma unroll
    for (int i = 0; i < 4; i++)
#pragma unroll
        for (int j = 0; j < 4; j++) { cr[i][j] = 0.f; ci[i][j] = 0.f; er[i][j] = 0.f; ei[i][j] = 0.f; }

    for (int k0 = 0; k0 < DIM; k0 += 16) {
#pragma unroll
        for (int r = 0; r < 4; r++) {
            int row = rr + r * 16;
            Xs[kk][row] = *(const float2*)&X[((size_t)(m0 + row) * DIM + k0 + kk) * 2];
            float wr = Wr[(size_t)(n0 + row) * DIM + k0 + kk];
            float wi = Wi[(size_t)(n0 + row) * DIM + k0 + kk];
            Ws[kk][row] = make_float2(wr, wi);
        }
        __syncthreads();
#pragma unroll
        for (int k = 0; k < 16; k++) {
            float2 a[4], w[4];
#pragma unroll
            for (int i = 0; i < 4; i++) a[i] = Xs[k][ty4 + i];
#pragma unroll
            for (int j = 0; j < 4; j++) w[j] = Ws[k][tx4 + j];
#pragma unroll
            for (int i = 0; i < 4; i++)
#pragma unroll
                for (int j = 0; j < 4; j++) {
                    float tr = __fmul_rn(a[i].x, w[j].x);
                    tr = __fmaf_rn(-a[i].y, w[j].y, tr);
                    kadd(cr[i][j], er[i][j], tr);
                    float tim = __fmul_rn(a[i].x, w[j].y);
                    tim = __fmaf_rn(a[i].y, w[j].x, tim);
                    kadd(ci[i][j], ei[i][j], tim);
                }
        }
        __syncthreads();
    }
#pragma unroll
    for (int i = 0; i < 4; i++) {
        int m = m0 + ty4 + i;
#pragma unroll
        for (int j = 0; j < 4; j++) {
            int n = n0 + tx4 + j;
            Y[((size_t)m * DIM + n) * 2 + 0] = __fadd_rn(cr[i][j], er[i][j]) + br[n];
            Y[((size_t)m * DIM + n) * 2 + 1] = __fadd_rn(ci[i][j], ei[i][j]) + bi[n];
        }
    }
}

// ---------------- fused prep: double mag + fp32 mag + bf16 conversion ----------------
__global__ void __launch_bounds__(128)
prep_bf16_kernel(const float* __restrict__ X, __nv_bfloat16* __restrict__ Xh,
                 double* __restrict__ out_d, float* __restrict__ out_f)
{
    __shared__ double sm[128];
    const int row = blockIdx.x;
    const int tid = threadIdx.x;
    const float* p = X + (size_t)row * TWO_D;
    const int base = tid * 8;

    float4 v0 = *(const float4*)(p + base);
    float4 v1 = *(const float4*)(p + base + 4);

    double s = (double)v0.x * v0.x + (double)v0.y * v0.y
             + (double)v0.z * v0.z + (double)v0.w * v0.w
             + (double)v1.x * v1.x + (double)v1.y * v1.y
             + (double)v1.z * v1.z + (double)v1.w * v1.w;

    __nv_bfloat162 b0 = __float22bfloat162_rn(make_float2(v0.x, v0.y));
    __nv_bfloat162 b1 = __float22bfloat162_rn(make_float2(v0.z, v0.w));
    __nv_bfloat162 b2 = __float22bfloat162_rn(make_float2(v1.x, v1.y));
    __nv_bfloat162 b3 = __float22bfloat162_rn(make_float2(v1.z, v1.w));
    uint4 packed;
    packed.x = *(uint32_t*)&b0; packed.y = *(uint32_t*)&b1;
    packed.z = *(uint32_t*)&b2; packed.w = *(uint32_t*)&b3;
    *(uint4*)(Xh + (size_t)row * TWO_D + base) = packed;

    sm[tid] = s;
    __syncthreads();
    for (int o = 64; o > 0; o >>= 1) {
        if (tid < o) sm[tid] += sm[tid + o];
        __syncthreads();
    }
    if (tid == 0) {
        double m = sqrt(sm[0] + 1e-8);
        out_d[row] = m;
        out_f[row] = (float)m;
    }
}

// ---------------- coherence GEMM: 3-stage pipeline ----------------
__device__ __forceinline__ void gemm_load_stage(
    const char* Abase, const char* Bbase, size_t rstride,
    uint32_t sb, int tid, int it, int s)
{
    const int seg = tid & 7;
    const size_t koff = (size_t)it * 128 + (size_t)seg * 16;
    const uint32_t so = sb + (uint32_t)s * STAGE_BYTES;
#pragma unroll
    for (int j = 0; j < 4; j++) {
        int row = (tid >> 3) + 32 * j;
        cpasync16(so + row * 144 + seg * 16, Abase + (size_t)row * rstride + koff);
    }
#pragma unroll
    for (int j = 0; j < 4; j++) {
        int row = (tid >> 3) + 32 * j;
        cpasync16(so + TILE_BYTES + row * 144 + seg * 16, Bbase + (size_t)row * rstride + koff);
    }
    asm volatile("cp.async.commit_group;" ::: "memory");
}

__global__ void __launch_bounds__(256, 2)
coh_gemm_mma(const __nv_bfloat16* __restrict__ A, const __nv_bfloat16* __restrict__ B,
             const float* __restrict__ qmag, const float* __restrict__ kmag,
             __half* __restrict__ C)
{
    extern __shared__ __align__(16) char smraw[];
    const uint32_t sb = smem_u32(smraw);
    const int tid = threadIdx.x;
    const int wid = tid >> 5, lane = tid & 31;
    const int m0 = blockIdx.x * GTM;
    const int n0 = blockIdx.y * GTN;
    const int wm0 = (wid & 1) * 64, wn0 = (wid >> 1) * 32;

    float acc[4][4][4];
#pragma unroll
    for (int a = 0; a < 4; a++)
#pragma unroll
        for (int b = 0; b < 4; b++)
#pragma unroll
            for (int c = 0; c < 4; c++) acc[a][b][c] = 0.f;

    const char* Abase = (const char*)A + (size_t)m0 * 2048;
    const char* Bbase = (const char*)B + (size_t)n0 * 2048;

    gemm_load_stage(Abase, Bbase, 2048, sb, tid, 0, 0);
    gemm_load_stage(Abase, Bbase, 2048, sb, tid, 1, 1);

    const int arow = lane & 15, acol = (lane >> 4) * 8;
    const int brow = lane & 7,  bcol = ((lane >> 3) & 1) * 8;
    int buf = 0;

    for (int it = 0; it < KCHUNKS; it++) {
        if (it < KCHUNKS - 1) {
            asm volatile("cp.async.wait_group 1;" ::: "memory");
        } else {
            asm volatile("cp.async.wait_group 0;" ::: "memory");
        }
        __syncthreads();
        if (it + 2 < KCHUNKS)
            gemm_load_stage(Abase, Bbase, 2048, sb, tid, it + 2, (it + 2) % NSTG);

        const uint32_t aB = sb + (uint32_t)buf * STAGE_BYTES;
        const uint32_t bB = aB + TILE_BYTES;
#pragma unroll
        for (int ks = 0; ks < 4; ks++) {
            uint32_t afr[4][4], bfr[4][2];
#pragma unroll
            for (int fm = 0; fm < 4; fm++)
                ldmx4(afr[fm], aB + (wm0 + fm * 16 + arow) * 144 + (ks * 16 + acol) * 2);
#pragma unroll
            for (int fn = 0; fn < 4; fn++)
                ldmx2(bfr[fn], bB + (wn0 + fn * 8 + brow) * 144 + (ks * 16 + bcol) * 2);
#pragma unroll
            for (int fm = 0; fm < 4; fm++)
#pragma unroll
                for (int fn = 0; fn < 4; fn++)
                    mma_bf16(acc[fm][fn], afr[fm], bfr[fn]);
        }
        buf = (buf + 1) % NSTG;
    }

#pragma unroll
    for (int fm = 0; fm < 4; fm++) {
        int mlo = m0 + wm0 + fm * 16 + (lane >> 2);
        int mhi = mlo + 8;
        float qlo = qmag[mlo], qhi = qmag[mhi];
#pragma unroll
        for (int fn = 0; fn < 4; fn++) {
            int n = n0 + wn0 + fn * 8 + (lane & 3) * 2;
            float k0v = kmag[n], k1v = kmag[n + 1];
            __half2 hlo, hhi;
            hlo.x = __float2half_rn(acc[fm][fn][0] / (qlo * k0v + EPSF));
            hlo.y = __float2half_rn(acc[fm][fn][1] / (qlo * k1v + EPSF));
            hhi.x = __float2half_rn(acc[fm][fn][2] / (qhi * k0v + EPSF));
            hhi.y = __float2half_rn(acc[fm][fn][3] / (qhi * k1v + EPSF));
            *(__half2*)&C[(size_t)mlo * NKEYS + n] = hlo;
            *(__half2*)&C[(size_t)mhi * NKEYS + n] = hhi;
        }
    }
}

// ------- top-64 (half2 screen -> float-float rescore -> select) + softmax + gather + norm -----
__global__ void __launch_bounds__(256)
topk_kernel(const __half* __restrict__ scores,
            const float* __restrict__ qbuf,
            const float* __restrict__ keys,
            const double* __restrict__ qmagd,
            const double* __restrict__ kmagd,
            const float* __restrict__ values,
            const float* __restrict__ gamma,
            float* __restrict__ outn)
{
    __shared__ int    hist[NBINS];
    __shared__ int    csum[256];
    __shared__ float  qs[TWO_D];
    __shared__ double cand_d[CAP];
    __shared__ int    cand_i[CAP];
    __shared__ int    s_cnt;
    __shared__ int    s_thresh;
    __shared__ double sel_d[TOPK];
    __shared__ int    sel_i[TOPK];
    __shared__ float  s_w[TOPK];
    __shared__ double redv[8];
    __shared__ int    redi[8];
    __shared__ float  snorm[256];
    __shared__ float  s_inv;

    const int q = blockIdx.x;
    const int tid = threadIdx.x;
    const __half2* row2 = (const __half2*)(scores + (size_t)q * NKEYS);

    for (int i = tid; i < NBINS; i += 256) hist[i] = 0;
    for (int i = tid; i < TWO_D; i += 256) qs[i] = qbuf[(size_t)q * TWO_D + i];
    if (tid == 0) s_cnt = 0;
    __syncthreads();

    for (int i = tid; i < NKEYS / 2; i += 256) {
        float2 s2 = __half22float2(row2[i]);
        int b0 = (int)floorf(__fmaf_rn(s2.x, 1024.f, 1024.f));
        int b1 = (int)floorf(__fmaf_rn(s2.y, 1024.f, 1024.f));
        b0 = max(0, min(NBINS - 1, b0));
        b1 = max(0, min(NBINS - 1, b1));
        atomicAdd(&hist[b0], 1);
        atomicAdd(&hist[b1], 1);
    }
    __syncthreads();

    {
        int c = 0;
#pragma unroll
        for (int j = 0; j < 8; j++) c += hist[tid * 8 + j];
        csum[tid] = c;
    }
    __syncthreads();
    if (tid == 0) {
        int acc = 0, thr = 0;
        for (int ch = 255; ch >= 0; ch--) {
            if (acc + csum[ch] >= TOPK) {
                for (int b = ch * 8 + 7; b >= ch * 8; b--) {
                    acc += hist[b];
                    if (acc >= TOPK) { thr = b; break; }
                }
                break;
            }
            acc += csum[ch];
        }
        s_thresh = max(thr - 2, 0);
    }
    __syncthreads();
    const int thresh = s_thresh;

    for (int i = tid; i < NKEYS / 2; i += 256) {
        float2 s2 = __half22float2(row2[i]);
        int b0 = (int)floorf(__fmaf_rn(s2.x, 1024.f, 1024.f));
        int b1 = (int)floorf(__fmaf_rn(s2.y, 1024.f, 1024.f));
        b0 = max(0, min(NBINS - 1, b0));
        b1 = max(0, min(NBINS - 1, b1));
        if (b0 >= thresh) {
            int pos = atomicAdd(&s_cnt, 1);
            if (pos < CAP) cand_i[pos] = 2 * i;
        }
        if (b1 >= thresh) {
            int pos = atomicAdd(&s_cnt, 1);
            if (pos < CAP) cand_i[pos] = 2 * i + 1;
        }
    }
    __syncthreads();
    const int cnt = min(s_cnt, CAP);

    {
        const int wid = tid >> 5, lane = tid & 31;
        const double qm = qmagd[q];
        for (int c = wid; c < cnt; c += 8) {
            const int ki = cand_i[c];
            const float* kr = keys + (size_t)ki * TWO_D;
            float s = 0.f, comp = 0.f, es = 0.f;
#pragma unroll
            for (int t = 0; t < 8; t++) {
                int e = t * 128 + lane * 4;
                float4 kv = *(const float4*)(kr + e);
                cdot(s, comp, es, qs[e],     kv.x);
                cdot(s, comp, es, qs[e + 1], kv.y);
                cdot(s, comp, es, qs[e + 2], kv.z);
                cdot(s, comp, es, qs[e + 3], kv.w);
            }
            double acc = (double)s + (double)comp + (double)es;
#pragma unroll
            for (int o = 16; o > 0; o >>= 1)
                acc += __shfl_down_sync(0xffffffffu, acc, o);
            if (lane == 0) cand_d[c] = acc / (qm * kmagd[ki] + (double)EPSF);
        }
    }
    __syncthreads();

    for (int t = 0; t < TOPK; t++) {
        double bv = -1e300; int bi = 0;
        for (int i = tid; i < cnt; i += 256) {
            double v = cand_d[i];
            if (v > bv) { bv = v; bi = i; }
        }
#pragma unroll
        for (int o = 16; o > 0; o >>= 1) {
            double ov = __shfl_down_sync(0xffffffffu, bv, o);
            int    oi = __shfl_down_sync(0xffffffffu, bi, o);
            if (ov > bv) { bv = ov; bi = oi; }
        }
        if ((tid & 31) == 0) { redv[tid >> 5] = bv; redi[tid >> 5] = bi; }
        __syncthreads();
        if (tid == 0) {
            double fv = redv[0]; int fi = redi[0];
#pragma unroll
            for (int w = 1; w < 8; w++)
                if (redv[w] > fv) { fv = redv[w]; fi = redi[w]; }
            sel_d[t] = fv; sel_i[t] = cand_i[fi];
            cand_d[fi] = -1e300;
        }
        __syncthreads();
    }

    if (tid == 0) {
        float m = (float)sel_d[0];
        float z = 0.f;
        for (int t = 0; t < TOPK; t++) { float w = expf((float)sel_d[t] - m); s_w[t] = w; z += w; }
        float inv = 1.0f / z;
        for (int t = 0; t < TOPK; t++) s_w[t] *= inv;
    }
    __syncthreads();

    const int col = tid * 4;
    float4 acc = make_float4(0.f, 0.f, 0.f, 0.f);
    for (int t = 0; t < TOPK; t++) {
        const float4 v = *(const float4*)&values[(size_t)sel_i[t] * TWO_D + col];
        float w = s_w[t];
        acc.x += w * v.x; acc.y += w * v.y; acc.z += w * v.z; acc.w += w * v.w;
    }

    snorm[tid] = acc.x * acc.x + acc.y * acc.y + acc.z * acc.z + acc.w * acc.w;
    __syncthreads();
    for (int o = 128; o > 0; o >>= 1) {
        if (tid < o) snorm[tid] += snorm[tid + o];
        __syncthreads();
    }
    if (tid == 0) {
        float mean = snorm[0] / (float)DIM;
        s_inv = 1.0f / sqrtf(mean + EPSF);
    }
    __syncthreads();
    const float inv = s_inv;
    float2 g2 = *(const float2*)&gamma[col >> 1];
    float4 o4;
    o4.x = acc.x * g2.x * inv;
    o4.y = acc.y * g2.x * inv;
    o4.z = acc.z * g2.y * inv;
    o4.w = acc.w * g2.y * inv;
    *(float4*)&outn[(size_t)q * TWO_D + col] = o4;
}

// ---------------- split prep for out-projection ----------------
// A2 row m: [xh(1024) | xh(1024) | xl(1024)] from nrmb
__global__ void __launch_bounds__(256)
prep_splitA_kernel(const float* __restrict__ X, __nv_bfloat16* __restrict__ A2)
{
    const int row = blockIdx.x;
    const int base = threadIdx.x * 4;
    float4 v = *(const float4*)&X[(size_t)row * TWO_D + base];
    __nv_bfloat16 h0 = __float2bfloat16(v.x), h1 = __float2bfloat16(v.y);
    __nv_bfloat16 h2 = __float2bfloat16(v.z), h3 = __float2bfloat16(v.w);
    __nv_bfloat16 l0 = __float2bfloat16(v.x - __bfloat162float(h0));
    __nv_bfloat16 l1 = __float2bfloat16(v.y - __bfloat162float(h1));
    __nv_bfloat16 l2 = __float2bfloat16(v.z - __bfloat162float(h2));
    __nv_bfloat16 l3 = __float2bfloat16(v.w - __bfloat162float(h3));
    __nv_bfloat16* r = A2 + (size_t)row * PK;
    uint2 hp, lp;
    ((__nv_bfloat16*)&hp)[0] = h0; ((__nv_bfloat16*)&hp)[1] = h1;
    ((__nv_bfloat16*)&hp)[2] = h2; ((__nv_bfloat16*)&hp)[3] = h3;
    ((__nv_bfloat16*)&lp)[0] = l0; ((__nv_bfloat16*)&lp)[1] = l1;
    ((__nv_bfloat16*)&lp)[2] = l2; ((__nv_bfloat16*)&lp)[3] = l3;
    *(uint2*)(r + base)          = hp;
    *(uint2*)(r + TWO_D + base)  = hp;
    *(uint2*)(r + 2048 + base)   = lp;
}

// B2 row j (j=2n+s): [Bh | Bl | Bh]; B[j][2d+p] = {s0:(Wr,-Wi), s1:(Wi,Wr)}[p]
__global__ void __launch_bounds__(256)
prep_splitB_kernel(const float* __restrict__ Wr, const float* __restrict__ Wi,
                   __nv_bfloat16* __restrict__ B2)
{
    const int j = blockIdx.x;
    const int n = j >> 1, s = j & 1;
    __nv_bfloat16* r = B2 + (size_t)j * PK;
    for (int c = threadIdx.x; c < TWO_D; c += 256) {
        int d = c >> 1, p = c & 1;
        float v;
        if (s == 0) v = (p == 0) ? Wr[(size_t)n * DIM + d] : -Wi[(size_t)n * DIM + d];
        else        v = (p == 0) ? Wi[(size_t)n * DIM + d] :  Wr[(size_t)n * DIM + d];
        __nv_bfloat16 h = __float2bfloat16(v);
        __nv_bfloat16 l = __float2bfloat16(v - __bfloat162float(h));
        r[c] = h;
        r[TWO_D + c] = l;
        r[2048 + c] = h;
    }
}

// ---------------- out-projection GEMM (split-bf16, K=3072, fp32 out + bias) -------------
__global__ void __launch_bounds__(256, 2)
proj_gemm_mma(const __nv_bfloat16* __restrict__ A, const __nv_bfloat16* __restrict__ B,
              const float* __restrict__ br, const float* __restrict__ bi,
              float* __restrict__ C)
{
    extern __shared__ __align__(16) char smraw[];
    const uint32_t sb = smem_u32(smraw);
    const int tid = threadIdx.x;
    const int wid = tid >> 5, lane = tid & 31;
    const int m0 = blockIdx.x * 128;
    const int n0 = blockIdx.y * 128;
    const int wm0 = (wid & 1) * 64, wn0 = (wid >> 1) * 32;

    float acc[4][4][4];
#pragma unroll
    for (int a = 0; a < 4; a++)
#pragma unroll
        for (int b = 0; b < 4; b++)
#pragma unroll
            for (int c = 0; c < 4; c++) acc[a][b][c] = 0.f;

    const char* Abase = (const char*)A + (size_t)m0 * (PK * 2);
    const char* Bbase = (const char*)B + (size_t)n0 * (PK * 2);

    gemm_load_stage(Abase, Bbase, PK * 2, sb, tid, 0, 0);
    int buf = 0;
    const int arow = lane & 15, acol = (lane >> 4) * 8;
    const int brow = lane & 7,  bcol = ((lane >> 3) & 1) * 8;

    for (int it = 0; it < PKCHUNKS; it++) {
        if (it < PKCHUNKS - 1) {
            gemm_load_stage(Abase, Bbase, PK * 2, sb, tid, it + 1, buf ^ 1);
            asm volatile("cp.async.wait_group 1;" ::: "memory");
        } else {
            asm volatile("cp.async.wait_group 0;" ::: "memory");
        }
        __syncthreads();
        const uint32_t aB = sb + (uint32_t)buf * STAGE_BYTES;
        const uint32_t bB = aB + TILE_BYTES;
#pragma unroll
        for (int ks = 0; ks < 4; ks++) {
            uint32_t afr[4][4], bfr[4][2];
#pragma unroll
            for (int fm = 0; fm < 4; fm++)
                ldmx4(afr[fm], aB + (wm0 + fm * 16 + arow) * 144 + (ks * 16 + acol) * 2);
#pragma unroll
            for (int fn = 0; fn < 4; fn++)
                ldmx2(bfr[fn], bB + (wn0 + fn * 8 + brow) * 144 + (ks * 16 + bcol) * 2);
#pragma unroll
            for (int fm = 0; fm < 4; fm++)
#pragma unroll
                for (int fn = 0; fn < 4; fn++)
                    mma_bf16(acc[fm][fn], afr[fm], bfr[fn]);
        }
        __syncthreads();
        buf ^= 1;
    }

#pragma unroll
    for (int fm = 0; fm < 4; fm++) {
        int mlo = m0 + wm0 + fm * 16 + (lane >> 2);
        int mhi = mlo + 8;
#pragma unroll
        for (int fn = 0; fn < 4; fn++) {
            int n = n0 + wn0 + fn * 8 + (lane & 3) * 2;   // even: (real, imag) pair
            float b0 = br[n >> 1], b1 = bi[n >> 1];
            float2 vlo = make_float2(acc[fm][fn][0] + b0, acc[fm][fn][1] + b1);
            float2 vhi = make_float2(acc[fm][fn][2] + b0, acc[fm][fn][3] + b1);
            *(float2*)&C[(size_t)mlo * TWO_D + n] = vlo;
            *(float2*)&C[(size_t)mhi * TWO_D + n] = vhi;
        }
    }
}

// ---------------- launch ----------------
extern "C" void kernel_launch(void* const* d_in, const int* in_sizes, int n_in,
                              void* d_out, int out_size)
{
    const float* query = (const float*)d_in[0];
    const float* keys  = (const float*)d_in[1];
    const float* vals  = (const float*)d_in[2];
    const float* Wq_r  = (const float*)d_in[3];
    const float* Wq_i  = (const float*)d_in[4];
    const float* bq_r  = (const float*)d_in[5];
    const float* bq_i  = (const float*)d_in[6];
    const float* Wo_r  = (const float*)d_in[7];
    const float* Wo_i  = (const float*)d_in[8];
    const float* bo_r  = (const float*)d_in[9];
    const float* bo_i  = (const float*)d_in[10];
    const float* gamma = (const float*)d_in[11];
    float* out = (float*)d_out;

    void *p_q, *p_qh, *p_kh, *p_qmd, *p_qmf, *p_kmd, *p_kmf, *p_sc, *p_nrm, *p_A2, *p_B2;
    cudaGetSymbolAddress(&p_q,   g_q);
    cudaGetSymbolAddress(&p_qh,  g_qh);
    cudaGetSymbolAddress(&p_kh,  g_kh);
    cudaGetSymbolAddress(&p_qmd, g_qmagd);
    cudaGetSymbolAddress(&p_qmf, g_qmagf);
    cudaGetSymbolAddress(&p_kmd, g_kmagd);
    cudaGetSymbolAddress(&p_kmf, g_kmagf);
    cudaGetSymbolAddress(&p_sc,  g_scoresh);
    cudaGetSymbolAddress(&p_nrm, g_norm);
    cudaGetSymbolAddress(&p_A2,  g_A2);
    cudaGetSymbolAddress(&p_B2,  g_B2);
    float*  qbuf  = (float*)p_q;
    __nv_bfloat16* qh = (__nv_bfloat16*)p_qh;
    __nv_bfloat16* kh = (__nv_bfloat16*)p_kh;
    double* qmagd = (double*)p_qmd;
    float*  qmagf = (float*)p_qmf;
    double* kmagd = (double*)p_kmd;
    float*  kmagf = (float*)p_kmf;
    __half* sc    = (__half*)p_sc;
    float*  nrmb  = (float*)p_nrm;
    __nv_bfloat16* A2 = (__nv_bfloat16*)p_A2;
    __nv_bfloat16* B2 = (__nv_bfloat16*)p_B2;

    cudaFuncSetAttribute(coh_gemm_mma, cudaFuncAttributeMaxDynamicSharedMemorySize, GEMM_SMEM);
    cudaFuncSetAttribute(proj_gemm_mma, cudaFuncAttributeMaxDynamicSharedMemorySize, PGEMM_SMEM);

    dim3 gproj(DIM / 64, QROWS / 64);

    prep_bf16_kernel<<<NKEYS, 128>>>(keys, kh, kmagd, kmagf);
    prep_splitB_kernel<<<TWO_D, 256>>>(Wo_r, Wo_i, B2);
    cproj_kernel<<<gproj, 256>>>(query, Wq_r, Wq_i, bq_r, bq_i, qbuf);
    prep_bf16_kernel<<<QROWS, 128>>>(qbuf, qh, qmagd, qmagf);

    dim3 ggemm(QROWS / GTM, NKEYS / GTN);
    coh_gemm_mma<<<ggemm, 256, GEMM_SMEM>>>(qh, kh, qmagf, kmagf, sc);

    topk_kernel<<<QROWS, 256>>>(sc, qbuf, keys, qmagd, kmagd, vals, gamma, nrmb);

    prep_splitA_kernel<<<QROWS, 256>>>(nrmb, A2);
    dim3 gpro(QROWS / 128, TWO_D / 128);
    proj_gemm_mma<<<gpro, 256, PGEMM_SMEM>>>(A2, B2, bo_r, bo_i, out);
}

// round 14
// speedup vs baseline: 5.0609x; 1.0565x over previous
#include <cuda_runtime.h>
#include <cuda_fp16.h>
#include <cuda_bf16.h>
#include <math.h>
#include <stdint.h>

#define QROWS 4096
#define DIM   512
#define TWO_D 1024
#define NKEYS 32768
#define TOPK  64
#define EPSF  1e-8f
#define NBINS 2048
#define CAP   1024

// ---- coherence GEMM: 128x128 tile, 3-stage cp.async ----
#define GTM 128
#define GTN 128
#define TILE_BYTES (128 * 144)
#define STAGE_BYTES (2 * TILE_BYTES)        // 36864
#define NSTG 3
#define GEMM_SMEM (NSTG * STAGE_BYTES)      // 110592
#define KCHUNKS 16

// ---- out-projection split-bf16 GEMM: K = 3072 ----
#define PKO 3072
#define PGEMM_SMEM (2 * STAGE_BYTES)        // 73728, 2-stage

// ---------------- scratch (no allocations allowed) ----------------
__device__ float  g_q[(size_t)QROWS * TWO_D];
__device__ __nv_bfloat16 g_qh[(size_t)QROWS * TWO_D];
__device__ __nv_bfloat16 g_kh[(size_t)NKEYS * TWO_D];
__device__ double g_qmagd[QROWS];
__device__ float  g_qmagf[QROWS];
__device__ double g_kmagd[NKEYS];
__device__ float  g_kmagf[NKEYS];
__device__ __half g_scoresh[(size_t)QROWS * NKEYS];
__device__ float  g_norm[(size_t)QROWS * TWO_D];
__device__ __nv_bfloat16 g_A2o[(size_t)QROWS * PKO];
__device__ __nv_bfloat16 g_B2o[(size_t)TWO_D * PKO];

// ---------------- helpers ----------------
__device__ __forceinline__ uint32_t smem_u32(const void* p) {
    uint32_t a;
    asm("{ .reg .u64 t; cvta.to.shared.u64 t, %1; cvt.u32.u64 %0, t; }" : "=r"(a) : "l"(p));
    return a;
}
__device__ __forceinline__ void cpasync16(uint32_t dst, const void* src) {
    asm volatile("cp.async.cg.shared.global [%0], [%1], 16;" :: "r"(dst), "l"(src) : "memory");
}
__device__ __forceinline__ void ldmx4(uint32_t* r, uint32_t a) {
    asm volatile("ldmatrix.sync.aligned.m8n8.x4.shared.b16 {%0,%1,%2,%3}, [%4];"
                 : "=r"(r[0]), "=r"(r[1]), "=r"(r[2]), "=r"(r[3]) : "r"(a));
}
__device__ __forceinline__ void ldmx2(uint32_t* r, uint32_t a) {
    asm volatile("ldmatrix.sync.aligned.m8n8.x2.shared.b16 {%0,%1}, [%2];"
                 : "=r"(r[0]), "=r"(r[1]) : "r"(a));
}
__device__ __forceinline__ void mma_bf16(float* d, const uint32_t* a, const uint32_t* b) {
    asm volatile(
        "mma.sync.aligned.m16n8k16.row.col.f32.bf16.bf16.f32 "
        "{%0,%1,%2,%3}, {%4,%5,%6,%7}, {%8,%9}, {%0,%1,%2,%3};"
        : "+f"(d[0]), "+f"(d[1]), "+f"(d[2]), "+f"(d[3])
        : "r"(a[0]), "r"(a[1]), "r"(a[2]), "r"(a[3]), "r"(b[0]), "r"(b[1]));
}

// Kahan add, rounding-mode-pinned
__device__ __forceinline__ void kadd(float& s, float& c, float t) {
    float y = __fsub_rn(t, c);
    float u = __fadd_rn(s, y);
    c = __fsub_rn(__fsub_rn(u, s), y);
    s = u;
}
// compensated product-accumulate (rescore path)
__device__ __forceinline__ void cdot(float& s, float& c, float& es, float a, float b) {
    float p = __fmul_rn(a, b);
    float e = __fmaf_rn(a, b, -p);
    kadd(s, c, p);
    es = __fadd_rn(es, e);
}

// ---------------- precise q projection: block-compensated accumulation ----------------
// Each 16-step k-block accumulated with plain FMA (partial |sum|~0.11 -> block err ~1e-8),
// folded into a Kahan master sum once per block. sigma_dq ~ 5e-8 (same regime as full Kahan).
__global__ void __launch_bounds__(256)
cproj_kernel(const float* __restrict__ X,
             const float* __restrict__ Wr, const float* __restrict__ Wi,
             const float* __restrict__ br, const float* __restrict__ bi,
             float* __restrict__ Y)
{
    __shared__ float2 Xs[16][64];
    __shared__ float2 Ws[16][64];
    const int tid = threadIdx.x;
    const int m0 = blockIdx.y * 64;
    const int n0 = blockIdx.x * 64;
    const int kk = tid & 15;
    const int rr = tid >> 4;
    const int ty4 = (tid >> 4) * 4;
    const int tx4 = (tid & 15) * 4;

    float cr[4][4], ci[4][4], er[4][4], ei[4][4];
#pragma unroll
    for (int i = 0; i < 4; i++)
#pragma unroll
        for (int j = 0; j < 4; j++) { cr[i][j] = 0.f; ci[i][j] = 0.f; er[i][j] = 0.f; ei[i][j] = 0.f; }

    for (int k0 = 0; k0 < DIM; k0 += 16) {
#pragma unroll
        for (int r = 0; r < 4; r++) {
            int row = rr + r * 16;
            Xs[kk][row] = *(const float2*)&X[((size_t)(m0 + row) * DIM + k0 + kk) * 2];
            float wr = Wr[(size_t)(n0 + row) * DIM + k0 + kk];
            float wi = Wi[(size_t)(n0 + row) * DIM + k0 + kk];
            Ws[kk][row] = make_float2(wr, wi);
        }
        __syncthreads();

        float tr[4][4], ti[4][4];
#pragma unroll
        for (int i = 0; i < 4; i++)
#pragma unroll
            for (int j = 0; j < 4; j++) { tr[i][j] = 0.f; ti[i][j] = 0.f; }

#pragma unroll
        for (int k = 0; k < 16; k++) {
            float2 a[4], w[4];
#pragma unroll
            for (int i = 0; i < 4; i++) a[i] = Xs[k][ty4 + i];
#pragma unroll
            for (int j = 0; j < 4; j++) w[j] = Ws[k][tx4 + j];
#pragma unroll
            for (int i = 0; i < 4; i++)
#pragma unroll
                for (int j = 0; j < 4; j++) {
                    tr[i][j] = __fmaf_rn(a[i].x, w[j].x, tr[i][j]);
                    tr[i][j] = __fmaf_rn(-a[i].y, w[j].y, tr[i][j]);
                    ti[i][j] = __fmaf_rn(a[i].x, w[j].y, ti[i][j]);
                    ti[i][j] = __fmaf_rn(a[i].y, w[j].x, ti[i][j]);
                }
        }
#pragma unroll
        for (int i = 0; i < 4; i++)
#pragma unroll
            for (int j = 0; j < 4; j++) {
                kadd(cr[i][j], er[i][j], tr[i][j]);
                kadd(ci[i][j], ei[i][j], ti[i][j]);
            }
        __syncthreads();
    }
#pragma unroll
    for (int i = 0; i < 4; i++) {
        int m = m0 + ty4 + i;
#pragma unroll
        for (int j = 0; j < 4; j++) {
            int n = n0 + tx4 + j;
            Y[((size_t)m * DIM + n) * 2 + 0] = __fadd_rn(cr[i][j], er[i][j]) + br[n];
            Y[((size_t)m * DIM + n) * 2 + 1] = __fadd_rn(ci[i][j], ei[i][j]) + bi[n];
        }
    }
}

// ---------------- fused prep: double mag + fp32 mag + bf16 conversion ----------------
__global__ void __launch_bounds__(128)
prep_bf16_kernel(const float* __restrict__ X, __nv_bfloat16* __restrict__ Xh,
                 double* __restrict__ out_d, float* __restrict__ out_f)
{
    __shared__ double sm[128];
    const int row = blockIdx.x;
    const int tid = threadIdx.x;
    const float* p = X + (size_t)row * TWO_D;
    const int base = tid * 8;

    float4 v0 = *(const float4*)(p + base);
    float4 v1 = *(const float4*)(p + base + 4);

    double s = (double)v0.x * v0.x + (double)v0.y * v0.y
             + (double)v0.z * v0.z + (double)v0.w * v0.w
             + (double)v1.x * v1.x + (double)v1.y * v1.y
             + (double)v1.z * v1.z + (double)v1.w * v1.w;

    __nv_bfloat162 b0 = __float22bfloat162_rn(make_float2(v0.x, v0.y));
    __nv_bfloat162 b1 = __float22bfloat162_rn(make_float2(v0.z, v0.w));
    __nv_bfloat162 b2 = __float22bfloat162_rn(make_float2(v1.x, v1.y));
    __nv_bfloat162 b3 = __float22bfloat162_rn(make_float2(v1.z, v1.w));
    uint4 packed;
    packed.x = *(uint32_t*)&b0; packed.y = *(uint32_t*)&b1;
    packed.z = *(uint32_t*)&b2; packed.w = *(uint32_t*)&b3;
    *(uint4*)(Xh + (size_t)row * TWO_D + base) = packed;

    sm[tid] = s;
    __syncthreads();
    for (int o = 64; o > 0; o >>= 1) {
        if (tid < o) sm[tid] += sm[tid + o];
        __syncthreads();
    }
    if (tid == 0) {
        double m = sqrt(sm[0] + 1e-8);
        out_d[row] = m;
        out_f[row] = (float)m;
    }
}

// ---------------- stage loader (A tile + B tile) ----------------
__device__ __forceinline__ void gemm_load_stage(
    const char* Abase, const char* Bbase, size_t rstride,
    uint32_t sb, int tid, int it, int s)
{
    const int seg = tid & 7;
    const size_t koff = (size_t)it * 128 + (size_t)seg * 16;
    const uint32_t so = sb + (uint32_t)s * STAGE_BYTES;
#pragma unroll
    for (int j = 0; j < 4; j++) {
        int row = (tid >> 3) + 32 * j;
        cpasync16(so + row * 144 + seg * 16, Abase + (size_t)row * rstride + koff);
    }
#pragma unroll
    for (int j = 0; j < 4; j++) {
        int row = (tid >> 3) + 32 * j;
        cpasync16(so + TILE_BYTES + row * 144 + seg * 16, Bbase + (size_t)row * rstride + koff);
    }
    asm volatile("cp.async.commit_group;" ::: "memory");
}

// ---------------- coherence GEMM: 3-stage pipeline ----------------
__global__ void __launch_bounds__(256, 2)
coh_gemm_mma(const __nv_bfloat16* __restrict__ A, const __nv_bfloat16* __restrict__ B,
             const float* __restrict__ qmag, const float* __restrict__ kmag,
             __half* __restrict__ C)
{
    extern __shared__ __align__(16) char smraw[];
    const uint32_t sb = smem_u32(smraw);
    const int tid = threadIdx.x;
    const int wid = tid >> 5, lane = tid & 31;
    const int m0 = blockIdx.x * GTM;
    const int n0 = blockIdx.y * GTN;
    const int wm0 = (wid & 1) * 64, wn0 = (wid >> 1) * 32;

    float acc[4][4][4];
#pragma unroll
    for (int a = 0; a < 4; a++)
#pragma unroll
        for (int b = 0; b < 4; b++)
#pragma unroll
            for (int c = 0; c < 4; c++) acc[a][b][c] = 0.f;

    const char* Abase = (const char*)A + (size_t)m0 * 2048;
    const char* Bbase = (const char*)B + (size_t)n0 * 2048;

    gemm_load_stage(Abase, Bbase, 2048, sb, tid, 0, 0);
    gemm_load_stage(Abase, Bbase, 2048, sb, tid, 1, 1);

    const int arow = lane & 15, acol = (lane >> 4) * 8;
    const int brow = lane & 7,  bcol = ((lane >> 3) & 1) * 8;
    int buf = 0;

    for (int it = 0; it < KCHUNKS; it++) {
        if (it < KCHUNKS - 1) {
            asm volatile("cp.async.wait_group 1;" ::: "memory");
        } else {
            asm volatile("cp.async.wait_group 0;" ::: "memory");
        }
        __syncthreads();
        if (it + 2 < KCHUNKS)
            gemm_load_stage(Abase, Bbase, 2048, sb, tid, it + 2, (it + 2) % NSTG);

        const uint32_t aB = sb + (uint32_t)buf * STAGE_BYTES;
        const uint32_t bB = aB + TILE_BYTES;
#pragma unroll
        for (int ks = 0; ks < 4; ks++) {
            uint32_t afr[4][4], bfr[4][2];
#pragma unroll
            for (int fm = 0; fm < 4; fm++)
                ldmx4(afr[fm], aB + (wm0 + fm * 16 + arow) * 144 + (ks * 16 + acol) * 2);
#pragma unroll
            for (int fn = 0; fn < 4; fn++)
                ldmx2(bfr[fn], bB + (wn0 + fn * 8 + brow) * 144 + (ks * 16 + bcol) * 2);
#pragma unroll
            for (int fm = 0; fm < 4; fm++)
#pragma unroll
                for (int fn = 0; fn < 4; fn++)
                    mma_bf16(acc[fm][fn], afr[fm], bfr[fn]);
        }
        buf = (buf + 1) % NSTG;
    }

#pragma unroll
    for (int fm = 0; fm < 4; fm++) {
        int mlo = m0 + wm0 + fm * 16 + (lane >> 2);
        int mhi = mlo + 8;
        float qlo = qmag[mlo], qhi = qmag[mhi];
#pragma unroll
        for (int fn = 0; fn < 4; fn++) {
            int n = n0 + wn0 + fn * 8 + (lane & 3) * 2;
            float k0v = kmag[n], k1v = kmag[n + 1];
            __half2 hlo, hhi;
            hlo.x = __float2half_rn(acc[fm][fn][0] / (qlo * k0v + EPSF));
            hlo.y = __float2half_rn(acc[fm][fn][1] / (qlo * k1v + EPSF));
            hhi.x = __float2half_rn(acc[fm][fn][2] / (qhi * k0v + EPSF));
            hhi.y = __float2half_rn(acc[fm][fn][3] / (qhi * k1v + EPSF));
            *(__half2*)&C[(size_t)mlo * NKEYS + n] = hlo;
            *(__half2*)&C[(size_t)mhi * NKEYS + n] = hhi;
        }
    }
}

// ------- top-64 (half2 screen -> float-float rescore -> select) + softmax + gather + norm -----
__global__ void __launch_bounds__(256)
topk_kernel(const __half* __restrict__ scores,
            const float* __restrict__ qbuf,
            const float* __restrict__ keys,
            const double* __restrict__ qmagd,
            const double* __restrict__ kmagd,
            const float* __restrict__ values,
            const float* __restrict__ gamma,
            float* __restrict__ outn)
{
    __shared__ int    hist[NBINS];
    __shared__ int    csum[256];
    __shared__ float  qs[TWO_D];
    __shared__ double cand_d[CAP];
    __shared__ int    cand_i[CAP];
    __shared__ int    s_cnt;
    __shared__ int    s_thresh;
    __shared__ double sel_d[TOPK];
    __shared__ int    sel_i[TOPK];
    __shared__ float  s_w[TOPK];
    __shared__ double redv[8];
    __shared__ int    redi[8];
    __shared__ float  snorm[256];
    __shared__ float  s_inv;

    const int q = blockIdx.x;
    const int tid = threadIdx.x;
    const __half2* row2 = (const __half2*)(scores + (size_t)q * NKEYS);

    for (int i = tid; i < NBINS; i += 256) hist[i] = 0;
    for (int i = tid; i < TWO_D; i += 256) qs[i] = qbuf[(size_t)q * TWO_D + i];
    if (tid == 0) s_cnt = 0;
    __syncthreads();

    for (int i = tid; i < NKEYS / 2; i += 256) {
        float2 s2 = __half22float2(row2[i]);
        int b0 = (int)floorf(__fmaf_rn(s2.x, 1024.f, 1024.f));
        int b1 = (int)floorf(__fmaf_rn(s2.y, 1024.f, 1024.f));
        b0 = max(0, min(NBINS - 1, b0));
        b1 = max(0, min(NBINS - 1, b1));
        atomicAdd(&hist[b0], 1);
        atomicAdd(&hist[b1], 1);
    }
    __syncthreads();

    {
        int c = 0;
#pragma unroll
        for (int j = 0; j < 8; j++) c += hist[tid * 8 + j];
        csum[tid] = c;
    }
    __syncthreads();
    if (tid == 0) {
        int acc = 0, thr = 0;
        for (int ch = 255; ch >= 0; ch--) {
            if (acc + csum[ch] >= TOPK) {
                for (int b = ch * 8 + 7; b >= ch * 8; b--) {
                    acc += hist[b];
                    if (acc >= TOPK) { thr = b; break; }
                }
                break;
            }
            acc += csum[ch];
        }
        s_thresh = max(thr - 2, 0);
    }
    __syncthreads();
    const int thresh = s_thresh;

    for (int i = tid; i < NKEYS / 2; i += 256) {
        float2 s2 = __half22float2(row2[i]);
        int b0 = (int)floorf(__fmaf_rn(s2.x, 1024.f, 1024.f));
        int b1 = (int)floorf(__fmaf_rn(s2.y, 1024.f, 1024.f));
        b0 = max(0, min(NBINS - 1, b0));
        b1 = max(0, min(NBINS - 1, b1));
        if (b0 >= thresh) {
            int pos = atomicAdd(&s_cnt, 1);
            if (pos < CAP) cand_i[pos] = 2 * i;
        }
        if (b1 >= thresh) {
            int pos = atomicAdd(&s_cnt, 1);
            if (pos < CAP) cand_i[pos] = 2 * i + 1;
        }
    }
    __syncthreads();
    const int cnt = min(s_cnt, CAP);

    {
        const int wid = tid >> 5, lane = tid & 31;
        const double qm = qmagd[q];
        for (int c = wid; c < cnt; c += 8) {
            const int ki = cand_i[c];
            const float* kr = keys + (size_t)ki * TWO_D;
            float s = 0.f, comp = 0.f, es = 0.f;
#pragma unroll
            for (int t = 0; t < 8; t++) {
                int e = t * 128 + lane * 4;
                float4 kv = *(const float4*)(kr + e);
                cdot(s, comp, es, qs[e],     kv.x);
                cdot(s, comp, es, qs[e + 1], kv.y);
                cdot(s, comp, es, qs[e + 2], kv.z);
                cdot(s, comp, es, qs[e + 3], kv.w);
            }
            double acc = (double)s + (double)comp + (double)es;
#pragma unroll
            for (int o = 16; o > 0; o >>= 1)
                acc += __shfl_down_sync(0xffffffffu, acc, o);
            if (lane == 0) cand_d[c] = acc / (qm * kmagd[ki] + (double)EPSF);
        }
    }
    __syncthreads();

    for (int t = 0; t < TOPK; t++) {
        double bv = -1e300; int bi = 0;
        for (int i = tid; i < cnt; i += 256) {
            double v = cand_d[i];
            if (v > bv) { bv = v; bi = i; }
        }
#pragma unroll
        for (int o = 16; o > 0; o >>= 1) {
            double ov = __shfl_down_sync(0xffffffffu, bv, o);
            int    oi = __shfl_down_sync(0xffffffffu, bi, o);
            if (ov > bv) { bv = ov; bi = oi; }
        }
        if ((tid & 31) == 0) { redv[tid >> 5] = bv; redi[tid >> 5] = bi; }
        __syncthreads();
        if (tid == 0) {
            double fv = redv[0]; int fi = redi[0];
#pragma unroll
            for (int w = 1; w < 8; w++)
                if (redv[w] > fv) { fv = redv[w]; fi = redi[w]; }
            sel_d[t] = fv; sel_i[t] = cand_i[fi];
            cand_d[fi] = -1e300;
        }
        __syncthreads();
    }

    if (tid == 0) {
        float m = (float)sel_d[0];
        float z = 0.f;
        for (int t = 0; t < TOPK; t++) { float w = expf((float)sel_d[t] - m); s_w[t] = w; z += w; }
        float inv = 1.0f / z;
        for (int t = 0; t < TOPK; t++) s_w[t] *= inv;
    }
    __syncthreads();

    const int col = tid * 4;
    float4 acc = make_float4(0.f, 0.f, 0.f, 0.f);
    for (int t = 0; t < TOPK; t++) {
        const float4 v = *(const float4*)&values[(size_t)sel_i[t] * TWO_D + col];
        float w = s_w[t];
        acc.x += w * v.x; acc.y += w * v.y; acc.z += w * v.z; acc.w += w * v.w;
    }

    snorm[tid] = acc.x * acc.x + acc.y * acc.y + acc.z * acc.z + acc.w * acc.w;
    __syncthreads();
    for (int o = 128; o > 0; o >>= 1) {
        if (tid < o) snorm[tid] += snorm[tid + o];
        __syncthreads();
    }
    if (tid == 0) {
        float mean = snorm[0] / (float)DIM;
        s_inv = 1.0f / sqrtf(mean + EPSF);
    }
    __syncthreads();
    const float inv = s_inv;
    float2 g2 = *(const float2*)&gamma[col >> 1];
    float4 o4;
    o4.x = acc.x * g2.x * inv;
    o4.y = acc.y * g2.x * inv;
    o4.z = acc.z * g2.y * inv;
    o4.w = acc.w * g2.y * inv;
    *(float4*)&outn[(size_t)q * TWO_D + col] = o4;
}

// ---------------- split preps (out-projection only) ----------------
__global__ void __launch_bounds__(256)
prep_splitAo_kernel(const float* __restrict__ X, __nv_bfloat16* __restrict__ A2)
{
    const int row = blockIdx.x;
    const int base = threadIdx.x * 4;
    float4 v = *(const float4*)&X[(size_t)row * TWO_D + base];
    __nv_bfloat16 h0 = __float2bfloat16(v.x), h1 = __float2bfloat16(v.y);
    __nv_bfloat16 h2 = __float2bfloat16(v.z), h3 = __float2bfloat16(v.w);
    __nv_bfloat16 l0 = __float2bfloat16(v.x - __bfloat162float(h0));
    __nv_bfloat16 l1 = __float2bfloat16(v.y - __bfloat162float(h1));
    __nv_bfloat16 l2 = __float2bfloat16(v.z - __bfloat162float(h2));
    __nv_bfloat16 l3 = __float2bfloat16(v.w - __bfloat162float(h3));
    __nv_bfloat16* r = A2 + (size_t)row * PKO;
    uint2 hp, lp;
    ((__nv_bfloat16*)&hp)[0] = h0; ((__nv_bfloat16*)&hp)[1] = h1;
    ((__nv_bfloat16*)&hp)[2] = h2; ((__nv_bfloat16*)&hp)[3] = h3;
    ((__nv_bfloat16*)&lp)[0] = l0; ((__nv_bfloat16*)&lp)[1] = l1;
    ((__nv_bfloat16*)&lp)[2] = l2; ((__nv_bfloat16*)&lp)[3] = l3;
    *(uint2*)(r + base)          = hp;
    *(uint2*)(r + TWO_D + base)  = hp;
    *(uint2*)(r + 2048 + base)   = lp;
}

__global__ void __launch_bounds__(256)
prep_splitBo_kernel(const float* __restrict__ Wr, const float* __restrict__ Wi,
                    __nv_bfloat16* __restrict__ B2)
{
    const int j = blockIdx.x;
    const int n = j >> 1, s = j & 1;
    __nv_bfloat16* r = B2 + (size_t)j * PKO;
    for (int c = threadIdx.x; c < TWO_D; c += 256) {
        int d = c >> 1, p = c & 1;
        float v;
        if (s == 0) v = (p == 0) ? Wr[(size_t)n * DIM + d] : -Wi[(size_t)n * DIM + d];
        else        v = (p == 0) ? Wi[(size_t)n * DIM + d] :  Wr[(size_t)n * DIM + d];
        __nv_bfloat16 h = __float2bfloat16(v);
        __nv_bfloat16 l = __float2bfloat16(v - __bfloat162float(h));
        r[c] = h;
        r[TWO_D + c] = l;
        r[2048 + c] = h;
    }
}

// ---------------- out-projection GEMM (split-bf16, K=3072, fp32 out + bias) -------------
__global__ void __launch_bounds__(256, 2)
proj_gemm_mma(const __nv_bfloat16* __restrict__ A, const __nv_bfloat16* __restrict__ B,
              const float* __restrict__ br, const float* __restrict__ bi,
              float* __restrict__ C, int kchunks)
{
    extern __shared__ __align__(16) char smraw[];
    const uint32_t sb = smem_u32(smraw);
    const int tid = threadIdx.x;
    const int wid = tid >> 5, lane = tid & 31;
    const int m0 = blockIdx.x * 128;
    const int n0 = blockIdx.y * 128;
    const int wm0 = (wid & 1) * 64, wn0 = (wid >> 1) * 32;
    const size_t rstride = (size_t)kchunks * 128;

    float acc[4][4][4];
#pragma unroll
    for (int a = 0; a < 4; a++)
#pragma unroll
        for (int b = 0; b < 4; b++)
#pragma unroll
            for (int c = 0; c < 4; c++) acc[a][b][c] = 0.f;

    const char* Abase = (const char*)A + (size_t)m0 * rstride;
    const char* Bbase = (const char*)B + (size_t)n0 * rstride;

    gemm_load_stage(Abase, Bbase, rstride, sb, tid, 0, 0);
    int buf = 0;
    const int arow = lane & 15, acol = (lane >> 4) * 8;
    const int brow = lane & 7,  bcol = ((lane >> 3) & 1) * 8;

    for (int it = 0; it < kchunks; it++) {
        if (it < kchunks - 1) {
            gemm_load_stage(Abase, Bbase, rstride, sb, tid, it + 1, buf ^ 1);
            asm volatile("cp.async.wait_group 1;" ::: "memory");
        } else {
            asm volatile("cp.async.wait_group 0;" ::: "memory");
        }
        __syncthreads();
        const uint32_t aB = sb + (uint32_t)buf * STAGE_BYTES;
        const uint32_t bB = aB + TILE_BYTES;
#pragma unroll
        for (int ks = 0; ks < 4; ks++) {
            uint32_t afr[4][4], bfr[4][2];
#pragma unroll
            for (int fm = 0; fm < 4; fm++)
                ldmx4(afr[fm], aB + (wm0 + fm * 16 + arow) * 144 + (ks * 16 + acol) * 2);
#pragma unroll
            for (int fn = 0; fn < 4; fn++)
                ldmx2(bfr[fn], bB + (wn0 + fn * 8 + brow) * 144 + (ks * 16 + bcol) * 2);
#pragma unroll
            for (int fm = 0; fm < 4; fm++)
#pragma unroll
                for (int fn = 0; fn < 4; fn++)
                    mma_bf16(acc[fm][fn], afr[fm], bfr[fn]);
        }
        __syncthreads();
        buf ^= 1;
    }

#pragma unroll
    for (int fm = 0; fm < 4; fm++) {
        int mlo = m0 + wm0 + fm * 16 + (lane >> 2);
        int mhi = mlo + 8;
#pragma unroll
        for (int fn = 0; fn < 4; fn++) {
            int n = n0 + wn0 + fn * 8 + (lane & 3) * 2;
            float b0 = br[n >> 1], b1 = bi[n >> 1];
            float2 vlo = make_float2(acc[fm][fn][0] + b0, acc[fm][fn][1] + b1);
            float2 vhi = make_float2(acc[fm][fn][2] + b0, acc[fm][fn][3] + b1);
            *(float2*)&C[(size_t)mlo * TWO_D + n] = vlo;
            *(float2*)&C[(size_t)mhi * TWO_D + n] = vhi;
        }
    }
}

// ---------------- launch ----------------
extern "C" void kernel_launch(void* const* d_in, const int* in_sizes, int n_in,
                              void* d_out, int out_size)
{
    const float* query = (const float*)d_in[0];
    const float* keys  = (const float*)d_in[1];
    const float* vals  = (const float*)d_in[2];
    const float* Wq_r  = (const float*)d_in[3];
    const float* Wq_i  = (const float*)d_in[4];
    const float* bq_r  = (const float*)d_in[5];
    const float* bq_i  = (const float*)d_in[6];
    const float* Wo_r  = (const float*)d_in[7];
    const float* Wo_i  = (const float*)d_in[8];
    const float* bo_r  = (const float*)d_in[9];
    const float* bo_i  = (const float*)d_in[10];
    const float* gamma = (const float*)d_in[11];
    float* out = (float*)d_out;

    void *p_q, *p_qh, *p_kh, *p_qmd, *p_qmf, *p_kmd, *p_kmf, *p_sc, *p_nrm, *p_A2o, *p_B2o;
    cudaGetSymbolAddress(&p_q,   g_q);
    cudaGetSymbolAddress(&p_qh,  g_qh);
    cudaGetSymbolAddress(&p_kh,  g_kh);
    cudaGetSymbolAddress(&p_qmd, g_qmagd);
    cudaGetSymbolAddress(&p_qmf, g_qmagf);
    cudaGetSymbolAddress(&p_kmd, g_kmagd);
    cudaGetSymbolAddress(&p_kmf, g_kmagf);
    cudaGetSymbolAddress(&p_sc,  g_scoresh);
    cudaGetSymbolAddress(&p_nrm, g_norm);
    cudaGetSymbolAddress(&p_A2o, g_A2o);
    cudaGetSymbolAddress(&p_B2o, g_B2o);
    float*  qbuf  = (float*)p_q;
    __nv_bfloat16* qh = (__nv_bfloat16*)p_qh;
    __nv_bfloat16* kh = (__nv_bfloat16*)p_kh;
    double* qmagd = (double*)p_qmd;
    float*  qmagf = (float*)p_qmf;
    double* kmagd = (double*)p_kmd;
    float*  kmagf = (float*)p_kmf;
    __half* sc    = (__half*)p_sc;
    float*  nrmb  = (float*)p_nrm;
    __nv_bfloat16* A2o = (__nv_bfloat16*)p_A2o;
    __nv_bfloat16* B2o = (__nv_bfloat16*)p_B2o;

    cudaFuncSetAttribute(coh_gemm_mma, cudaFuncAttributeMaxDynamicSharedMemorySize, GEMM_SMEM);
    cudaFuncSetAttribute(proj_gemm_mma, cudaFuncAttributeMaxDynamicSharedMemorySize, PGEMM_SMEM);

    dim3 gproj(DIM / 64, QROWS / 64);

    prep_bf16_kernel<<<NKEYS, 128>>>(keys, kh, kmagd, kmagf);
    prep_splitBo_kernel<<<TWO_D, 256>>>(Wo_r, Wo_i, B2o);

    // precise q projection (block-compensated Kahan, fma pipe)
    cproj_kernel<<<gproj, 256>>>(query, Wq_r, Wq_i, bq_r, bq_i, qbuf);
    prep_bf16_kernel<<<QROWS, 128>>>(qbuf, qh, qmagd, qmagf);

    // coherence screening GEMM
    dim3 ggemm(QROWS / GTM, NKEYS / GTN);
    coh_gemm_mma<<<ggemm, 256, GEMM_SMEM>>>(qh, kh, qmagf, kmagf, sc);

    // top-64 + softmax + gather + phase norm
    topk_kernel<<<QROWS, 256>>>(sc, qbuf, keys, qmagd, kmagd, vals, gamma, nrmb);

    // output projection (tensor, 3-term split, K=3072)
    prep_splitAo_kernel<<<QROWS, 256>>>(nrmb, A2o);
    dim3 gpro(QROWS / 128, TWO_D / 128);
    proj_gemm_mma<<<gpro, 256, PGEMM_SMEM>>>(A2o, B2o, bo_r, bo_i, out, PKO / 64);
}